// round 8
// baseline (speedup 1.0000x reference)
#include <cuda_runtime.h>
#include <math.h>

#define QLEN 1024
#define BATCH 4
#define DMODEL 512
#define HEADS 8
#define DHEAD 64
#define MEMLEN 1024
#define KLEN 2048
#define DMLP 2048
#define BH 32
#define QROWS 4096
#define KROWS 8192
#define QKVW 1536
#define QSTRIDE 6144
#define QK ((size_t)QLEN * KLEN)
#define SMEM_DYN 61440   // 3 stages * (128+128) rows * 20 floats * 4B

// ---------------- scratch ----------------
__device__ float g_qkv[KROWS * QKVW];
__device__ float g_rk[KLEN * DMODEL];
__device__ float g_qu[BH * QLEN * DHEAD];
__device__ float g_qv[BH * QLEN * DHEAD];
__device__ float g_vt[BH * DHEAD * KLEN];
__device__ float g_S[(size_t)BH * QLEN * KLEN];
__device__ float g_BD[(size_t)BH * QLEN * KLEN];
__device__ float2 g_part[(size_t)BH * QLEN * 16];
__device__ float2 g_stat[BH * QLEN];
__device__ float g_attn[QROWS * DMODEL];
__device__ float g_ao[QROWS * DMODEL];
__device__ float g_y[QROWS * DMODEL];
__device__ float g_yr[QROWS * DMODEL];
__device__ float g_h[QROWS * DMLP];
__device__ float g_z[QROWS * DMODEL];
__device__ float g_rnd[8650752];   // concatenated RNA-rounded inputs/weights

#define OFF_MEM  0
#define OFF_IN   2097152
#define OFF_R    4194304
#define OFF_WQKV 5242880
#define OFF_WR   6029312
#define OFF_WO   6291456
#define OFF_W1   6553600
#define OFF_W2   7602176

// ---------------- helpers ----------------
__device__ __forceinline__ float f2tf(float x) {
    unsigned r;
    asm("cvt.rna.tf32.f32 %0, %1;" : "=r"(r) : "f"(x));
    return __uint_as_float(r);
}
__device__ __forceinline__ void cp16(float* dst_smem, const float* src) {
    unsigned d = (unsigned)__cvta_generic_to_shared(dst_smem);
    asm volatile("cp.async.ca.shared.global [%0], [%1], 16;" :: "r"(d), "l"(src));
}
__device__ __forceinline__ void cp_commit() { asm volatile("cp.async.commit_group;"); }
__device__ __forceinline__ void cp_wait1()  { asm volatile("cp.async.wait_group 1;"); }
__device__ __forceinline__ void cp_wait0()  { asm volatile("cp.async.wait_group 0;"); }

__device__ __forceinline__ void mma_tf32(float* acc, unsigned a0, unsigned a1,
                                         unsigned a2, unsigned a3,
                                         unsigned b0, unsigned b1) {
    asm volatile(
        "mma.sync.aligned.m16n8k8.row.col.f32.tf32.tf32.f32 "
        "{%0,%1,%2,%3}, {%4,%5,%6,%7}, {%8,%9}, {%0,%1,%2,%3};"
        : "+f"(acc[0]), "+f"(acc[1]), "+f"(acc[2]), "+f"(acc[3])
        : "r"(a0), "r"(a1), "r"(a2), "r"(a3), "r"(b0), "r"(b1));
}
// ldmatrix x4: 16 rows x 8 tf32 cols; r0..r3 = tf32 mma A-fragment order
__device__ __forceinline__ void ldsm_x4(unsigned& r0, unsigned& r1, unsigned& r2,
                                        unsigned& r3, unsigned addr) {
    asm volatile("ldmatrix.sync.aligned.m8n8.x4.shared.b16 {%0,%1,%2,%3}, [%4];"
                 : "=r"(r0), "=r"(r1), "=r"(r2), "=r"(r3) : "r"(addr));
}

// ---------------- fused RNA round-copy ----------------
__global__ void round_all(const float* __restrict__ s0, const float* __restrict__ s1,
                          const float* __restrict__ s2, const float* __restrict__ s3,
                          const float* __restrict__ s4, const float* __restrict__ s5,
                          const float* __restrict__ s6, const float* __restrict__ s7,
                          float4* __restrict__ dst) {
    int idx = blockIdx.x * 256 + threadIdx.x;
    if (idx >= 2162688) return;
    const float4* src; int base;
    if      (idx < 524288)  { src = (const float4*)s0; base = 0; }
    else if (idx < 1048576) { src = (const float4*)s1; base = 524288; }
    else if (idx < 1310720) { src = (const float4*)s2; base = 1048576; }
    else if (idx < 1507328) { src = (const float4*)s3; base = 1310720; }
    else if (idx < 1572864) { src = (const float4*)s4; base = 1507328; }
    else if (idx < 1638400) { src = (const float4*)s5; base = 1572864; }
    else if (idx < 1900544) { src = (const float4*)s6; base = 1638400; }
    else                    { src = (const float4*)s7; base = 1900544; }
    float4 v = src[idx - base];
    v.x = f2tf(v.x); v.y = f2tf(v.y); v.z = f2tf(v.z); v.w = f2tf(v.w);
    dst[idx] = v;
}

// ---------------- 128x128 tf32 NT GEMM core: 3-stage cp.async + ldmatrix -----
__device__ __forceinline__ void gemm_core128(
    const float* __restrict__ A, int lda,
    const float* __restrict__ B, int ldb,
    int K0, int K1, float acc[4][8][4], float* sm)
{
    const int tid = threadIdx.x;
    const int lane = tid & 31, warp = tid >> 5;
    const int wm = warp & 1, wn = warp >> 1;

    #pragma unroll
    for (int mt = 0; mt < 4; mt++)
        #pragma unroll
        for (int nt = 0; nt < 8; nt++)
            #pragma unroll
            for (int q = 0; q < 4; q++) acc[mt][nt][q] = 0.0f;

    const int nk = (K1 - K0) >> 4;

    auto load = [&](int it, int s) {
        int kt = K0 + it * 16;
        float* as = sm + s * 2560;
        float* bs = sm + 7680 + s * 2560;
        #pragma unroll
        for (int l = 0; l < 4; l++) {
            int idx = l * 128 + tid;
            int r = idx >> 2, c4 = (idx & 3) << 2;
            cp16(as + r * 20 + c4, A + (size_t)r * lda + kt + c4);
            cp16(bs + r * 20 + c4, B + (size_t)r * ldb + kt + c4);
        }
        cp_commit();
    };

    load(0, 0);
    if (nk > 1) load(1, 1);

    const unsigned smem_u = (unsigned)__cvta_generic_to_shared(sm);
    const int rowsel = lane & 15;
    const int colsel = (lane >> 4) << 2;
    const unsigned aOff = (unsigned)((wm * 64 + rowsel) * 20 + colsel);
    const unsigned bOff = (unsigned)(7680 + (wn * 64 + rowsel) * 20 + colsel);

    for (int it = 0; it < nk; it++) {
        if (it + 1 < nk) cp_wait1(); else cp_wait0();
        __syncthreads();
        if (it + 2 < nk) load(it + 2, (it + 2) % 3);
        const unsigned stageOff = (unsigned)((it % 3) * 2560);
        const unsigned aS = smem_u + (stageOff + aOff) * 4;
        const unsigned bS = smem_u + (stageOff + bOff) * 4;
        #pragma unroll
        for (int ks = 0; ks < 16; ks += 8) {
            unsigned af[4][4], bf[8][2];
            #pragma unroll
            for (int mt = 0; mt < 4; mt++)
                ldsm_x4(af[mt][0], af[mt][1], af[mt][2], af[mt][3],
                        aS + (mt * 16 * 20 + ks) * 4);
            #pragma unroll
            for (int p = 0; p < 4; p++) {
                unsigned r0, r1, r2, r3;
                ldsm_x4(r0, r1, r2, r3, bS + (p * 16 * 20 + ks) * 4);
                bf[2*p][0] = r0; bf[2*p+1][0] = r1;
                bf[2*p][1] = r2; bf[2*p+1][1] = r3;
            }
            #pragma unroll
            for (int mt = 0; mt < 4; mt++)
                #pragma unroll
                for (int nt = 0; nt < 8; nt++)
                    mma_tf32(acc[mt][nt], af[mt][0], af[mt][1], af[mt][2], af[mt][3],
                             bf[nt][0], bf[nt][1]);
        }
    }
}

// ---------------- linear GEMM (act: +1 bias, +2 relu, +4 round-out) ----------
__global__ __launch_bounds__(128, 2) void lin_gemm(
    const float* __restrict__ A, const float* __restrict__ W,
    const float* __restrict__ bias, float* __restrict__ C,
    int K, int N, int act)
{
    extern __shared__ float sm[];
    int m0 = blockIdx.y * 128, n0 = blockIdx.x * 128;
    float acc[4][8][4];
    gemm_core128(A + (size_t)m0 * K, K, W + (size_t)n0 * K, K, 0, K, acc, sm);
    const int lane = threadIdx.x & 31, warp = threadIdx.x >> 5;
    const int wm = warp & 1, wn = warp >> 1;
    const int grp = lane >> 2, tig = lane & 3;
    float* Cp = C + (size_t)m0 * N + n0;
    const float* bp = bias ? bias + n0 : nullptr;
    #pragma unroll
    for (int mt = 0; mt < 4; mt++) {
        int r0 = wm * 64 + mt * 16 + grp;
        #pragma unroll
        for (int nt = 0; nt < 8; nt++) {
            int c0 = wn * 64 + nt * 8 + tig * 2;
            float v0 = acc[mt][nt][0], v1 = acc[mt][nt][1];
            float v2 = acc[mt][nt][2], v3 = acc[mt][nt][3];
            if (act & 1) {
                float b0 = bp[c0], b1 = bp[c0 + 1];
                v0 += b0; v1 += b1; v2 += b0; v3 += b1;
            }
            if (act & 2) {
                v0 = fmaxf(v0, 0.f); v1 = fmaxf(v1, 0.f);
                v2 = fmaxf(v2, 0.f); v3 = fmaxf(v3, 0.f);
            }
            if (act & 4) {
                v0 = f2tf(v0); v1 = f2tf(v1); v2 = f2tf(v2); v3 = f2tf(v3);
            }
            *(float2*)(Cp + (size_t)r0 * N + c0) = make_float2(v0, v1);
            *(float2*)(Cp + (size_t)(r0 + 8) * N + c0) = make_float2(v2, v3);
        }
    }
}

// ---------------- BD raw scores ----------------
__global__ __launch_bounds__(128, 2) void score_bd(
    const float* __restrict__ Qv, const float* __restrict__ rk,
    float* __restrict__ BD)
{
    extern __shared__ float sm[];
    int bh = blockIdx.z, h = bh & 7;
    int i0 = blockIdx.y * 128, p0 = blockIdx.x * 128;
    if (p0 + i0 < 896) return;
    float acc[4][8][4];
    gemm_core128(Qv + ((size_t)bh * QLEN + i0) * DHEAD, DHEAD,
                 rk + (size_t)p0 * DMODEL + h * DHEAD, DMODEL, 0, DHEAD, acc, sm);
    const int lane = threadIdx.x & 31, warp = threadIdx.x >> 5;
    const int wm = warp & 1, wn = warp >> 1;
    const int grp = lane >> 2, tig = lane & 3;
    float* Cp = BD + (size_t)bh * QK + (size_t)i0 * KLEN + p0;
    #pragma unroll
    for (int mt = 0; mt < 4; mt++) {
        int r0 = wm * 64 + mt * 16 + grp;
        #pragma unroll
        for (int nt = 0; nt < 8; nt++) {
            int c0 = wn * 64 + nt * 8 + tig * 2;
            *(float2*)(Cp + (size_t)r0 * KLEN + c0) =
                make_float2(acc[mt][nt][0], acc[mt][nt][1]);
            *(float2*)(Cp + (size_t)(r0 + 8) * KLEN + c0) =
                make_float2(acc[mt][nt][2], acc[mt][nt][3]);
        }
    }
}

// ---------------- AC scores + BD rel-shift + scale + softmax partials --------
__global__ __launch_bounds__(128, 2) void score_ac(
    const float* __restrict__ Qu, const float* __restrict__ qkv,
    const float* __restrict__ BD, float* __restrict__ S,
    float2* __restrict__ part_out)
{
    extern __shared__ float sm[];
    int bh = blockIdx.z, b = bh >> 3, h = bh & 7;
    int i0 = blockIdx.y * 128, j0 = blockIdx.x * 128;
    if (j0 - i0 > 1024) return;
    float acc[4][8][4];
    gemm_core128(Qu + ((size_t)bh * QLEN + i0) * DHEAD, DHEAD,
                 qkv + (size_t)j0 * QSTRIDE + b * QKVW + DMODEL + h * DHEAD, QSTRIDE,
                 0, DHEAD, acc, sm);
    const int tid = threadIdx.x;
    const int lane = tid & 31, warp = tid >> 5;
    const int wm = warp & 1, wn = warp >> 1;
    const int grp = lane >> 2, tig = lane & 3;
    const float* bdb = BD + (size_t)bh * QK;
    float* Sp = S + (size_t)bh * QK;

    #pragma unroll
    for (int mt = 0; mt < 4; mt++) {
        #pragma unroll
        for (int hh = 0; hh < 2; hh++) {
            int gi = i0 + wm * 64 + mt * 16 + grp + hh * 8;
            const float* bdr = bdb + (size_t)gi * KLEN;
            int jmax = gi + MEMLEN;
            #pragma unroll
            for (int nt = 0; nt < 8; nt++) {
                int gj = j0 + wn * 64 + nt * 8 + tig * 2;
                int p0 = min(gj - gi + (QLEN - 1), KLEN - 1);
                int p1 = min(p0 + 1, KLEN - 1);
                float v0 = (gj     <= jmax) ? (acc[mt][nt][hh*2+0] + bdr[p0]) * 0.125f : -1e30f;
                float v1 = (gj + 1 <= jmax) ? (acc[mt][nt][hh*2+1] + bdr[p1]) * 0.125f : -1e30f;
                acc[mt][nt][hh*2+0] = v0;
                acc[mt][nt][hh*2+1] = v1;
                *(float2*)(Sp + (size_t)gi * KLEN + gj) = make_float2(v0, v1);
            }
        }
    }

    __syncthreads();
    float2* part = (float2*)sm;
    #pragma unroll
    for (int mt = 0; mt < 4; mt++) {
        #pragma unroll
        for (int hh = 0; hh < 2; hh++) {
            float m = -1e30f;
            #pragma unroll
            for (int nt = 0; nt < 8; nt++) {
                m = fmaxf(m, acc[mt][nt][hh*2+0]);
                m = fmaxf(m, acc[mt][nt][hh*2+1]);
            }
            float s = 0.f;
            #pragma unroll
            for (int nt = 0; nt < 8; nt++) {
                s += __expf(acc[mt][nt][hh*2+0] - m);
                s += __expf(acc[mt][nt][hh*2+1] - m);
            }
            #pragma unroll
            for (int o = 1; o < 4; o <<= 1) {
                float m2 = __shfl_xor_sync(0xffffffffu, m, o);
                float s2 = __shfl_xor_sync(0xffffffffu, s, o);
                float mm = fmaxf(m, m2);
                s = s * __expf(m - mm) + s2 * __expf(m2 - mm);
                m = mm;
            }
            if (tig == 0)
                part[wn * 128 + wm * 64 + mt * 16 + hh * 8 + grp] = make_float2(m, s);
        }
    }
    __syncthreads();
    {
        float2 a = part[tid], c = part[128 + tid];
        float mm = fmaxf(a.x, c.x);
        float ss = a.y * __expf(a.x - mm) + c.y * __expf(c.x - mm);
        part_out[((size_t)bh * QLEN + i0 + tid) * 16 + (j0 >> 7)] = make_float2(mm, ss);
    }
}

// ---------------- combine partials ----------------
__global__ void statcombine(const float2* __restrict__ part, float2* __restrict__ stat) {
    int id = blockIdx.x * 256 + threadIdx.x;
    if (id >= BH * QLEN) return;
    int i = id & (QLEN - 1);
    int ntl = (i >> 7) + 9; if (ntl > 16) ntl = 16;
    float M = -1e30f, Ssum = 0.f;
    const float2* p = part + (size_t)id * 16;
    for (int t = 0; t < ntl; t++) {
        float2 q = p[t];
        float mm = fmaxf(M, q.x);
        Ssum = Ssum * __expf(M - mm) + q.y * __expf(q.x - mm);
        M = mm;
    }
    stat[id] = make_float2(M, 1.0f / Ssum);
}

// ---------------- prob output ----------------
__global__ void probout(const float* __restrict__ S, const float2* __restrict__ stat,
                        float* __restrict__ out) {
    __shared__ float t[32][33];
    __shared__ float m_s[32], inv_s[32];
    const int i = blockIdx.y, j0 = blockIdx.x * 32;
    const int tid = threadIdx.x;
    if (tid < 32) {
        float2 st = stat[tid * QLEN + i];
        m_s[tid] = st.x; inv_s[tid] = st.y;
    }
    __syncthreads();
    const int lj = tid & 31, lb = tid >> 5;
    const int jmax = i + MEMLEN;
    #pragma unroll
    for (int r = 0; r < 4; r++) {
        int bh = r * 8 + lb;
        int j = j0 + lj;
        float val = 0.0f;
        if (j <= jmax)
            val = __expf(S[((size_t)bh * QLEN + i) * KLEN + j] - m_s[bh]) * inv_s[bh];
        t[lj][bh] = val;
    }
    __syncthreads();
    const int lbh = tid & 31, ljw = tid >> 5;
    #pragma unroll
    for (int r = 0; r < 4; r++) {
        int jj = r * 8 + ljw;
        out[((size_t)i * KLEN + j0 + jj) * 32 + lbh] = t[jj][lbh];
    }
}

// ---------------- attention: exp(S) on the fly @ Vt (ldmatrix frags) ----------
__global__ __launch_bounds__(128, 2) void attn_exp_gemm(
    const float* __restrict__ S, const float2* __restrict__ stat,
    const float* __restrict__ Vt, float* __restrict__ attn)
{
    const int bh = blockIdx.y, b = bh >> 3, h = bh & 7;
    const int i0 = blockIdx.x * 128;
    __shared__ __align__(16) float As[128][20];
    __shared__ __align__(16) float Bs[2][64][20];
    __shared__ float m_s[128], inv_s[128];
    const int tid = threadIdx.x;
    const int lane = tid & 31, warp = tid >> 5;
    const int wm = warp & 1, wn = warp >> 1;
    const int grp = lane >> 2, tig = lane & 3;
    {
        float2 st = stat[bh * QLEN + i0 + tid];
        m_s[tid] = st.x; inv_s[tid] = st.y;
    }
    __syncthreads();

    const float* Srow = S + (size_t)bh * QK + (size_t)i0 * KLEN;
    const float* Vb = Vt + (size_t)bh * DHEAD * KLEN;
    const int K1 = min(KLEN, i0 + 128 + MEMLEN);
    const int nk = K1 >> 4;

    float acc[4][4][4];
    #pragma unroll
    for (int mt = 0; mt < 4; mt++)
        #pragma unroll
        for (int nt = 0; nt < 4; nt++)
            #pragma unroll
            for (int q = 0; q < 4; q++) acc[mt][nt][q] = 0.f;

    float4 aReg[4];
    #pragma unroll
    for (int l = 0; l < 4; l++) {
        int idx = l * 128 + tid;
        int r = idx >> 2, c4 = (idx & 3) << 2;
        aReg[l] = *(const float4*)(Srow + (size_t)r * KLEN + c4);
    }
    #pragma unroll
    for (int l = 0; l < 2; l++) {
        int idx = l * 128 + tid;
        int r = idx >> 2, c4 = (idx & 3) << 2;
        cp16(&Bs[0][r][c4], Vb + (size_t)r * KLEN + c4);
    }
    cp_commit();

    const unsigned aBase = (unsigned)__cvta_generic_to_shared(&As[0][0]);
    const unsigned bBase = (unsigned)__cvta_generic_to_shared(&Bs[0][0][0]);
    const int rowsel = lane & 15;
    const int colsel = (lane >> 4) << 2;
    const unsigned aOff = aBase + (unsigned)(((wm * 64 + rowsel) * 20 + colsel) * 4);
    const unsigned bOff = bBase + (unsigned)(((wn * 32 + rowsel) * 20 + colsel) * 4);

    int cur = 0;
    for (int it = 0; it < nk; it++) {
        const int kt = it * 16;
        float4 aNext[4];
        if (it + 1 < nk) {
            int ktn = kt + 16;
            #pragma unroll
            for (int l = 0; l < 2; l++) {
                int idx = l * 128 + tid;
                int r = idx >> 2, c4 = (idx & 3) << 2;
                cp16(&Bs[cur ^ 1][r][c4], Vb + (size_t)r * KLEN + ktn + c4);
            }
            #pragma unroll
            for (int l = 0; l < 4; l++) {
                int idx = l * 128 + tid;
                int r = idx >> 2, c4 = (idx & 3) << 2;
                aNext[l] = *(const float4*)(Srow + (size_t)r * KLEN + ktn + c4);
            }
            cp_commit();
        }
        #pragma unroll
        for (int l = 0; l < 4; l++) {
            int idx = l * 128 + tid;
            int r = idx >> 2, c4 = (idx & 3) << 2;
            float mr = m_s[r];
            int jmax = i0 + r + MEMLEN;
            As[r][c4]     = (kt + c4 + 0 <= jmax) ? f2tf(__expf(aReg[l].x - mr)) : 0.f;
            As[r][c4 + 1] = (kt + c4 + 1 <= jmax) ? f2tf(__expf(aReg[l].y - mr)) : 0.f;
            As[r][c4 + 2] = (kt + c4 + 2 <= jmax) ? f2tf(__expf(aReg[l].z - mr)) : 0.f;
            As[r][c4 + 3] = (kt + c4 + 3 <= jmax) ? f2tf(__expf(aReg[l].w - mr)) : 0.f;
        }
        if (it + 1 < nk) cp_wait1(); else cp_wait0();
        __syncthreads();
        const unsigned bS = bOff + (unsigned)(cur * 64 * 20 * 4);
        #pragma unroll
        for (int ks = 0; ks < 16; ks += 8) {
            unsigned af[4][4], bf[4][2];
            #pragma unroll
            for (int mt = 0; mt < 4; mt++)
                ldsm_x4(af[mt][0], af[mt][1], af[mt][2], af[mt][3],
                        aOff + (mt * 16 * 20 + ks) * 4);
            #pragma unroll
            for (int p = 0; p < 2; p++) {
                unsigned r0, r1, r2, r3;
                ldsm_x4(r0, r1, r2, r3, bS + (p * 16 * 20 + ks) * 4);
                bf[2*p][0] = r0; bf[2*p+1][0] = r1;
                bf[2*p][1] = r2; bf[2*p+1][1] = r3;
            }
            #pragma unroll
            for (int mt = 0; mt < 4; mt++)
                #pragma unroll
                for (int nt = 0; nt < 4; nt++)
                    mma_tf32(acc[mt][nt], af[mt][0], af[mt][1], af[mt][2], af[mt][3],
                             bf[nt][0], bf[nt][1]);
        }
        __syncthreads();
        #pragma unroll
        for (int l = 0; l < 4; l++) aReg[l] = aNext[l];
        cur ^= 1;
    }

    #pragma unroll
    for (int mt = 0; mt < 4; mt++) {
        int r0 = wm * 64 + mt * 16 + grp;
        float iv0 = inv_s[r0], iv1 = inv_s[r0 + 8];
        #pragma unroll
        for (int nt = 0; nt < 4; nt++) {
            int c0 = wn * 32 + nt * 8 + tig * 2;
            float v0 = f2tf(acc[mt][nt][0] * iv0);
            float v1 = f2tf(acc[mt][nt][1] * iv0);
            float v2 = f2tf(acc[mt][nt][2] * iv1);
            float v3 = f2tf(acc[mt][nt][3] * iv1);
            size_t o0 = ((size_t)(i0 + r0) * BATCH + b) * DMODEL + h * DHEAD + c0;
            size_t o1 = ((size_t)(i0 + r0 + 8) * BATCH + b) * DMODEL + h * DHEAD + c0;
            *(float2*)(attn + o0) = make_float2(v0, v1);
            *(float2*)(attn + o1) = make_float2(v2, v3);
        }
    }
}

// ---------------- prep: Qu/Qv (rounded) ----------------
__global__ void prep_quv(const float* __restrict__ qkv, const float* __restrict__ u,
                         const float* __restrict__ v, float* __restrict__ Qu,
                         float* __restrict__ Qv) {
    int i = blockIdx.x, b = blockIdx.y, t = threadIdx.x;
    float q = qkv[(size_t)(MEMLEN + i) * QSTRIDE + b * QKVW + t];
    int h = t >> 6, d = t & 63;
    size_t o = ((size_t)(b * HEADS + h) * QLEN + i) * DHEAD + d;
    Qu[o] = f2tf(q + u[t]);
    Qv[o] = f2tf(q + v[t]);
}

// ---------------- prep: Vt[bh][d][j] ----------------
__global__ void prep_vt(const float* __restrict__ qkv, float* __restrict__ Vt) {
    __shared__ float t[32][33];
    int bh = blockIdx.z, b = bh >> 3, h = bh & 7;
    int j0 = blockIdx.x * 32, d0 = blockIdx.y * 32;
    int tc = threadIdx.x & 31, tr = threadIdx.x >> 5;
    #pragma unroll
    for (int rr = 0; rr < 32; rr += 8)
        t[tr + rr][tc] = qkv[(size_t)(j0 + tr + rr) * QSTRIDE + b * QKVW
                             + 2 * DMODEL + h * DHEAD + d0 + tc];
    __syncthreads();
    #pragma unroll
    for (int rr = 0; rr < 32; rr += 8)
        Vt[((size_t)bh * DHEAD + d0 + tr + rr) * KLEN + j0 + tc] = t[tc][tr + rr];
}

// ---------------- residual add + layernorm ----------------
__global__ void add_ln(const float* __restrict__ x1, const float* __restrict__ x2,
                       const float* __restrict__ g, const float* __restrict__ bb,
                       float* __restrict__ out, float* __restrict__ out_r) {
    const int row = blockIdx.x;
    const int tid = threadIdx.x;
    __shared__ float red[256];
    __shared__ float red2[256];
    const float* a = x1 + (size_t)row * DMODEL;
    const float* c = x2 + (size_t)row * DMODEL;
    float v0 = a[tid] + c[tid];
    float v1 = a[tid + 256] + c[tid + 256];
    red[tid] = v0 + v1;
    red2[tid] = v0 * v0 + v1 * v1;
    __syncthreads();
    for (int o = 128; o > 0; o >>= 1) {
        if (tid < o) { red[tid] += red[tid + o]; red2[tid] += red2[tid + o]; }
        __syncthreads();
    }
    const float mu = red[0] * (1.0f / DMODEL);
    const float var = red2[0] * (1.0f / DMODEL) - mu * mu;
    const float rstd = rsqrtf(var + 1e-5f);
    float* o = out + (size_t)row * DMODEL;
    float r0 = (v0 - mu) * rstd * g[tid] + bb[tid];
    float r1 = (v1 - mu) * rstd * g[tid + 256] + bb[tid + 256];
    o[tid] = r0;
    o[tid + 256] = r1;
    if (out_r) {
        float* orr = out_r + (size_t)row * DMODEL;
        orr[tid] = f2tf(r0);
        orr[tid + 256] = f2tf(r1);
    }
}

// ---------------- launch ----------------
extern "C" void kernel_launch(void* const* d_in, const int* in_sizes, int n_in,
                              void* d_out, int out_size) {
    const float* inputs = (const float*)d_in[0];
    const float* r      = (const float*)d_in[1];
    const float* u      = (const float*)d_in[2];
    const float* v      = (const float*)d_in[3];
    const float* mem    = (const float*)d_in[4];
    const float* Wqkv   = (const float*)d_in[6];
    const float* Wr     = (const float*)d_in[7];
    const float* Wo     = (const float*)d_in[8];
    const float* ln1_g  = (const float*)d_in[9];
    const float* ln1_b  = (const float*)d_in[10];
    const float* w1     = (const float*)d_in[11];
    const float* b1     = (const float*)d_in[12];
    const float* w2     = (const float*)d_in[13];
    const float* b2     = (const float*)d_in[14];
    const float* ln2_g  = (const float*)d_in[15];
    const float* ln2_b  = (const float*)d_in[16];

    static bool attr_done = false;
    if (!attr_done) {
        cudaFuncSetAttribute(lin_gemm, cudaFuncAttributeMaxDynamicSharedMemorySize, SMEM_DYN);
        cudaFuncSetAttribute(score_bd, cudaFuncAttributeMaxDynamicSharedMemorySize, SMEM_DYN);
        cudaFuncSetAttribute(score_ac, cudaFuncAttributeMaxDynamicSharedMemorySize, SMEM_DYN);
        attr_done = true;
    }

    float *qkvp, *rkp, *qup, *qvp, *vtp, *sp, *bdp, *attnp, *aop, *yp, *yrp, *hp, *zp, *rnd;
    float2 *statp, *partp;
    cudaGetSymbolAddress((void**)&qkvp,  g_qkv);
    cudaGetSymbolAddress((void**)&rkp,   g_rk);
    cudaGetSymbolAddress((void**)&qup,   g_qu);
    cudaGetSymbolAddress((void**)&qvp,   g_qv);
    cudaGetSymbolAddress((void**)&vtp,   g_vt);
    cudaGetSymbolAddress((void**)&sp,    g_S);
    cudaGetSymbolAddress((void**)&bdp,   g_BD);
    cudaGetSymbolAddress((void**)&statp, g_stat);
    cudaGetSymbolAddress((void**)&partp, g_part);
    cudaGetSymbolAddress((void**)&attnp, g_attn);
    cudaGetSymbolAddress((void**)&aop,   g_ao);
    cudaGetSymbolAddress((void**)&yp,    g_y);
    cudaGetSymbolAddress((void**)&yrp,   g_yr);
    cudaGetSymbolAddress((void**)&hp,    g_h);
    cudaGetSymbolAddress((void**)&zp,    g_z);
    cudaGetSymbolAddress((void**)&rnd,   g_rnd);

    const float* memr  = rnd + OFF_MEM;
    const float* rr    = rnd + OFF_R;
    const float* wqkvr = rnd + OFF_WQKV;
    const float* wrr   = rnd + OFF_WR;
    const float* wor   = rnd + OFF_WO;
    const float* w1r   = rnd + OFF_W1;
    const float* w2r   = rnd + OFF_W2;

    // 1: fused RNA rounding
    round_all<<<(2162688 + 255) / 256, 256>>>(mem, inputs, r, Wqkv, Wr, Wo, w1, w2,
                                              (float4*)rnd);
    // 2: qkv projection, single GEMM over concat(mem, inputs) = rnd[0:8192*512]
    lin_gemm<<<dim3(QKVW / 128, KROWS / 128), 128, SMEM_DYN>>>(memr, wqkvr, nullptr, qkvp,
                                                               DMODEL, QKVW, 4);
    // 3: rk projection
    lin_gemm<<<dim3(DMODEL / 128, KLEN / 128), 128, SMEM_DYN>>>(rr, wrr, nullptr, rkp,
                                                                DMODEL, DMODEL, 4);
    // 4-5: prep
    prep_quv<<<dim3(QLEN, BATCH), 512>>>(qkvp, u, v, qup, qvp);
    prep_vt<<<dim3(KLEN / 32, DHEAD / 32, BH), 256>>>(qkvp, vtp);
    // 6: score_bd (profiled launch)
    score_bd<<<dim3(KLEN / 128, QLEN / 128, BH), 128, SMEM_DYN>>>(qvp, rkp, bdp);
    // 7-9
    score_ac<<<dim3(KLEN / 128, QLEN / 128, BH), 128, SMEM_DYN>>>(qup, qkvp, bdp, sp, partp);
    statcombine<<<(BH * QLEN + 255) / 256, 256>>>(partp, statp);
    float* prob_out = (float*)d_out + QLEN * BATCH * DMODEL;
    probout<<<dim3(KLEN / 32, QLEN), 256>>>(sp, statp, prob_out);
    // 10-15
    attn_exp_gemm<<<dim3(QLEN / 128, BH), 128>>>(sp, statp, vtp, attnp);
    lin_gemm<<<dim3(DMODEL / 128, QROWS / 128), 128, SMEM_DYN>>>(attnp, wor, nullptr, aop,
                                                                 DMODEL, DMODEL, 0);
    add_ln<<<QROWS, 256>>>(inputs, aop, ln1_g, ln1_b, yp, yrp);
    lin_gemm<<<dim3(DMLP / 128, QROWS / 128), 128, SMEM_DYN>>>(yrp, w1r, b1, hp,
                                                               DMODEL, DMLP, 7);
    lin_gemm<<<dim3(DMODEL / 128, QROWS / 128), 128, SMEM_DYN>>>(hp, w2r, b2, zp,
                                                                 DMLP, DMODEL, 1);
    add_ln<<<QROWS, 256>>>(yp, zp, ln2_g, ln2_b, (float*)d_out, nullptr);
}

// round 9
// speedup vs baseline: 1.0037x; 1.0037x over previous
#include <cuda_runtime.h>
#include <math.h>

#define QLEN 1024
#define BATCH 4
#define DMODEL 512
#define HEADS 8
#define DHEAD 64
#define MEMLEN 1024
#define KLEN 2048
#define DMLP 2048
#define BH 32
#define QROWS 4096
#define KROWS 8192
#define QKVW 1536
#define QSTRIDE 6144
#define QK ((size_t)QLEN * KLEN)
#define SMEM_DYN 61440

__device__ float g_qkv[KROWS * QKVW];
__device__ float g_rk[KLEN * DMODEL];
__device__ float g_qu[BH * QLEN * DHEAD];
__device__ float g_qv[BH * QLEN * DHEAD];
__device__ float g_vt[BH * DHEAD * KLEN];
__device__ float g_S[(size_t)BH * QLEN * KLEN];
__device__ float g_BD[(size_t)BH * QLEN * KLEN];
__device__ float2 g_part[(size_t)BH * QLEN * 16];
__device__ float2 g_stat[BH * QLEN];
__device__ float g_attn[QROWS * DMODEL];
__device__ float g_ao[QROWS * DMODEL];
__device__ float g_y[QROWS * DMODEL];
__device__ float g_yr[QROWS * DMODEL];
__device__ float g_h[QROWS * DMLP];
__device__ float g_z[QROWS * DMODEL];
__device__ float g_rnd[8650752];

#define OFF_R    4194304
#define OFF_WQKV 5242880
#define OFF_WR   6029312
#define OFF_WO   6291456
#define OFF_W1   6553600
#define OFF_W2   7602176

__device__ __forceinline__ float f2tf(float x) {
    unsigned r;
    asm("cvt.rna.tf32.f32 %0, %1;" : "=r"(r) : "f"(x));
    return __uint_as_float(r);
}
__device__ __forceinline__ void cp16(float* dst_smem, const float* src) {
    unsigned d = (unsigned)__cvta_generic_to_shared(dst_smem);
    asm volatile("cp.async.ca.shared.global [%0], [%1], 16;" :: "r"(d), "l"(src));
}
__device__ __forceinline__ void cp_commit() { asm volatile("cp.async.commit_group;"); }
__device__ __forceinline__ void cp_wait1()  { asm volatile("cp.async.wait_group 1;"); }
__device__ __forceinline__ void cp_wait0()  { asm volatile("cp.async.wait_group 0;"); }

__device__ __forceinline__ void mma_tf32(float* acc, unsigned a0, unsigned a1,
                                         unsigned a2, unsigned a3,
                                         unsigned b0, unsigned b1) {
    asm volatile(
        "mma.sync.aligned.m16n8k8.row.col.f32.tf32.tf32.f32 "
        "{%0,%1,%2,%3}, {%4,%5,%6,%7}, {%8,%9}, {%0,%1,%2,%3};"
        : "+f"(acc[0]), "+f"(acc[1]), "+f"(acc[2]), "+f"(acc[3])
        : "r"(a0), "r"(a1), "r"(a2), "r"(a3), "r"(b0), "r"(b1));
}
__device__ __forceinline__ void ldsm_x4(unsigned& r0, unsigned& r1, unsigned& r2,
                                        unsigned& r3, unsigned addr) {
    asm volatile("ldmatrix.sync.aligned.m8n8.x4.shared.b16 {%0,%1,%2,%3}, [%4];"
                 : "=r"(r0), "=r"(r1), "=r"(r2), "=r"(r3) : "r"(addr));
}

__global__ void round_all(const float* __restrict__ s0, const float* __restrict__ s1,
                          const float* __restrict__ s2, const float* __restrict__ s3,
                          const float* __restrict__ s4, const float* __restrict__ s5,
                          const float* __restrict__ s6, const float* __restrict__ s7,
                          float4* __restrict__ dst) {
    int idx = blockIdx.x * 256 + threadIdx.x;
    if (idx >= 2162688) return;
    const float4* src; int base;
    if      (idx < 524288)  { src = (const float4*)s0; base = 0; }
    else if (idx < 1048576) { src = (const float4*)s1; base = 524288; }
    else if (idx < 1310720) { src = (const float4*)s2; base = 1048576; }
    else if (idx < 1507328) { src = (const float4*)s3; base = 1310720; }
    else if (idx < 1572864) { src = (const float4*)s4; base = 1507328; }
    else if (idx < 1638400) { src = (const float4*)s5; base = 1572864; }
    else if (idx < 1900544) { src = (const float4*)s6; base = 1638400; }
    else                    { src = (const float4*)s7; base = 1900544; }
    float4 v = src[idx - base];
    v.x = f2tf(v.x); v.y = f2tf(v.y); v.z = f2tf(v.z); v.w = f2tf(v.w);
    dst[idx] = v;
}

__device__ __forceinline__ void gemm_core128(
    const float* __restrict__ A, int lda,
    const float* __restrict__ B, int ldb,
    int K0, int K1, float acc[4][8][4], float* sm)
{
    const int tid = threadIdx.x;
    const int lane = tid & 31, warp = tid >> 5;
    const int wm = warp & 1, wn = warp >> 1;
    #pragma unroll
    for (int mt = 0; mt < 4; mt++)
        #pragma unroll
        for (int nt = 0; nt < 8; nt++)
            #pragma unroll
            for (int q = 0; q < 4; q++) acc[mt][nt][q] = 0.0f;

    const int nk = (K1 - K0) >> 4;
    auto load = [&](int it, int s) {
        int kt = K0 + it * 16;
        float* as = sm + s * 2560;
        float* bs = sm + 7680 + s * 2560;
        #pragma unroll
        for (int l = 0; l < 4; l++) {
            int idx = l * 128 + tid;
            int r = idx >> 2, c4 = (idx & 3) << 2;
            cp16(as + r * 20 + c4, A + (size_t)r * lda + kt + c4);
            cp16(bs + r * 20 + c4, B + (size_t)r * ldb + kt + c4);
        }
        cp_commit();
    };
    load(0, 0);
    if (nk > 1) load(1, 1);

    const unsigned smem_u = (unsigned)__cvta_generic_to_shared(sm);
    const int rowsel = lane & 15;
    const int colsel = (lane >> 4) << 2;
    const unsigned aOff = (unsigned)((wm * 64 + rowsel) * 20 + colsel);
    const unsigned bOff = (unsigned)(7680 + (wn * 64 + rowsel) * 20 + colsel);

    for (int it = 0; it < nk; it++) {
        if (it + 1 < nk) cp_wait1(); else cp_wait0();
        __syncthreads();
        if (it + 2 < nk) load(it + 2, (it + 2) % 3);
        const unsigned stageOff = (unsigned)((it % 3) * 2560);
        const unsigned aS = smem_u + (stageOff + aOff) * 4;
        const unsigned bS = smem_u + (stageOff + bOff) * 4;
        #pragma unroll
        for (int ks = 0; ks < 16; ks += 8) {
            unsigned af[4][4], bf[8][2];
            #pragma unroll
            for (int mt = 0; mt < 4; mt++)
                ldsm_x4(af[mt][0], af[mt][1], af[mt][2], af[mt][3],
                        aS + (mt * 16 * 20 + ks) * 4);
            #pragma unroll
            for (int p = 0; p < 4; p++) {
                unsigned r0, r1, r2, r3;
                ldsm_x4(r0, r1, r2, r3, bS + (p * 16 * 20 + ks) * 4);
                bf[2*p][0] = r0; bf[2*p+1][0] = r1;
                bf[2*p][1] = r2; bf[2*p+1][1] = r3;
            }
            #pragma unroll
            for (int mt = 0; mt < 4; mt++)
                #pragma unroll
                for (int nt = 0; nt < 8; nt++)
                    mma_tf32(acc[mt][nt], af[mt][0], af[mt][1], af[mt][2], af[mt][3],
                             bf[nt][0], bf[nt][1]);
        }
    }
}

__global__ __launch_bounds__(128, 2) void lin_gemm(
    const float* __restrict__ A, const float* __restrict__ W,
    const float* __restrict__ bias, float* __restrict__ C,
    int K, int N, int act)
{
    extern __shared__ float sm[];
    int m0 = blockIdx.y * 128, n0 = blockIdx.x * 128;
    float acc[4][8][4];
    gemm_core128(A + (size_t)m0 * K, K, W + (size_t)n0 * K, K, 0, K, acc, sm);
    const int lane = threadIdx.x & 31, warp = threadIdx.x >> 5;
    const int wm = warp & 1, wn = warp >> 1;
    const int grp = lane >> 2, tig = lane & 3;
    float* Cp = C + (size_t)m0 * N + n0;
    const float* bp = bias ? bias + n0 : nullptr;
    #pragma unroll
    for (int mt = 0; mt < 4; mt++) {
        int r0 = wm * 64 + mt * 16 + grp;
        #pragma unroll
        for (int nt = 0; nt < 8; nt++) {
            int c0 = wn * 64 + nt * 8 + tig * 2;
            float v0 = acc[mt][nt][0], v1 = acc[mt][nt][1];
            float v2 = acc[mt][nt][2], v3 = acc[mt][nt][3];
            if (act & 1) { float b0 = bp[c0], b1 = bp[c0 + 1];
                           v0 += b0; v1 += b1; v2 += b0; v3 += b1; }
            if (act & 2) { v0 = fmaxf(v0, 0.f); v1 = fmaxf(v1, 0.f);
                           v2 = fmaxf(v2, 0.f); v3 = fmaxf(v3, 0.f); }
            if (act & 4) { v0 = f2tf(v0); v1 = f2tf(v1); v2 = f2tf(v2); v3 = f2tf(v3); }
            *(float2*)(Cp + (size_t)r0 * N + c0) = make_float2(v0, v1);
            *(float2*)(Cp + (size_t)(r0 + 8) * N + c0) = make_float2(v2, v3);
        }
    }
}

__global__ __launch_bounds__(128, 2) void score_bd(
    const float* __restrict__ Qv, const float* __restrict__ rk,
    float* __restrict__ BD)
{
    extern __shared__ float sm[];
    int bh = blockIdx.z, h = bh & 7;
    int i0 = blockIdx.y * 128, p0 = blockIdx.x * 128;
    if (p0 + i0 < 896) return;
    float acc[4][8][4];
    gemm_core128(Qv + ((size_t)bh * QLEN + i0) * DHEAD, DHEAD,
                 rk + (size_t)p0 * DMODEL + h * DHEAD, DMODEL, 0, DHEAD, acc, sm);
    const int lane = threadIdx.x & 31, warp = threadIdx.x >> 5;
    const int wm = warp & 1, wn = warp >> 1;
    const int grp = lane >> 2, tig = lane & 3;
    float* Cp = BD + (size_t)bh * QK + (size_t)i0 * KLEN + p0;
    #pragma unroll
    for (int mt = 0; mt < 4; mt++) {
        int r0 = wm * 64 + mt * 16 + grp;
        #pragma unroll
        for (int nt = 0; nt < 8; nt++) {
            int c0 = wn * 64 + nt * 8 + tig * 2;
            *(float2*)(Cp + (size_t)r0 * KLEN + c0) =
                make_float2(acc[mt][nt][0], acc[mt][nt][1]);
            *(float2*)(Cp + (size_t)(r0 + 8) * KLEN + c0) =
                make_float2(acc[mt][nt][2], acc[mt][nt][3]);
        }
    }
}

__global__ __launch_bounds__(128, 2) void score_ac(
    const float* __restrict__ Qu, const float* __restrict__ qkv,
    const float* __restrict__ BD, float* __restrict__ S,
    float2* __restrict__ part_out)
{
    extern __shared__ float sm[];
    int bh = blockIdx.z, b = bh >> 3, h = bh & 7;
    int i0 = blockIdx.y * 128, j0 = blockIdx.x * 128;
    if (j0 - i0 > 1024) return;
    float acc[4][8][4];
    gemm_core128(Qu + ((size_t)bh * QLEN + i0) * DHEAD, DHEAD,
                 qkv + (size_t)j0 * QSTRIDE + b * QKVW + DMODEL + h * DHEAD, QSTRIDE,
                 0, DHEAD, acc, sm);
    const int tid = threadIdx.x;
    const int lane = tid & 31, warp = tid >> 5;
    const int wm = warp & 1, wn = warp >> 1;
    const int grp = lane >> 2, tig = lane & 3;
    const float* bdb = BD + (size_t)bh * QK;
    float* Sp = S + (size_t)bh * QK;
    #pragma unroll
    for (int mt = 0; mt < 4; mt++) {
        #pragma unroll
        for (int hh = 0; hh < 2; hh++) {
            int gi = i0 + wm * 64 + mt * 16 + grp + hh * 8;
            const float* bdr = bdb + (size_t)gi * KLEN;
            int jmax = gi + MEMLEN;
            #pragma unroll
            for (int nt = 0; nt < 8; nt++) {
                int gj = j0 + wn * 64 + nt * 8 + tig * 2;
                int p0 = min(gj - gi + (QLEN - 1), KLEN - 1);
                int p1 = min(p0 + 1, KLEN - 1);
                float v0 = (gj     <= jmax) ? (acc[mt][nt][hh*2+0] + bdr[p0]) * 0.125f : -1e30f;
                float v1 = (gj + 1 <= jmax) ? (acc[mt][nt][hh*2+1] + bdr[p1]) * 0.125f : -1e30f;
                acc[mt][nt][hh*2+0] = v0;
                acc[mt][nt][hh*2+1] = v1;
                *(float2*)(Sp + (size_t)gi * KLEN + gj) = make_float2(v0, v1);
            }
        }
    }
    __syncthreads();
    float2* part = (float2*)sm;
    #pragma unroll
    for (int mt = 0; mt < 4; mt++) {
        #pragma unroll
        for (int hh = 0; hh < 2; hh++) {
            float m = -1e30f;
            #pragma unroll
            for (int nt = 0; nt < 8; nt++) {
                m = fmaxf(m, acc[mt][nt][hh*2+0]);
                m = fmaxf(m, acc[mt][nt][hh*2+1]);
            }
            float s = 0.f;
            #pragma unroll
            for (int nt = 0; nt < 8; nt++) {
                s += __expf(acc[mt][nt][hh*2+0] - m);
                s += __expf(acc[mt][nt][hh*2+1] - m);
            }
            #pragma unroll
            for (int o = 1; o < 4; o <<= 1) {
                float m2 = __shfl_xor_sync(0xffffffffu, m, o);
                float s2 = __shfl_xor_sync(0xffffffffu, s, o);
                float mm = fmaxf(m, m2);
                s = s * __expf(m - mm) + s2 * __expf(m2 - mm);
                m = mm;
            }
            if (tig == 0)
                part[wn * 128 + wm * 64 + mt * 16 + hh * 8 + grp] = make_float2(m, s);
        }
    }
    __syncthreads();
    {
        float2 a = part[tid], c = part[128 + tid];
        float mm = fmaxf(a.x, c.x);
        float ss = a.y * __expf(a.x - mm) + c.y * __expf(c.x - mm);
        part_out[((size_t)bh * QLEN + i0 + tid) * 16 + (j0 >> 7)] = make_float2(mm, ss);
    }
}

__global__ void statcombine(const float2* __restrict__ part, float2* __restrict__ stat) {
    int id = blockIdx.x * 256 + threadIdx.x;
    if (id >= BH * QLEN) return;
    int i = id & (QLEN - 1);
    int ntl = (i >> 7) + 9; if (ntl > 16) ntl = 16;
    float M = -1e30f, Ssum = 0.f;
    const float2* p = part + (size_t)id * 16;
    for (int t = 0; t < ntl; t++) {
        float2 q = p[t];
        float mm = fmaxf(M, q.x);
        Ssum = Ssum * __expf(M - mm) + q.y * __expf(q.x - mm);
        M = mm;
    }
    stat[id] = make_float2(M, 1.0f / Ssum);
}

// prob output: 128-j tiles, float4 both sides, masked-tile fast path
__global__ void probout(const float* __restrict__ S, const float2* __restrict__ stat,
                        float* __restrict__ out) {
    __shared__ float t[128][33];
    __shared__ float m_s[32], inv_s[32];
    const int i = blockIdx.y, j0 = blockIdx.x * 128;
    const int tid = threadIdx.x;   // 256
    const int jmax = i + MEMLEN;
    float* obase = out + ((size_t)i * KLEN + j0) * 32;
    if (j0 > jmax) {
        float4 z = make_float4(0.f, 0.f, 0.f, 0.f);
        #pragma unroll
        for (int l = 0; l < 4; l++)
            ((float4*)obase)[l * 256 + tid] = z;
        return;
    }
    if (tid < 32) {
        float2 st = stat[tid * QLEN + i];
        m_s[tid] = st.x; inv_s[tid] = st.y;
    }
    __syncthreads();
    const int lb = tid >> 5, lj4 = tid & 31;
    #pragma unroll
    for (int r = 0; r < 4; r++) {
        int bh = r * 8 + lb;
        float4 v = *(const float4*)(S + ((size_t)bh * QLEN + i) * KLEN + j0 + lj4 * 4);
        float m = m_s[bh], iv = inv_s[bh];
        int j = j0 + lj4 * 4;
        t[lj4*4+0][bh] = (j     <= jmax) ? __expf(v.x - m) * iv : 0.f;
        t[lj4*4+1][bh] = (j + 1 <= jmax) ? __expf(v.y - m) * iv : 0.f;
        t[lj4*4+2][bh] = (j + 2 <= jmax) ? __expf(v.z - m) * iv : 0.f;
        t[lj4*4+3][bh] = (j + 3 <= jmax) ? __expf(v.w - m) * iv : 0.f;
    }
    __syncthreads();
    const int bh4 = (tid & 7) * 4;
    #pragma unroll
    for (int p = 0; p < 4; p++) {
        int jl = p * 32 + (tid >> 3);
        float4 w = make_float4(t[jl][bh4], t[jl][bh4+1], t[jl][bh4+2], t[jl][bh4+3]);
        *(float4*)(obase + (size_t)jl * 32 + bh4) = w;
    }
}

__global__ __launch_bounds__(128, 2) void attn_exp_gemm(
    const float* __restrict__ S, const float2* __restrict__ stat,
    const float* __restrict__ Vt, float* __restrict__ attn)
{
    const int bh = blockIdx.y, b = bh >> 3, h = bh & 7;
    const int i0 = blockIdx.x * 128;
    __shared__ __align__(16) float As[128][20];
    __shared__ __align__(16) float Bs[2][64][20];
    __shared__ float m_s[128], inv_s[128];
    const int tid = threadIdx.x;
    const int lane = tid & 31, warp = tid >> 5;
    const int wm = warp & 1, wn = warp >> 1;
    const int grp = lane >> 2, tig = lane & 3;
    {
        float2 st = stat[bh * QLEN + i0 + tid];
        m_s[tid] = st.x; inv_s[tid] = st.y;
    }
    __syncthreads();
    const float* Srow = S + (size_t)bh * QK + (size_t)i0 * KLEN;
    const float* Vb = Vt + (size_t)bh * DHEAD * KLEN;
    const int K1 = min(KLEN, i0 + 128 + MEMLEN);
    const int nk = K1 >> 4;

    float acc[4][4][4];
    #pragma unroll
    for (int mt = 0; mt < 4; mt++)
        #pragma unroll
        for (int nt = 0; nt < 4; nt++)
            #pragma unroll
            for (int q = 0; q < 4; q++) acc[mt][nt][q] = 0.f;

    float4 aReg[4];
    #pragma unroll
    for (int l = 0; l < 4; l++) {
        int idx = l * 128 + tid;
        int r = idx >> 2, c4 = (idx & 3) << 2;
        aReg[l] = *(const float4*)(Srow + (size_t)r * KLEN + c4);
    }
    #pragma unroll
    for (int l = 0; l < 2; l++) {
        int idx = l * 128 + tid;
        int r = idx >> 2, c4 = (idx & 3) << 2;
        cp16(&Bs[0][r][c4], Vb + (size_t)r * KLEN + c4);
    }
    cp_commit();

    const unsigned aBase = (unsigned)__cvta_generic_to_shared(&As[0][0]);
    const unsigned bBase = (unsigned)__cvta_generic_to_shared(&Bs[0][0][0]);
    const int rowsel = lane & 15;
    const int colsel = (lane >> 4) << 2;
    const unsigned aOff = aBase + (unsigned)(((wm * 64 + rowsel) * 20 + colsel) * 4);
    const unsigned bOff = bBase + (unsigned)(((wn * 32 + rowsel) * 20 + colsel) * 4);

    int cur = 0;
    for (int it = 0; it < nk; it++) {
        const int kt = it * 16;
        float4 aNext[4];
        if (it + 1 < nk) {
            int ktn = kt + 16;
            #pragma unroll
            for (int l = 0; l < 2; l++) {
                int idx = l * 128 + tid;
                int r = idx >> 2, c4 = (idx & 3) << 2;
                cp16(&Bs[cur ^ 1][r][c4], Vb + (size_t)r * KLEN + ktn + c4);
            }
            #pragma unroll
            for (int l = 0; l < 4; l++) {
                int idx = l * 128 + tid;
                int r = idx >> 2, c4 = (idx & 3) << 2;
                aNext[l] = *(const float4*)(Srow + (size_t)r * KLEN + ktn + c4);
            }
            cp_commit();
        }
        #pragma unroll
        for (int l = 0; l < 4; l++) {
            int idx = l * 128 + tid;
            int r = idx >> 2, c4 = (idx & 3) << 2;
            float mr = m_s[r];
            int jmax = i0 + r + MEMLEN;
            As[r][c4]     = (kt + c4 + 0 <= jmax) ? f2tf(__expf(aReg[l].x - mr)) : 0.f;
            As[r][c4 + 1] = (kt + c4 + 1 <= jmax) ? f2tf(__expf(aReg[l].y - mr)) : 0.f;
            As[r][c4 + 2] = (kt + c4 + 2 <= jmax) ? f2tf(__expf(aReg[l].z - mr)) : 0.f;
            As[r][c4 + 3] = (kt + c4 + 3 <= jmax) ? f2tf(__expf(aReg[l].w - mr)) : 0.f;
        }
        if (it + 1 < nk) cp_wait1(); else cp_wait0();
        __syncthreads();
        const unsigned bS = bOff + (unsigned)(cur * 64 * 20 * 4);
        #pragma unroll
        for (int ks = 0; ks < 16; ks += 8) {
            unsigned af[4][4], bf[4][2];
            #pragma unroll
            for (int mt = 0; mt < 4; mt++)
                ldsm_x4(af[mt][0], af[mt][1], af[mt][2], af[mt][3],
                        aOff + (mt * 16 * 20 + ks) * 4);
            #pragma unroll
            for (int p = 0; p < 2; p++) {
                unsigned r0, r1, r2, r3;
                ldsm_x4(r0, r1, r2, r3, bS + (p * 16 * 20 + ks) * 4);
                bf[2*p][0] = r0; bf[2*p+1][0] = r1;
                bf[2*p][1] = r2; bf[2*p+1][1] = r3;
            }
            #pragma unroll
            for (int mt = 0; mt < 4; mt++)
                #pragma unroll
                for (int nt = 0; nt < 4; nt++)
                    mma_tf32(acc[mt][nt], af[mt][0], af[mt][1], af[mt][2], af[mt][3],
                             bf[nt][0], bf[nt][1]);
        }
        __syncthreads();
        #pragma unroll
        for (int l = 0; l < 4; l++) aReg[l] = aNext[l];
        cur ^= 1;
    }
    #pragma unroll
    for (int mt = 0; mt < 4; mt++) {
        int r0 = wm * 64 + mt * 16 + grp;
        float iv0 = inv_s[r0], iv1 = inv_s[r0 + 8];
        #pragma unroll
        for (int nt = 0; nt < 4; nt++) {
            int c0 = wn * 32 + nt * 8 + tig * 2;
            float v0 = f2tf(acc[mt][nt][0] * iv0);
            float v1 = f2tf(acc[mt][nt][1] * iv0);
            float v2 = f2tf(acc[mt][nt][2] * iv1);
            float v3 = f2tf(acc[mt][nt][3] * iv1);
            size_t o0 = ((size_t)(i0 + r0) * BATCH + b) * DMODEL + h * DHEAD + c0;
            size_t o1 = ((size_t)(i0 + r0 + 8) * BATCH + b) * DMODEL + h * DHEAD + c0;
            *(float2*)(attn + o0) = make_float2(v0, v1);
            *(float2*)(attn + o1) = make_float2(v2, v3);
        }
    }
}

__global__ void prep_quv(const float* __restrict__ qkv, const float* __restrict__ u,
                         const float* __restrict__ v, float* __restrict__ Qu,
                         float* __restrict__ Qv) {
    int i = blockIdx.x, b = blockIdx.y, t = threadIdx.x;
    float q = qkv[(size_t)(MEMLEN + i) * QSTRIDE + b * QKVW + t];
    int h = t >> 6, d = t & 63;
    size_t o = ((size_t)(b * HEADS + h) * QLEN + i) * DHEAD + d;
    Qu[o] = f2tf(q + u[t]);
    Qv[o] = f2tf(q + v[t]);
}

__global__ void prep_vt(const float* __restrict__ qkv, float* __restrict__ Vt) {
    __shared__ float t[32][33];
    int bh = blockIdx.z, b = bh >> 3, h = bh & 7;
    int j0 = blockIdx.x * 32, d0 = blockIdx.y * 32;
    int tc = threadIdx.x & 31, tr = threadIdx.x >> 5;
    #pragma unroll
    for (int rr = 0; rr < 32; rr += 8)
        t[tr + rr][tc] = qkv[(size_t)(j0 + tr + rr) * QSTRIDE + b * QKVW
                             + 2 * DMODEL + h * DHEAD + d0 + tc];
    __syncthreads();
    #pragma unroll
    for (int rr = 0; rr < 32; rr += 8)
        Vt[((size_t)bh * DHEAD + d0 + tr + rr) * KLEN + j0 + tc] = t[tc][tr + rr];
}

__global__ void add_ln(const float* __restrict__ x1, const float* __restrict__ x2,
                       const float* __restrict__ g, const float* __restrict__ bb,
                       float* __restrict__ out, float* __restrict__ out_r) {
    const int row = blockIdx.x;
    const int tid = threadIdx.x;
    __shared__ float red[256];
    __shared__ float red2[256];
    const float* a = x1 + (size_t)row * DMODEL;
    const float* c = x2 + (size_t)row * DMODEL;
    float v0 = a[tid] + c[tid];
    float v1 = a[tid + 256] + c[tid + 256];
    red[tid] = v0 + v1;
    red2[tid] = v0 * v0 + v1 * v1;
    __syncthreads();
    for (int o = 128; o > 0; o >>= 1) {
        if (tid < o) { red[tid] += red[tid + o]; red2[tid] += red2[tid + o]; }
        __syncthreads();
    }
    const float mu = red[0] * (1.0f / DMODEL);
    const float var = red2[0] * (1.0f / DMODEL) - mu * mu;
    const float rstd = rsqrtf(var + 1e-5f);
    float* o = out + (size_t)row * DMODEL;
    float r0 = (v0 - mu) * rstd * g[tid] + bb[tid];
    float r1 = (v1 - mu) * rstd * g[tid + 256] + bb[tid + 256];
    o[tid] = r0;
    o[tid + 256] = r1;
    if (out_r) {
        float* orr = out_r + (size_t)row * DMODEL;
        orr[tid] = f2tf(r0);
        orr[tid + 256] = f2tf(r1);
    }
}

extern "C" void kernel_launch(void* const* d_in, const int* in_sizes, int n_in,
                              void* d_out, int out_size) {
    const float* inputs = (const float*)d_in[0];
    const float* r      = (const float*)d_in[1];
    const float* u      = (const float*)d_in[2];
    const float* v      = (const float*)d_in[3];
    const float* mem    = (const float*)d_in[4];
    const float* Wqkv   = (const float*)d_in[6];
    const float* Wr     = (const float*)d_in[7];
    const float* Wo     = (const float*)d_in[8];
    const float* ln1_g  = (const float*)d_in[9];
    const float* ln1_b  = (const float*)d_in[10];
    const float* w1     = (const float*)d_in[11];
    const float* b1     = (const float*)d_in[12];
    const float* w2     = (const float*)d_in[13];
    const float* b2     = (const float*)d_in[14];
    const float* ln2_g  = (const float*)d_in[15];
    const float* ln2_b  = (const float*)d_in[16];

    static cudaStream_t s2 = nullptr;
    static cudaEvent_t eFork = nullptr, eJoin = nullptr;
    if (!s2) {
        cudaFuncSetAttribute(lin_gemm, cudaFuncAttributeMaxDynamicSharedMemorySize, SMEM_DYN);
        cudaFuncSetAttribute(score_bd, cudaFuncAttributeMaxDynamicSharedMemorySize, SMEM_DYN);
        cudaFuncSetAttribute(score_ac, cudaFuncAttributeMaxDynamicSharedMemorySize, SMEM_DYN);
        cudaStreamCreateWithFlags(&s2, cudaStreamNonBlocking);
        cudaEventCreateWithFlags(&eFork, cudaEventDisableTiming);
        cudaEventCreateWithFlags(&eJoin, cudaEventDisableTiming);
    }

    float *qkvp, *rkp, *qup, *qvp, *vtp, *sp, *bdp, *attnp, *aop, *yp, *yrp, *hp, *zp, *rnd;
    float2 *statp, *partp;
    cudaGetSymbolAddress((void**)&qkvp,  g_qkv);
    cudaGetSymbolAddress((void**)&rkp,   g_rk);
    cudaGetSymbolAddress((void**)&qup,   g_qu);
    cudaGetSymbolAddress((void**)&qvp,   g_qv);
    cudaGetSymbolAddress((void**)&vtp,   g_vt);
    cudaGetSymbolAddress((void**)&sp,    g_S);
    cudaGetSymbolAddress((void**)&bdp,   g_BD);
    cudaGetSymbolAddress((void**)&statp, g_stat);
    cudaGetSymbolAddress((void**)&partp, g_part);
    cudaGetSymbolAddress((void**)&attnp, g_attn);
    cudaGetSymbolAddress((void**)&aop,   g_ao);
    cudaGetSymbolAddress((void**)&yp,    g_y);
    cudaGetSymbolAddress((void**)&yrp,   g_yr);
    cudaGetSymbolAddress((void**)&hp,    g_h);
    cudaGetSymbolAddress((void**)&zp,    g_z);
    cudaGetSymbolAddress((void**)&rnd,   g_rnd);

    const float* memr  = rnd;
    const float* rr    = rnd + OFF_R;
    const float* wqkvr = rnd + OFF_WQKV;
    const float* wrr   = rnd + OFF_WR;
    const float* wor   = rnd + OFF_WO;
    const float* w1r   = rnd + OFF_W1;
    const float* w2r   = rnd + OFF_W2;

    round_all<<<(2162688 + 255) / 256, 256>>>(mem, inputs, r, Wqkv, Wr, Wo, w1, w2,
                                              (float4*)rnd);
    lin_gemm<<<dim3(QKVW / 128, KROWS / 128), 128, SMEM_DYN>>>(memr, wqkvr, nullptr, qkvp,
                                                               DMODEL, QKVW, 4);
    lin_gemm<<<dim3(DMODEL / 128, KLEN / 128), 128, SMEM_DYN>>>(rr, wrr, nullptr, rkp,
                                                                DMODEL, DMODEL, 4);
    prep_quv<<<dim3(QLEN, BATCH), 512>>>(qkvp, u, v, qup, qvp);
    prep_vt<<<dim3(KLEN / 32, DHEAD / 32, BH), 256>>>(qkvp, vtp);
    score_bd<<<dim3(KLEN / 128, QLEN / 128, BH), 128, SMEM_DYN>>>(qvp, rkp, bdp);
    score_ac<<<dim3(KLEN / 128, QLEN / 128, BH), 128, SMEM_DYN>>>(qup, qkvp, bdp, sp, partp);
    statcombine<<<(BH * QLEN + 255) / 256, 256>>>(partp, statp);

    // fork: prob output runs on side stream, overlapped with the whole tail
    cudaEventRecord(eFork, 0);
    cudaStreamWaitEvent(s2, eFork, 0);
    float* prob_out = (float*)d_out + QLEN * BATCH * DMODEL;
    probout<<<dim3(KLEN / 128, QLEN), 256, 0, s2>>>(sp, statp, prob_out);
    cudaEventRecord(eJoin, s2);

    attn_exp_gemm<<<dim3(QLEN / 128, BH), 128>>>(sp, statp, vtp, attnp);
    lin_gemm<<<dim3(DMODEL / 128, QROWS / 128), 128, SMEM_DYN>>>(attnp, wor, nullptr, aop,
                                                                 DMODEL, DMODEL, 0);
    add_ln<<<QROWS, 256>>>(inputs, aop, ln1_g, ln1_b, yp, yrp);
    lin_gemm<<<dim3(DMLP / 128, QROWS / 128), 128, SMEM_DYN>>>(yrp, w1r, b1, hp,
                                                               DMODEL, DMLP, 7);
    lin_gemm<<<dim3(DMODEL / 128, QROWS / 128), 128, SMEM_DYN>>>(hp, w2r, b2, zp,
                                                                 DMLP, DMODEL, 1);
    add_ln<<<QROWS, 256>>>(yp, zp, ln2_g, ln2_b, (float*)d_out, nullptr);

    // join side stream back into the capture origin stream
    cudaStreamWaitEvent(0, eJoin, 0);
}

// round 11
// speedup vs baseline: 1.0202x; 1.0165x over previous
#include <cuda_runtime.h>
#include <cuda_bf16.h>
#include <math.h>

#define QLEN 1024
#define BATCH 4
#define DMODEL 512
#define HEADS 8
#define DHEAD 64
#define MEMLEN 1024
#define KLEN 2048
#define DMLP 2048
#define BH 32
#define QROWS 4096
#define KROWS 8192
#define QKVW 1536
#define QSTRIDE 6144
#define QK ((size_t)QLEN * KLEN)
#define SMEM_DYN 61440

__device__ float g_qkv[KROWS * QKVW];
__device__ float g_rk[KLEN * DMODEL];
__device__ float g_qu[BH * QLEN * DHEAD];
__device__ float g_qv[BH * QLEN * DHEAD];
__device__ float g_vt[BH * DHEAD * KLEN];
__device__ float g_S[(size_t)BH * QLEN * KLEN];
__device__ __nv_bfloat16 g_BDh[(size_t)BH * QLEN * KLEN];   // bf16 BD (128MB)
__device__ float2 g_part[(size_t)BH * QLEN * 16];
__device__ float2 g_stat[BH * QLEN];
__device__ float g_attn[QROWS * DMODEL];
__device__ float g_ao[QROWS * DMODEL];
__device__ float g_y[QROWS * DMODEL];
__device__ float g_yr[QROWS * DMODEL];
__device__ float g_h[QROWS * DMLP];
__device__ float g_z[QROWS * DMODEL];
__device__ float g_rnd[8650752];

#define OFF_R    4194304
#define OFF_WQKV 5242880
#define OFF_WR   6029312
#define OFF_WO   6291456
#define OFF_W1   6553600
#define OFF_W2   7602176

__device__ __forceinline__ float f2tf(float x) {
    unsigned r;
    asm("cvt.rna.tf32.f32 %0, %1;" : "=r"(r) : "f"(x));
    return __uint_as_float(r);
}
__device__ __forceinline__ void cp16(float* dst_smem, const float* src) {
    unsigned d = (unsigned)__cvta_generic_to_shared(dst_smem);
    asm volatile("cp.async.ca.shared.global [%0], [%1], 16;" :: "r"(d), "l"(src));
}
__device__ __forceinline__ void cp_commit() { asm volatile("cp.async.commit_group;"); }
__device__ __forceinline__ void cp_wait1()  { asm volatile("cp.async.wait_group 1;"); }
__device__ __forceinline__ void cp_wait0()  { asm volatile("cp.async.wait_group 0;"); }

__device__ __forceinline__ void mma_tf32(float* acc, unsigned a0, unsigned a1,
                                         unsigned a2, unsigned a3,
                                         unsigned b0, unsigned b1) {
    asm volatile(
        "mma.sync.aligned.m16n8k8.row.col.f32.tf32.tf32.f32 "
        "{%0,%1,%2,%3}, {%4,%5,%6,%7}, {%8,%9}, {%0,%1,%2,%3};"
        : "+f"(acc[0]), "+f"(acc[1]), "+f"(acc[2]), "+f"(acc[3])
        : "r"(a0), "r"(a1), "r"(a2), "r"(a3), "r"(b0), "r"(b1));
}
__device__ __forceinline__ void ldsm_x4(unsigned& r0, unsigned& r1, unsigned& r2,
                                        unsigned& r3, unsigned addr) {
    asm volatile("ldmatrix.sync.aligned.m8n8.x4.shared.b16 {%0,%1,%2,%3}, [%4];"
                 : "=r"(r0), "=r"(r1), "=r"(r2), "=r"(r3) : "r"(addr));
}

__global__ void round_all(const float* __restrict__ s0, const float* __restrict__ s1,
                          const float* __restrict__ s2, const float* __restrict__ s3,
                          const float* __restrict__ s4, const float* __restrict__ s5,
                          const float* __restrict__ s6, const float* __restrict__ s7,
                          float4* __restrict__ dst) {
    int idx = blockIdx.x * 256 + threadIdx.x;
    if (idx >= 2162688) return;
    const float4* src; int base;
    if      (idx < 524288)  { src = (const float4*)s0; base = 0; }
    else if (idx < 1048576) { src = (const float4*)s1; base = 524288; }
    else if (idx < 1310720) { src = (const float4*)s2; base = 1048576; }
    else if (idx < 1507328) { src = (const float4*)s3; base = 1310720; }
    else if (idx < 1572864) { src = (const float4*)s4; base = 1507328; }
    else if (idx < 1638400) { src = (const float4*)s5; base = 1572864; }
    else if (idx < 1900544) { src = (const float4*)s6; base = 1638400; }
    else                    { src = (const float4*)s7; base = 1900544; }
    float4 v = src[idx - base];
    v.x = f2tf(v.x); v.y = f2tf(v.y); v.z = f2tf(v.z); v.w = f2tf(v.w);
    dst[idx] = v;
}

__device__ __forceinline__ void gemm_core128(
    const float* __restrict__ A, int lda,
    const float* __restrict__ B, int ldb,
    int K0, int K1, float acc[4][8][4], float* sm)
{
    const int tid = threadIdx.x;
    const int lane = tid & 31, warp = tid >> 5;
    const int wm = warp & 1, wn = warp >> 1;
    #pragma unroll
    for (int mt = 0; mt < 4; mt++)
        #pragma unroll
        for (int nt = 0; nt < 8; nt++)
            #pragma unroll
            for (int q = 0; q < 4; q++) acc[mt][nt][q] = 0.0f;

    const int nk = (K1 - K0) >> 4;
    auto load = [&](int it, int s) {
        int kt = K0 + it * 16;
        float* as = sm + s * 2560;
        float* bs = sm + 7680 + s * 2560;
        #pragma unroll
        for (int l = 0; l < 4; l++) {
            int idx = l * 128 + tid;
            int r = idx >> 2, c4 = (idx & 3) << 2;
            cp16(as + r * 20 + c4, A + (size_t)r * lda + kt + c4);
            cp16(bs + r * 20 + c4, B + (size_t)r * ldb + kt + c4);
        }
        cp_commit();
    };
    load(0, 0);
    if (nk > 1) load(1, 1);

    const unsigned smem_u = (unsigned)__cvta_generic_to_shared(sm);
    const int rowsel = lane & 15;
    const int colsel = (lane >> 4) << 2;
    const unsigned aOff = (unsigned)((wm * 64 + rowsel) * 20 + colsel);
    const unsigned bOff = (unsigned)(7680 + (wn * 64 + rowsel) * 20 + colsel);

    for (int it = 0; it < nk; it++) {
        if (it + 1 < nk) cp_wait1(); else cp_wait0();
        __syncthreads();
        if (it + 2 < nk) load(it + 2, (it + 2) % 3);
        const unsigned stageOff = (unsigned)((it % 3) * 2560);
        const unsigned aS = smem_u + (stageOff + aOff) * 4;
        const unsigned bS = smem_u + (stageOff + bOff) * 4;
        #pragma unroll
        for (int ks = 0; ks < 16; ks += 8) {
            unsigned af[4][4], bf[8][2];
            #pragma unroll
            for (int mt = 0; mt < 4; mt++)
                ldsm_x4(af[mt][0], af[mt][1], af[mt][2], af[mt][3],
                        aS + (mt * 16 * 20 + ks) * 4);
            #pragma unroll
            for (int p = 0; p < 4; p++) {
                unsigned r0, r1, r2, r3;
                ldsm_x4(r0, r1, r2, r3, bS + (p * 16 * 20 + ks) * 4);
                bf[2*p][0] = r0; bf[2*p+1][0] = r1;
                bf[2*p][1] = r2; bf[2*p+1][1] = r3;
            }
            #pragma unroll
            for (int mt = 0; mt < 4; mt++)
                #pragma unroll
                for (int nt = 0; nt < 8; nt++)
                    mma_tf32(acc[mt][nt], af[mt][0], af[mt][1], af[mt][2], af[mt][3],
                             bf[nt][0], bf[nt][1]);
        }
    }
}

// linear GEMM; act: 1 bias, 2 relu, 4 round-out, 32 emit Qu/Qv from q-columns
__global__ __launch_bounds__(128, 2) void lin_gemm(
    const float* __restrict__ A, const float* __restrict__ W,
    const float* __restrict__ bias, float* __restrict__ C,
    const float* __restrict__ uu, const float* __restrict__ vv,
    float* __restrict__ Qu, float* __restrict__ Qv,
    int K, int N, int act)
{
    extern __shared__ float sm[];
    int m0 = blockIdx.y * 128, n0 = blockIdx.x * 128;
    float acc[4][8][4];
    gemm_core128(A + (size_t)m0 * K, K, W + (size_t)n0 * K, K, 0, K, acc, sm);
    const int lane = threadIdx.x & 31, warp = threadIdx.x >> 5;
    const int wm = warp & 1, wn = warp >> 1;
    const int grp = lane >> 2, tig = lane & 3;
    float* Cp = C + (size_t)m0 * N + n0;
    const float* bp = bias ? bias + n0 : nullptr;
    #pragma unroll
    for (int mt = 0; mt < 4; mt++) {
        int r0l = wm * 64 + mt * 16 + grp;
        #pragma unroll
        for (int nt = 0; nt < 8; nt++) {
            int c0 = wn * 64 + nt * 8 + tig * 2;
            float v0 = acc[mt][nt][0], v1 = acc[mt][nt][1];
            float v2 = acc[mt][nt][2], v3 = acc[mt][nt][3];
            if (act & 1) { float b0 = bp[c0], b1 = bp[c0 + 1];
                           v0 += b0; v1 += b1; v2 += b0; v3 += b1; }
            if (act & 2) { v0 = fmaxf(v0, 0.f); v1 = fmaxf(v1, 0.f);
                           v2 = fmaxf(v2, 0.f); v3 = fmaxf(v3, 0.f); }
            if (act & 32) {   // q-part rows >= 4096 (j >= MEMLEN), cols < 512
                int n = n0 + c0;
                if (n < DMODEL) {
                    float u0 = uu[n], u1 = uu[n + 1], w0 = vv[n], w1 = vv[n + 1];
                    int h = n >> 6, d = n & 63;
                    #pragma unroll
                    for (int hh = 0; hh < 2; hh++) {
                        int r = m0 + r0l + hh * 8;      // global row = j*4+b
                        if (r >= 4096) {
                            int j = (r >> 2) - MEMLEN, b = r & 3;
                            size_t o = ((size_t)(b * HEADS + h) * QLEN + j) * DHEAD + d;
                            float q0 = acc[mt][nt][hh * 2 + 0];
                            float q1 = acc[mt][nt][hh * 2 + 1];
                            Qu[o]     = f2tf(q0 + u0);
                            Qu[o + 1] = f2tf(q1 + u1);
                            Qv[o]     = f2tf(q0 + w0);
                            Qv[o + 1] = f2tf(q1 + w1);
                        }
                    }
                }
            }
            if (act & 4) { v0 = f2tf(v0); v1 = f2tf(v1); v2 = f2tf(v2); v3 = f2tf(v3); }
            *(float2*)(Cp + (size_t)r0l * N + c0) = make_float2(v0, v1);
            *(float2*)(Cp + (size_t)(r0l + 8) * N + c0) = make_float2(v2, v3);
        }
    }
}

// BD scores -> bf16
__global__ __launch_bounds__(128, 2) void score_bd(
    const float* __restrict__ Qv, const float* __restrict__ rk,
    __nv_bfloat16* __restrict__ BD)
{
    extern __shared__ float sm[];
    int bh = blockIdx.z, h = bh & 7;
    int i0 = blockIdx.y * 128, p0 = blockIdx.x * 128;
    if (p0 + i0 < 896) return;
    float acc[4][8][4];
    gemm_core128(Qv + ((size_t)bh * QLEN + i0) * DHEAD, DHEAD,
                 rk + (size_t)p0 * DMODEL + h * DHEAD, DMODEL, 0, DHEAD, acc, sm);
    const int lane = threadIdx.x & 31, warp = threadIdx.x >> 5;
    const int wm = warp & 1, wn = warp >> 1;
    const int grp = lane >> 2, tig = lane & 3;
    __nv_bfloat16* Cp = BD + (size_t)bh * QK + (size_t)i0 * KLEN + p0;
    #pragma unroll
    for (int mt = 0; mt < 4; mt++) {
        int r0 = wm * 64 + mt * 16 + grp;
        #pragma unroll
        for (int nt = 0; nt < 8; nt++) {
            int c0 = wn * 64 + nt * 8 + tig * 2;
            *(__nv_bfloat162*)(Cp + (size_t)r0 * KLEN + c0) =
                __float22bfloat162_rn(make_float2(acc[mt][nt][0], acc[mt][nt][1]));
            *(__nv_bfloat162*)(Cp + (size_t)(r0 + 8) * KLEN + c0) =
                __float22bfloat162_rn(make_float2(acc[mt][nt][2], acc[mt][nt][3]));
        }
    }
}

__global__ __launch_bounds__(128, 2) void score_ac(
    const float* __restrict__ Qu, const float* __restrict__ qkv,
    const __nv_bfloat16* __restrict__ BD, float* __restrict__ S,
    float2* __restrict__ part_out)
{
    extern __shared__ float sm[];
    int bh = blockIdx.z, b = bh >> 3, h = bh & 7;
    int i0 = blockIdx.y * 128, j0 = blockIdx.x * 128;
    if (j0 - i0 > 1024) return;
    float acc[4][8][4];
    gemm_core128(Qu + ((size_t)bh * QLEN + i0) * DHEAD, DHEAD,
                 qkv + (size_t)j0 * QSTRIDE + b * QKVW + DMODEL + h * DHEAD, QSTRIDE,
                 0, DHEAD, acc, sm);
    const int tid = threadIdx.x;
    const int lane = tid & 31, warp = tid >> 5;
    const int wm = warp & 1, wn = warp >> 1;
    const int grp = lane >> 2, tig = lane & 3;
    const __nv_bfloat16* bdb = BD + (size_t)bh * QK;
    float* Sp = S + (size_t)bh * QK;
    #pragma unroll
    for (int mt = 0; mt < 4; mt++) {
        #pragma unroll
        for (int hh = 0; hh < 2; hh++) {
            int gi = i0 + wm * 64 + mt * 16 + grp + hh * 8;
            const __nv_bfloat16* bdr = bdb + (size_t)gi * KLEN;
            int jmax = gi + MEMLEN;
            #pragma unroll
            for (int nt = 0; nt < 8; nt++) {
                int gj = j0 + wn * 64 + nt * 8 + tig * 2;
                int p0 = min(gj - gi + (QLEN - 1), KLEN - 1);
                int p1 = min(p0 + 1, KLEN - 1);
                float v0 = (gj <= jmax)
                    ? (acc[mt][nt][hh*2+0] + __bfloat162float(bdr[p0])) * 0.125f : -1e30f;
                float v1 = (gj + 1 <= jmax)
                    ? (acc[mt][nt][hh*2+1] + __bfloat162float(bdr[p1])) * 0.125f : -1e30f;
                acc[mt][nt][hh*2+0] = v0;
                acc[mt][nt][hh*2+1] = v1;
                *(float2*)(Sp + (size_t)gi * KLEN + gj) = make_float2(v0, v1);
            }
        }
    }
    __syncthreads();
    float2* part = (float2*)sm;
    #pragma unroll
    for (int mt = 0; mt < 4; mt++) {
        #pragma unroll
        for (int hh = 0; hh < 2; hh++) {
            float m = -1e30f;
            #pragma unroll
            for (int nt = 0; nt < 8; nt++) {
                m = fmaxf(m, acc[mt][nt][hh*2+0]);
                m = fmaxf(m, acc[mt][nt][hh*2+1]);
            }
            float s = 0.f;
            #pragma unroll
            for (int nt = 0; nt < 8; nt++) {
                s += __expf(acc[mt][nt][hh*2+0] - m);
                s += __expf(acc[mt][nt][hh*2+1] - m);
            }
            #pragma unroll
            for (int o = 1; o < 4; o <<= 1) {
                float m2 = __shfl_xor_sync(0xffffffffu, m, o);
                float s2 = __shfl_xor_sync(0xffffffffu, s, o);
                float mm = fmaxf(m, m2);
                s = s * __expf(m - mm) + s2 * __expf(m2 - mm);
                m = mm;
            }
            if (tig == 0)
                part[wn * 128 + wm * 64 + mt * 16 + hh * 8 + grp] = make_float2(m, s);
        }
    }
    __syncthreads();
    {
        float2 a = part[tid], c = part[128 + tid];
        float mm = fmaxf(a.x, c.x);
        float ss = a.y * __expf(a.x - mm) + c.y * __expf(c.x - mm);
        part_out[((size_t)bh * QLEN + i0 + tid) * 16 + (j0 >> 7)] = make_float2(mm, ss);
    }
}

__global__ void statcombine(const float2* __restrict__ part, float2* __restrict__ stat) {
    int id = blockIdx.x * 256 + threadIdx.x;
    if (id >= BH * QLEN) return;
    int i = id & (QLEN - 1);
    int ntl = (i >> 7) + 9; if (ntl > 16) ntl = 16;
    float M = -1e30f, Ssum = 0.f;
    const float2* p = part + (size_t)id * 16;
    for (int t = 0; t < ntl; t++) {
        float2 q = p[t];
        float mm = fmaxf(M, q.x);
        Ssum = Ssum * __expf(M - mm) + q.y * __expf(q.x - mm);
        M = mm;
    }
    stat[id] = make_float2(M, 1.0f / Ssum);
}

__global__ void probout(const float* __restrict__ S, const float2* __restrict__ stat,
                        float* __restrict__ out) {
    __shared__ float t[128][33];
    __shared__ float m_s[32], inv_s[32];
    const int i = blockIdx.y, j0 = blockIdx.x * 128;
    const int tid = threadIdx.x;
    const int jmax = i + MEMLEN;
    float* obase = out + ((size_t)i * KLEN + j0) * 32;
    if (j0 > jmax) {
        float4 z = make_float4(0.f, 0.f, 0.f, 0.f);
        #pragma unroll
        for (int l = 0; l < 4; l++)
            ((float4*)obase)[l * 256 + tid] = z;
        return;
    }
    if (tid < 32) {
        float2 st = stat[tid * QLEN + i];
        m_s[tid] = st.x; inv_s[tid] = st.y;
    }
    __syncthreads();
    const int lb = tid >> 5, lj4 = tid & 31;
    #pragma unroll
    for (int r = 0; r < 4; r++) {
        int bh = r * 8 + lb;
        float4 v = *(const float4*)(S + ((size_t)bh * QLEN + i) * KLEN + j0 + lj4 * 4);
        float m = m_s[bh], iv = inv_s[bh];
        int j = j0 + lj4 * 4;
        t[lj4*4+0][bh] = (j     <= jmax) ? __expf(v.x - m) * iv : 0.f;
        t[lj4*4+1][bh] = (j + 1 <= jmax) ? __expf(v.y - m) * iv : 0.f;
        t[lj4*4+2][bh] = (j + 2 <= jmax) ? __expf(v.z - m) * iv : 0.f;
        t[lj4*4+3][bh] = (j + 3 <= jmax) ? __expf(v.w - m) * iv : 0.f;
    }
    __syncthreads();
    const int bh4 = (tid & 7) * 4;
    #pragma unroll
    for (int p = 0; p < 4; p++) {
        int jl = p * 32 + (tid >> 3);
        float4 w = make_float4(t[jl][bh4], t[jl][bh4+1], t[jl][bh4+2], t[jl][bh4+3]);
        *(float4*)(obase + (size_t)jl * 32 + bh4) = w;
    }
}

__global__ __launch_bounds__(128, 2) void attn_exp_gemm(
    const float* __restrict__ S, const float2* __restrict__ stat,
    const float* __restrict__ Vt, float* __restrict__ attn)
{
    const int bh = blockIdx.y, b = bh >> 3, h = bh & 7;
    const int i0 = blockIdx.x * 128;
    __shared__ __align__(16) float As[128][20];
    __shared__ __align__(16) float Bs[2][64][20];
    __shared__ float m_s[128], inv_s[128];
    const int tid = threadIdx.x;
    const int lane = tid & 31, warp = tid >> 5;
    const int wm = warp & 1, wn = warp >> 1;
    const int grp = lane >> 2, tig = lane & 3;
    {
        float2 st = stat[bh * QLEN + i0 + tid];
        m_s[tid] = st.x; inv_s[tid] = st.y;
    }
    __syncthreads();
    const float* Srow = S + (size_t)bh * QK + (size_t)i0 * KLEN;
    const float* Vb = Vt + (size_t)bh * DHEAD * KLEN;
    const int K1 = min(KLEN, i0 + 128 + MEMLEN);
    const int nk = K1 >> 4;

    float acc[4][4][4];
    #pragma unroll
    for (int mt = 0; mt < 4; mt++)
        #pragma unroll
        for (int nt = 0; nt < 4; nt++)
            #pragma unroll
            for (int q = 0; q < 4; q++) acc[mt][nt][q] = 0.f;

    float4 aReg[4];
    #pragma unroll
    for (int l = 0; l < 4; l++) {
        int idx = l * 128 + tid;
        int r = idx >> 2, c4 = (idx & 3) << 2;
        aReg[l] = *(const float4*)(Srow + (size_t)r * KLEN + c4);
    }
    #pragma unroll
    for (int l = 0; l < 2; l++) {
        int idx = l * 128 + tid;
        int r = idx >> 2, c4 = (idx & 3) << 2;
        cp16(&Bs[0][r][c4], Vb + (size_t)r * KLEN + c4);
    }
    cp_commit();

    const unsigned aBase = (unsigned)__cvta_generic_to_shared(&As[0][0]);
    const unsigned bBase = (unsigned)__cvta_generic_to_shared(&Bs[0][0][0]);
    const int rowsel = lane & 15;
    const int colsel = (lane >> 4) << 2;
    const unsigned aOff = aBase + (unsigned)(((wm * 64 + rowsel) * 20 + colsel) * 4);
    const unsigned bOff = bBase + (unsigned)(((wn * 32 + rowsel) * 20 + colsel) * 4);

    int cur = 0;
    for (int it = 0; it < nk; it++) {
        const int kt = it * 16;
        float4 aNext[4];
        if (it + 1 < nk) {
            int ktn = kt + 16;
            #pragma unroll
            for (int l = 0; l < 2; l++) {
                int idx = l * 128 + tid;
                int r = idx >> 2, c4 = (idx & 3) << 2;
                cp16(&Bs[cur ^ 1][r][c4], Vb + (size_t)r * KLEN + ktn + c4);
            }
            #pragma unroll
            for (int l = 0; l < 4; l++) {
                int idx = l * 128 + tid;
                int r = idx >> 2, c4 = (idx & 3) << 2;
                aNext[l] = *(const float4*)(Srow + (size_t)r * KLEN + ktn + c4);
            }
            cp_commit();
        }
        #pragma unroll
        for (int l = 0; l < 4; l++) {
            int idx = l * 128 + tid;
            int r = idx >> 2, c4 = (idx & 3) << 2;
            float mr = m_s[r];
            int jmax = i0 + r + MEMLEN;
            As[r][c4]     = (kt + c4 + 0 <= jmax) ? f2tf(__expf(aReg[l].x - mr)) : 0.f;
            As[r][c4 + 1] = (kt + c4 + 1 <= jmax) ? f2tf(__expf(aReg[l].y - mr)) : 0.f;
            As[r][c4 + 2] = (kt + c4 + 2 <= jmax) ? f2tf(__expf(aReg[l].z - mr)) : 0.f;
            As[r][c4 + 3] = (kt + c4 + 3 <= jmax) ? f2tf(__expf(aReg[l].w - mr)) : 0.f;
        }
        if (it + 1 < nk) cp_wait1(); else cp_wait0();
        __syncthreads();
        const unsigned bS = bOff + (unsigned)(cur * 64 * 20 * 4);
        #pragma unroll
        for (int ks = 0; ks < 16; ks += 8) {
            unsigned af[4][4], bf[4][2];
            #pragma unroll
            for (int mt = 0; mt < 4; mt++)
                ldsm_x4(af[mt][0], af[mt][1], af[mt][2], af[mt][3],
                        aOff + (mt * 16 * 20 + ks) * 4);
            #pragma unroll
            for (int p = 0; p < 2; p++) {
                unsigned r0, r1, r2, r3;
                ldsm_x4(r0, r1, r2, r3, bS + (p * 16 * 20 + ks) * 4);
                bf[2*p][0] = r0; bf[2*p+1][0] = r1;
                bf[2*p][1] = r2; bf[2*p+1][1] = r3;
            }
            #pragma unroll
            for (int mt = 0; mt < 4; mt++)
                #pragma unroll
                for (int nt = 0; nt < 4; nt++)
                    mma_tf32(acc[mt][nt], af[mt][0], af[mt][1], af[mt][2], af[mt][3],
                             bf[nt][0], bf[nt][1]);
        }
        __syncthreads();
        #pragma unroll
        for (int l = 0; l < 4; l++) aReg[l] = aNext[l];
        cur ^= 1;
    }
    #pragma unroll
    for (int mt = 0; mt < 4; mt++) {
        int r0 = wm * 64 + mt * 16 + grp;
        float iv0 = inv_s[r0], iv1 = inv_s[r0 + 8];
        #pragma unroll
        for (int nt = 0; nt < 4; nt++) {
            int c0 = wn * 32 + nt * 8 + tig * 2;
            float v0 = f2tf(acc[mt][nt][0] * iv0);
            float v1 = f2tf(acc[mt][nt][1] * iv0);
            float v2 = f2tf(acc[mt][nt][2] * iv1);
            float v3 = f2tf(acc[mt][nt][3] * iv1);
            size_t o0 = ((size_t)(i0 + r0) * BATCH + b) * DMODEL + h * DHEAD + c0;
            size_t o1 = ((size_t)(i0 + r0 + 8) * BATCH + b) * DMODEL + h * DHEAD + c0;
            *(float2*)(attn + o0) = make_float2(v0, v1);
            *(float2*)(attn + o1) = make_float2(v2, v3);
        }
    }
}

__global__ void prep_vt(const float* __restrict__ qkv, float* __restrict__ Vt) {
    __shared__ float t[32][33];
    int bh = blockIdx.z, b = bh >> 3, h = bh & 7;
    int j0 = blockIdx.x * 32, d0 = blockIdx.y * 32;
    int tc = threadIdx.x & 31, tr = threadIdx.x >> 5;
    #pragma unroll
    for (int rr = 0; rr < 32; rr += 8)
        t[tr + rr][tc] = qkv[(size_t)(j0 + tr + rr) * QSTRIDE + b * QKVW
                             + 2 * DMODEL + h * DHEAD + d0 + tc];
    __syncthreads();
    #pragma unroll
    for (int rr = 0; rr < 32; rr += 8)
        Vt[((size_t)bh * DHEAD + d0 + tr + rr) * KLEN + j0 + tc] = t[tc][tr + rr];
}

__global__ void add_ln(const float* __restrict__ x1, const float* __restrict__ x2,
                       const float* __restrict__ g, const float* __restrict__ bb,
                       float* __restrict__ out, float* __restrict__ out_r) {
    const int row = blockIdx.x;
    const int tid = threadIdx.x;
    __shared__ float red[256];
    __shared__ float red2[256];
    const float* a = x1 + (size_t)row * DMODEL;
    const float* c = x2 + (size_t)row * DMODEL;
    float v0 = a[tid] + c[tid];
    float v1 = a[tid + 256] + c[tid + 256];
    red[tid] = v0 + v1;
    red2[tid] = v0 * v0 + v1 * v1;
    __syncthreads();
    for (int o = 128; o > 0; o >>= 1) {
        if (tid < o) { red[tid] += red[tid + o]; red2[tid] += red2[tid + o]; }
        __syncthreads();
    }
    const float mu = red[0] * (1.0f / DMODEL);
    const float var = red2[0] * (1.0f / DMODEL) - mu * mu;
    const float rstd = rsqrtf(var + 1e-5f);
    float* o = out + (size_t)row * DMODEL;
    float r0 = (v0 - mu) * rstd * g[tid] + bb[tid];
    float r1 = (v1 - mu) * rstd * g[tid + 256] + bb[tid + 256];
    o[tid] = r0;
    o[tid + 256] = r1;
    if (out_r) {
        float* orr = out_r + (size_t)row * DMODEL;
        orr[tid] = f2tf(r0);
        orr[tid + 256] = f2tf(r1);
    }
}

extern "C" void kernel_launch(void* const* d_in, const int* in_sizes, int n_in,
                              void* d_out, int out_size) {
    const float* inputs = (const float*)d_in[0];
    const float* r      = (const float*)d_in[1];
    const float* u      = (const float*)d_in[2];
    const float* v      = (const float*)d_in[3];
    const float* mem    = (const float*)d_in[4];
    const float* Wqkv   = (const float*)d_in[6];
    const float* Wr     = (const float*)d_in[7];
    const float* Wo     = (const float*)d_in[8];
    const float* ln1_g  = (const float*)d_in[9];
    const float* ln1_b  = (const float*)d_in[10];
    const float* w1     = (const float*)d_in[11];
    const float* b1     = (const float*)d_in[12];
    const float* w2     = (const float*)d_in[13];
    const float* b2     = (const float*)d_in[14];
    const float* ln2_g  = (const float*)d_in[15];
    const float* ln2_b  = (const float*)d_in[16];

    static cudaStream_t s2 = nullptr;
    static cudaEvent_t eFork = nullptr, eJoin = nullptr;
    if (!s2) {
        cudaFuncSetAttribute(lin_gemm, cudaFuncAttributeMaxDynamicSharedMemorySize, SMEM_DYN);
        cudaFuncSetAttribute(score_bd, cudaFuncAttributeMaxDynamicSharedMemorySize, SMEM_DYN);
        cudaFuncSetAttribute(score_ac, cudaFuncAttributeMaxDynamicSharedMemorySize, SMEM_DYN);
        cudaStreamCreateWithFlags(&s2, cudaStreamNonBlocking);
        cudaEventCreateWithFlags(&eFork, cudaEventDisableTiming);
        cudaEventCreateWithFlags(&eJoin, cudaEventDisableTiming);
    }

    float *qkvp, *rkp, *qup, *qvp, *vtp, *sp, *attnp, *aop, *yp, *yrp, *hp, *zp, *rnd;
    __nv_bfloat16* bdp;
    float2 *statp, *partp;
    cudaGetSymbolAddress((void**)&qkvp,  g_qkv);
    cudaGetSymbolAddress((void**)&rkp,   g_rk);
    cudaGetSymbolAddress((void**)&qup,   g_qu);
    cudaGetSymbolAddress((void**)&qvp,   g_qv);
    cudaGetSymbolAddress((void**)&vtp,   g_vt);
    cudaGetSymbolAddress((void**)&sp,    g_S);
    cudaGetSymbolAddress((void**)&bdp,   g_BDh);
    cudaGetSymbolAddress((void**)&statp, g_stat);
    cudaGetSymbolAddress((void**)&partp, g_part);
    cudaGetSymbolAddress((void**)&attnp, g_attn);
    cudaGetSymbolAddress((void**)&aop,   g_ao);
    cudaGetSymbolAddress((void**)&yp,    g_y);
    cudaGetSymbolAddress((void**)&yrp,   g_yr);
    cudaGetSymbolAddress((void**)&hp,    g_h);
    cudaGetSymbolAddress((void**)&zp,    g_z);
    cudaGetSymbolAddress((void**)&rnd,   g_rnd);

    const float* memr  = rnd;
    const float* rr    = rnd + OFF_R;
    const float* wqkvr = rnd + OFF_WQKV;
    const float* wrr   = rnd + OFF_WR;
    const float* wor   = rnd + OFF_WO;
    const float* w1r   = rnd + OFF_W1;
    const float* w2r   = rnd + OFF_W2;

    // 1: RNA rounding  2: qkv GEMM (+fused Qu/Qv)  3: rk  4: score_bd (profiled)
    round_all<<<(2162688 + 255) / 256, 256>>>(mem, inputs, r, Wqkv, Wr, Wo, w1, w2,
                                              (float4*)rnd);
    lin_gemm<<<dim3(QKVW / 128, KROWS / 128), 128, SMEM_DYN>>>(
        memr, wqkvr, nullptr, qkvp, u, v, qup, qvp, DMODEL, QKVW, 4 | 32);
    lin_gemm<<<dim3(DMODEL / 128, KLEN / 128), 128, SMEM_DYN>>>(
        rr, wrr, nullptr, rkp, nullptr, nullptr, nullptr, nullptr, DMODEL, DMODEL, 4);
    score_bd<<<dim3(KLEN / 128, QLEN / 128, BH), 128, SMEM_DYN>>>(qvp, rkp, bdp);
    // 5-7
    score_ac<<<dim3(KLEN / 128, QLEN / 128, BH), 128, SMEM_DYN>>>(qup, qkvp, bdp, sp, partp);
    prep_vt<<<dim3(KLEN / 32, DHEAD / 32, BH), 256>>>(qkvp, vtp);
    statcombine<<<(BH * QLEN + 255) / 256, 256>>>(partp, statp);
    // fork prob output onto side stream
    cudaEventRecord(eFork, 0);
    cudaStreamWaitEvent(s2, eFork, 0);
    float* prob_out = (float*)d_out + QLEN * BATCH * DMODEL;
    probout<<<dim3(KLEN / 128, QLEN), 256, 0, s2>>>(sp, statp, prob_out);
    cudaEventRecord(eJoin, s2);
    // tail
    attn_exp_gemm<<<dim3(QLEN / 128, BH), 128>>>(sp, statp, vtp, attnp);
    lin_gemm<<<dim3(DMODEL / 128, QROWS / 128), 128, SMEM_DYN>>>(
        attnp, wor, nullptr, aop, nullptr, nullptr, nullptr, nullptr, DMODEL, DMODEL, 0);
    add_ln<<<QROWS, 256>>>(inputs, aop, ln1_g, ln1_b, yp, yrp);
    lin_gemm<<<dim3(DMLP / 128, QROWS / 128), 128, SMEM_DYN>>>(
        yrp, w1r, b1, hp, nullptr, nullptr, nullptr, nullptr, DMODEL, DMLP, 7);
    lin_gemm<<<dim3(DMODEL / 128, QROWS / 128), 128, SMEM_DYN>>>(
        hp, w2r, b2, zp, nullptr, nullptr, nullptr, nullptr, DMLP, DMODEL, 1);
    add_ln<<<QROWS, 256>>>(yp, zp, ln2_g, ln2_b, (float*)d_out, nullptr);
    cudaStreamWaitEvent(0, eJoin, 0);
}

// round 12
// speedup vs baseline: 1.0640x; 1.0429x over previous
#include <cuda_runtime.h>
#include <cuda_bf16.h>
#include <math.h>

#define QLEN 1024
#define BATCH 4
#define DMODEL 512
#define HEADS 8
#define DHEAD 64
#define MEMLEN 1024
#define KLEN 2048
#define DMLP 2048
#define BH 32
#define QROWS 4096
#define KROWS 8192
#define QKVW 1536
#define QSTRIDE 6144
#define QK ((size_t)QLEN * KLEN)
#define SMEM_DYN 61440

__device__ float g_qkv[KROWS * QKVW];
__device__ float g_rk[KLEN * DMODEL];
__device__ float g_qu[BH * QLEN * DHEAD];
__device__ float g_qv[BH * QLEN * DHEAD];
__device__ float g_vt[BH * DHEAD * KLEN];
__device__ float g_S[(size_t)BH * QLEN * KLEN];
__device__ __nv_bfloat16 g_BDh[(size_t)BH * QLEN * KLEN];
__device__ float2 g_part[(size_t)BH * QLEN * 16];
__device__ float2 g_stat[BH * QLEN];
__device__ float g_attn[QROWS * DMODEL];
__device__ float g_ao[QROWS * DMODEL];
__device__ float g_y[QROWS * DMODEL];
__device__ float g_yr[QROWS * DMODEL];
__device__ float g_h[QROWS * DMLP];
__device__ float g_z[QROWS * DMODEL];
__device__ float g_rnd[8650752];

#define OFF_R    4194304
#define OFF_WQKV 5242880
#define OFF_WR   6029312
#define OFF_WO   6291456
#define OFF_W1   6553600
#define OFF_W2   7602176

__device__ __forceinline__ float f2tf(float x) {
    unsigned r;
    asm("cvt.rna.tf32.f32 %0, %1;" : "=r"(r) : "f"(x));
    return __uint_as_float(r);
}
__device__ __forceinline__ void cp16(float* dst_smem, const float* src) {
    unsigned d = (unsigned)__cvta_generic_to_shared(dst_smem);
    asm volatile("cp.async.ca.shared.global [%0], [%1], 16;" :: "r"(d), "l"(src));
}
__device__ __forceinline__ void cp_commit() { asm volatile("cp.async.commit_group;"); }
__device__ __forceinline__ void cp_wait1()  { asm volatile("cp.async.wait_group 1;"); }
__device__ __forceinline__ void cp_wait0()  { asm volatile("cp.async.wait_group 0;"); }

__device__ __forceinline__ void mma_tf32(float* acc, unsigned a0, unsigned a1,
                                         unsigned a2, unsigned a3,
                                         unsigned b0, unsigned b1) {
    asm volatile(
        "mma.sync.aligned.m16n8k8.row.col.f32.tf32.tf32.f32 "
        "{%0,%1,%2,%3}, {%4,%5,%6,%7}, {%8,%9}, {%0,%1,%2,%3};"
        : "+f"(acc[0]), "+f"(acc[1]), "+f"(acc[2]), "+f"(acc[3])
        : "r"(a0), "r"(a1), "r"(a2), "r"(a3), "r"(b0), "r"(b1));
}
__device__ __forceinline__ void ldsm_x4(unsigned& r0, unsigned& r1, unsigned& r2,
                                        unsigned& r3, unsigned addr) {
    asm volatile("ldmatrix.sync.aligned.m8n8.x4.shared.b16 {%0,%1,%2,%3}, [%4];"
                 : "=r"(r0), "=r"(r1), "=r"(r2), "=r"(r3) : "r"(addr));
}

__global__ void round_all(const float* __restrict__ s0, const float* __restrict__ s1,
                          const float* __restrict__ s2, const float* __restrict__ s3,
                          const float* __restrict__ s4, const float* __restrict__ s5,
                          const float* __restrict__ s6, const float* __restrict__ s7,
                          float4* __restrict__ dst) {
    int idx = blockIdx.x * 256 + threadIdx.x;
    if (idx >= 2162688) return;
    const float4* src; int base;
    if      (idx < 524288)  { src = (const float4*)s0; base = 0; }
    else if (idx < 1048576) { src = (const float4*)s1; base = 524288; }
    else if (idx < 1310720) { src = (const float4*)s2; base = 1048576; }
    else if (idx < 1507328) { src = (const float4*)s3; base = 1310720; }
    else if (idx < 1572864) { src = (const float4*)s4; base = 1507328; }
    else if (idx < 1638400) { src = (const float4*)s5; base = 1572864; }
    else if (idx < 1900544) { src = (const float4*)s6; base = 1638400; }
    else                    { src = (const float4*)s7; base = 1900544; }
    float4 v = src[idx - base];
    v.x = f2tf(v.x); v.y = f2tf(v.y); v.z = f2tf(v.z); v.w = f2tf(v.w);
    dst[idx] = v;
}

// ---- 128x128 tf32 NT GEMM core: 256 threads, 8 warps (2M x 4N), 64x32 tiles --
__device__ __forceinline__ void gemm_core256(
    const float* __restrict__ A, int lda,
    const float* __restrict__ B, int ldb,
    int K0, int K1, float acc[4][4][4], float* sm)
{
    const int tid = threadIdx.x;
    const int lane = tid & 31, warp = tid >> 5;
    const int wm = warp & 1, wn = warp >> 1;
    #pragma unroll
    for (int mt = 0; mt < 4; mt++)
        #pragma unroll
        for (int nt = 0; nt < 4; nt++)
            #pragma unroll
            for (int q = 0; q < 4; q++) acc[mt][nt][q] = 0.0f;

    const int nk = (K1 - K0) >> 4;
    auto load = [&](int it, int s) {
        int kt = K0 + it * 16;
        float* as = sm + s * 2560;
        float* bs = sm + 7680 + s * 2560;
        #pragma unroll
        for (int l = 0; l < 2; l++) {
            int idx = l * 256 + tid;
            int r = idx >> 2, c4 = (idx & 3) << 2;
            cp16(as + r * 20 + c4, A + (size_t)r * lda + kt + c4);
            cp16(bs + r * 20 + c4, B + (size_t)r * ldb + kt + c4);
        }
        cp_commit();
    };
    load(0, 0);
    if (nk > 1) load(1, 1);

    const unsigned smem_u = (unsigned)__cvta_generic_to_shared(sm);
    const int rowsel = lane & 15;
    const int colsel = (lane >> 4) << 2;
    const unsigned aOff = (unsigned)((wm * 64 + rowsel) * 20 + colsel);
    const unsigned bOff = (unsigned)(7680 + (wn * 32 + rowsel) * 20 + colsel);

    for (int it = 0; it < nk; it++) {
        if (it + 1 < nk) cp_wait1(); else cp_wait0();
        __syncthreads();
        if (it + 2 < nk) load(it + 2, (it + 2) % 3);
        const unsigned stageOff = (unsigned)((it % 3) * 2560);
        const unsigned aS = smem_u + (stageOff + aOff) * 4;
        const unsigned bS = smem_u + (stageOff + bOff) * 4;
        #pragma unroll
        for (int ks = 0; ks < 16; ks += 8) {
            unsigned af[4][4], bf[4][2];
            #pragma unroll
            for (int mt = 0; mt < 4; mt++)
                ldsm_x4(af[mt][0], af[mt][1], af[mt][2], af[mt][3],
                        aS + (mt * 16 * 20 + ks) * 4);
            #pragma unroll
            for (int p = 0; p < 2; p++) {
                unsigned r0, r1, r2, r3;
                ldsm_x4(r0, r1, r2, r3, bS + (p * 16 * 20 + ks) * 4);
                bf[2*p][0] = r0; bf[2*p+1][0] = r1;
                bf[2*p][1] = r2; bf[2*p+1][1] = r3;
            }
            #pragma unroll
            for (int mt = 0; mt < 4; mt++)
                #pragma unroll
                for (int nt = 0; nt < 4; nt++)
                    mma_tf32(acc[mt][nt], af[mt][0], af[mt][1], af[mt][2], af[mt][3],
                             bf[nt][0], bf[nt][1]);
        }
    }
}

// linear GEMM; act: 1 bias, 2 relu, 4 round-out, 32 emit Qu/Qv from q-columns
__global__ __launch_bounds__(256, 2) void lin_gemm(
    const float* __restrict__ A, const float* __restrict__ W,
    const float* __restrict__ bias, float* __restrict__ C,
    const float* __restrict__ uu, const float* __restrict__ vv,
    float* __restrict__ Qu, float* __restrict__ Qv,
    int K, int N, int act)
{
    extern __shared__ float sm[];
    int m0 = blockIdx.y * 128, n0 = blockIdx.x * 128;
    float acc[4][4][4];
    gemm_core256(A + (size_t)m0 * K, K, W + (size_t)n0 * K, K, 0, K, acc, sm);
    const int lane = threadIdx.x & 31, warp = threadIdx.x >> 5;
    const int wm = warp & 1, wn = warp >> 1;
    const int grp = lane >> 2, tig = lane & 3;
    float* Cp = C + (size_t)m0 * N + n0;
    const float* bp = bias ? bias + n0 : nullptr;
    #pragma unroll
    for (int mt = 0; mt < 4; mt++) {
        int r0l = wm * 64 + mt * 16 + grp;
        #pragma unroll
        for (int nt = 0; nt < 4; nt++) {
            int c0 = wn * 32 + nt * 8 + tig * 2;
            float v0 = acc[mt][nt][0], v1 = acc[mt][nt][1];
            float v2 = acc[mt][nt][2], v3 = acc[mt][nt][3];
            if (act & 1) { float b0 = bp[c0], b1 = bp[c0 + 1];
                           v0 += b0; v1 += b1; v2 += b0; v3 += b1; }
            if (act & 2) { v0 = fmaxf(v0, 0.f); v1 = fmaxf(v1, 0.f);
                           v2 = fmaxf(v2, 0.f); v3 = fmaxf(v3, 0.f); }
            if (act & 32) {
                int n = n0 + c0;
                if (n < DMODEL) {
                    float u0 = uu[n], u1 = uu[n + 1], w0 = vv[n], w1 = vv[n + 1];
                    int h = n >> 6, d = n & 63;
                    #pragma unroll
                    for (int hh = 0; hh < 2; hh++) {
                        int r = m0 + r0l + hh * 8;
                        if (r >= 4096) {
                            int j = (r >> 2) - MEMLEN, b = r & 3;
                            size_t o = ((size_t)(b * HEADS + h) * QLEN + j) * DHEAD + d;
                            float q0 = acc[mt][nt][hh * 2 + 0];
                            float q1 = acc[mt][nt][hh * 2 + 1];
                            Qu[o]     = f2tf(q0 + u0);
                            Qu[o + 1] = f2tf(q1 + u1);
                            Qv[o]     = f2tf(q0 + w0);
                            Qv[o + 1] = f2tf(q1 + w1);
                        }
                    }
                }
            }
            if (act & 4) { v0 = f2tf(v0); v1 = f2tf(v1); v2 = f2tf(v2); v3 = f2tf(v3); }
            *(float2*)(Cp + (size_t)r0l * N + c0) = make_float2(v0, v1);
            *(float2*)(Cp + (size_t)(r0l + 8) * N + c0) = make_float2(v2, v3);
        }
    }
}

// BD scores -> bf16
__global__ __launch_bounds__(256, 2) void score_bd(
    const float* __restrict__ Qv, const float* __restrict__ rk,
    __nv_bfloat16* __restrict__ BD)
{
    extern __shared__ float sm[];
    int bh = blockIdx.z, h = bh & 7;
    int i0 = blockIdx.y * 128, p0 = blockIdx.x * 128;
    if (p0 + i0 < 896) return;
    float acc[4][4][4];
    gemm_core256(Qv + ((size_t)bh * QLEN + i0) * DHEAD, DHEAD,
                 rk + (size_t)p0 * DMODEL + h * DHEAD, DMODEL, 0, DHEAD, acc, sm);
    const int lane = threadIdx.x & 31, warp = threadIdx.x >> 5;
    const int wm = warp & 1, wn = warp >> 1;
    const int grp = lane >> 2, tig = lane & 3;
    __nv_bfloat16* Cp = BD + (size_t)bh * QK + (size_t)i0 * KLEN + p0;
    #pragma unroll
    for (int mt = 0; mt < 4; mt++) {
        int r0 = wm * 64 + mt * 16 + grp;
        #pragma unroll
        for (int nt = 0; nt < 4; nt++) {
            int c0 = wn * 32 + nt * 8 + tig * 2;
            *(__nv_bfloat162*)(Cp + (size_t)r0 * KLEN + c0) =
                __float22bfloat162_rn(make_float2(acc[mt][nt][0], acc[mt][nt][1]));
            *(__nv_bfloat162*)(Cp + (size_t)(r0 + 8) * KLEN + c0) =
                __float22bfloat162_rn(make_float2(acc[mt][nt][2], acc[mt][nt][3]));
        }
    }
}

__global__ __launch_bounds__(256, 2) void score_ac(
    const float* __restrict__ Qu, const float* __restrict__ qkv,
    const __nv_bfloat16* __restrict__ BD, float* __restrict__ S,
    float2* __restrict__ part_out)
{
    extern __shared__ float sm[];
    int bh = blockIdx.z, b = bh >> 3, h = bh & 7;
    int i0 = blockIdx.y * 128, j0 = blockIdx.x * 128;
    if (j0 - i0 > 1024) return;
    float acc[4][4][4];
    gemm_core256(Qu + ((size_t)bh * QLEN + i0) * DHEAD, DHEAD,
                 qkv + (size_t)j0 * QSTRIDE + b * QKVW + DMODEL + h * DHEAD, QSTRIDE,
                 0, DHEAD, acc, sm);
    const int tid = threadIdx.x;
    const int lane = tid & 31, warp = tid >> 5;
    const int wm = warp & 1, wn = warp >> 1;
    const int grp = lane >> 2, tig = lane & 3;
    const __nv_bfloat16* bdb = BD + (size_t)bh * QK;
    float* Sp = S + (size_t)bh * QK;
    #pragma unroll
    for (int mt = 0; mt < 4; mt++) {
        #pragma unroll
        for (int hh = 0; hh < 2; hh++) {
            int gi = i0 + wm * 64 + mt * 16 + grp + hh * 8;
            const __nv_bfloat16* bdr = bdb + (size_t)gi * KLEN;
            int jmax = gi + MEMLEN;
            #pragma unroll
            for (int nt = 0; nt < 4; nt++) {
                int gj = j0 + wn * 32 + nt * 8 + tig * 2;
                int p0 = min(gj - gi + (QLEN - 1), KLEN - 1);
                int p1 = min(p0 + 1, KLEN - 1);
                float v0 = (gj <= jmax)
                    ? (acc[mt][nt][hh*2+0] + __bfloat162float(bdr[p0])) * 0.125f : -1e30f;
                float v1 = (gj + 1 <= jmax)
                    ? (acc[mt][nt][hh*2+1] + __bfloat162float(bdr[p1])) * 0.125f : -1e30f;
                acc[mt][nt][hh*2+0] = v0;
                acc[mt][nt][hh*2+1] = v1;
                *(float2*)(Sp + (size_t)gi * KLEN + gj) = make_float2(v0, v1);
            }
        }
    }
    __syncthreads();
    float2* part = (float2*)sm;           // [4 wn][128 rows]
    #pragma unroll
    for (int mt = 0; mt < 4; mt++) {
        #pragma unroll
        for (int hh = 0; hh < 2; hh++) {
            float m = -1e30f;
            #pragma unroll
            for (int nt = 0; nt < 4; nt++) {
                m = fmaxf(m, acc[mt][nt][hh*2+0]);
                m = fmaxf(m, acc[mt][nt][hh*2+1]);
            }
            float s = 0.f;
            #pragma unroll
            for (int nt = 0; nt < 4; nt++) {
                s += __expf(acc[mt][nt][hh*2+0] - m);
                s += __expf(acc[mt][nt][hh*2+1] - m);
            }
            #pragma unroll
            for (int o = 1; o < 4; o <<= 1) {
                float m2 = __shfl_xor_sync(0xffffffffu, m, o);
                float s2 = __shfl_xor_sync(0xffffffffu, s, o);
                float mm = fmaxf(m, m2);
                s = s * __expf(m - mm) + s2 * __expf(m2 - mm);
                m = mm;
            }
            if (tig == 0)
                part[wn * 128 + wm * 64 + mt * 16 + hh * 8 + grp] = make_float2(m, s);
        }
    }
    __syncthreads();
    if (tid < 128) {
        float2 a = part[tid];
        float M = a.x, Ssum = a.y;
        #pragma unroll
        for (int t = 1; t < 4; t++) {
            float2 c = part[t * 128 + tid];
            float mm = fmaxf(M, c.x);
            Ssum = Ssum * __expf(M - mm) + c.y * __expf(c.x - mm);
            M = mm;
        }
        part_out[((size_t)bh * QLEN + i0 + tid) * 16 + (j0 >> 7)] = make_float2(M, Ssum);
    }
}

__global__ void statcombine(const float2* __restrict__ part, float2* __restrict__ stat) {
    int id = blockIdx.x * 256 + threadIdx.x;
    if (id >= BH * QLEN) return;
    int i = id & (QLEN - 1);
    int ntl = (i >> 7) + 9; if (ntl > 16) ntl = 16;
    float M = -1e30f, Ssum = 0.f;
    const float2* p = part + (size_t)id * 16;
    for (int t = 0; t < ntl; t++) {
        float2 q = p[t];
        float mm = fmaxf(M, q.x);
        Ssum = Ssum * __expf(M - mm) + q.y * __expf(q.x - mm);
        M = mm;
    }
    stat[id] = make_float2(M, 1.0f / Ssum);
}

__global__ void probout(const float* __restrict__ S, const float2* __restrict__ stat,
                        float* __restrict__ out) {
    __shared__ float t[128][33];
    __shared__ float m_s[32], inv_s[32];
    const int i = blockIdx.y, j0 = blockIdx.x * 128;
    const int tid = threadIdx.x;
    const int jmax = i + MEMLEN;
    float* obase = out + ((size_t)i * KLEN + j0) * 32;
    if (j0 > jmax) {
        float4 z = make_float4(0.f, 0.f, 0.f, 0.f);
        #pragma unroll
        for (int l = 0; l < 4; l++)
            ((float4*)obase)[l * 256 + tid] = z;
        return;
    }
    if (tid < 32) {
        float2 st = stat[tid * QLEN + i];
        m_s[tid] = st.x; inv_s[tid] = st.y;
    }
    __syncthreads();
    const int lb = tid >> 5, lj4 = tid & 31;
    #pragma unroll
    for (int r = 0; r < 4; r++) {
        int bh = r * 8 + lb;
        float4 v = *(const float4*)(S + ((size_t)bh * QLEN + i) * KLEN + j0 + lj4 * 4);
        float m = m_s[bh], iv = inv_s[bh];
        int j = j0 + lj4 * 4;
        t[lj4*4+0][bh] = (j     <= jmax) ? __expf(v.x - m) * iv : 0.f;
        t[lj4*4+1][bh] = (j + 1 <= jmax) ? __expf(v.y - m) * iv : 0.f;
        t[lj4*4+2][bh] = (j + 2 <= jmax) ? __expf(v.z - m) * iv : 0.f;
        t[lj4*4+3][bh] = (j + 3 <= jmax) ? __expf(v.w - m) * iv : 0.f;
    }
    __syncthreads();
    const int bh4 = (tid & 7) * 4;
    #pragma unroll
    for (int p = 0; p < 4; p++) {
        int jl = p * 32 + (tid >> 3);
        float4 w = make_float4(t[jl][bh4], t[jl][bh4+1], t[jl][bh4+2], t[jl][bh4+3]);
        *(float4*)(obase + (size_t)jl * 32 + bh4) = w;
    }
}

__global__ __launch_bounds__(128, 2) void attn_exp_gemm(
    const float* __restrict__ S, const float2* __restrict__ stat,
    const float* __restrict__ Vt, float* __restrict__ attn)
{
    const int bh = blockIdx.y, b = bh >> 3, h = bh & 7;
    const int i0 = blockIdx.x * 128;
    __shared__ __align__(16) float As[128][20];
    __shared__ __align__(16) float Bs[2][64][20];
    __shared__ float m_s[128], inv_s[128];
    const int tid = threadIdx.x;
    const int lane = tid & 31, warp = tid >> 5;
    const int wm = warp & 1, wn = warp >> 1;
    const int grp = lane >> 2, tig = lane & 3;
    {
        float2 st = stat[bh * QLEN + i0 + tid];
        m_s[tid] = st.x; inv_s[tid] = st.y;
    }
    __syncthreads();
    const float* Srow = S + (size_t)bh * QK + (size_t)i0 * KLEN;
    const float* Vb = Vt + (size_t)bh * DHEAD * KLEN;
    const int K1 = min(KLEN, i0 + 128 + MEMLEN);
    const int nk = K1 >> 4;

    float acc[4][4][4];
    #pragma unroll
    for (int mt = 0; mt < 4; mt++)
        #pragma unroll
        for (int nt = 0; nt < 4; nt++)
            #pragma unroll
            for (int q = 0; q < 4; q++) acc[mt][nt][q] = 0.f;

    float4 aReg[4];
    #pragma unroll
    for (int l = 0; l < 4; l++) {
        int idx = l * 128 + tid;
        int r = idx >> 2, c4 = (idx & 3) << 2;
        aReg[l] = *(const float4*)(Srow + (size_t)r * KLEN + c4);
    }
    #pragma unroll
    for (int l = 0; l < 2; l++) {
        int idx = l * 128 + tid;
        int r = idx >> 2, c4 = (idx & 3) << 2;
        cp16(&Bs[0][r][c4], Vb + (size_t)r * KLEN + c4);
    }
    cp_commit();

    const unsigned aBase = (unsigned)__cvta_generic_to_shared(&As[0][0]);
    const unsigned bBase = (unsigned)__cvta_generic_to_shared(&Bs[0][0][0]);
    const int rowsel = lane & 15;
    const int colsel = (lane >> 4) << 2;
    const unsigned aOff = aBase + (unsigned)(((wm * 64 + rowsel) * 20 + colsel) * 4);
    const unsigned bOff = bBase + (unsigned)(((wn * 32 + rowsel) * 20 + colsel) * 4);

    int cur = 0;
    for (int it = 0; it < nk; it++) {
        const int kt = it * 16;
        float4 aNext[4];
        if (it + 1 < nk) {
            int ktn = kt + 16;
            #pragma unroll
            for (int l = 0; l < 2; l++) {
                int idx = l * 128 + tid;
                int r = idx >> 2, c4 = (idx & 3) << 2;
                cp16(&Bs[cur ^ 1][r][c4], Vb + (size_t)r * KLEN + ktn + c4);
            }
            #pragma unroll
            for (int l = 0; l < 4; l++) {
                int idx = l * 128 + tid;
                int r = idx >> 2, c4 = (idx & 3) << 2;
                aNext[l] = *(const float4*)(Srow + (size_t)r * KLEN + ktn + c4);
            }
            cp_commit();
        }
        #pragma unroll
        for (int l = 0; l < 4; l++) {
            int idx = l * 128 + tid;
            int r = idx >> 2, c4 = (idx & 3) << 2;
            float mr = m_s[r];
            int jmax = i0 + r + MEMLEN;
            As[r][c4]     = (kt + c4 + 0 <= jmax) ? f2tf(__expf(aReg[l].x - mr)) : 0.f;
            As[r][c4 + 1] = (kt + c4 + 1 <= jmax) ? f2tf(__expf(aReg[l].y - mr)) : 0.f;
            As[r][c4 + 2] = (kt + c4 + 2 <= jmax) ? f2tf(__expf(aReg[l].z - mr)) : 0.f;
            As[r][c4 + 3] = (kt + c4 + 3 <= jmax) ? f2tf(__expf(aReg[l].w - mr)) : 0.f;
        }
        if (it + 1 < nk) cp_wait1(); else cp_wait0();
        __syncthreads();
        const unsigned bS = bOff + (unsigned)(cur * 64 * 20 * 4);
        #pragma unroll
        for (int ks = 0; ks < 16; ks += 8) {
            unsigned af[4][4], bf[4][2];
            #pragma unroll
            for (int mt = 0; mt < 4; mt++)
                ldsm_x4(af[mt][0], af[mt][1], af[mt][2], af[mt][3],
                        aOff + (mt * 16 * 20 + ks) * 4);
            #pragma unroll
            for (int p = 0; p < 2; p++) {
                unsigned r0, r1, r2, r3;
                ldsm_x4(r0, r1, r2, r3, bS + (p * 16 * 20 + ks) * 4);
                bf[2*p][0] = r0; bf[2*p+1][0] = r1;
                bf[2*p][1] = r2; bf[2*p+1][1] = r3;
            }
            #pragma unroll
            for (int mt = 0; mt < 4; mt++)
                #pragma unroll
                for (int nt = 0; nt < 4; nt++)
                    mma_tf32(acc[mt][nt], af[mt][0], af[mt][1], af[mt][2], af[mt][3],
                             bf[nt][0], bf[nt][1]);
        }
        __syncthreads();
        #pragma unroll
        for (int l = 0; l < 4; l++) aReg[l] = aNext[l];
        cur ^= 1;
    }
    #pragma unroll
    for (int mt = 0; mt < 4; mt++) {
        int r0 = wm * 64 + mt * 16 + grp;
        float iv0 = inv_s[r0], iv1 = inv_s[r0 + 8];
        #pragma unroll
        for (int nt = 0; nt < 4; nt++) {
            int c0 = wn * 32 + nt * 8 + tig * 2;
            float v0 = f2tf(acc[mt][nt][0] * iv0);
            float v1 = f2tf(acc[mt][nt][1] * iv0);
            float v2 = f2tf(acc[mt][nt][2] * iv1);
            float v3 = f2tf(acc[mt][nt][3] * iv1);
            size_t o0 = ((size_t)(i0 + r0) * BATCH + b) * DMODEL + h * DHEAD + c0;
            size_t o1 = ((size_t)(i0 + r0 + 8) * BATCH + b) * DMODEL + h * DHEAD + c0;
            *(float2*)(attn + o0) = make_float2(v0, v1);
            *(float2*)(attn + o1) = make_float2(v2, v3);
        }
    }
}

__global__ void prep_vt(const float* __restrict__ qkv, float* __restrict__ Vt) {
    __shared__ float t[32][33];
    int bh = blockIdx.z, b = bh >> 3, h = bh & 7;
    int j0 = blockIdx.x * 32, d0 = blockIdx.y * 32;
    int tc = threadIdx.x & 31, tr = threadIdx.x >> 5;
    #pragma unroll
    for (int rr = 0; rr < 32; rr += 8)
        t[tr + rr][tc] = qkv[(size_t)(j0 + tr + rr) * QSTRIDE + b * QKVW
                             + 2 * DMODEL + h * DHEAD + d0 + tc];
    __syncthreads();
    #pragma unroll
    for (int rr = 0; rr < 32; rr += 8)
        Vt[((size_t)bh * DHEAD + d0 + tr + rr) * KLEN + j0 + tc] = t[tc][tr + rr];
}

__global__ void add_ln(const float* __restrict__ x1, const float* __restrict__ x2,
                       const float* __restrict__ g, const float* __restrict__ bb,
                       float* __restrict__ out, float* __restrict__ out_r) {
    const int row = blockIdx.x;
    const int tid = threadIdx.x;
    __shared__ float red[256];
    __shared__ float red2[256];
    const float* a = x1 + (size_t)row * DMODEL;
    const float* c = x2 + (size_t)row * DMODEL;
    float v0 = a[tid] + c[tid];
    float v1 = a[tid + 256] + c[tid + 256];
    red[tid] = v0 + v1;
    red2[tid] = v0 * v0 + v1 * v1;
    __syncthreads();
    for (int o = 128; o > 0; o >>= 1) {
        if (tid < o) { red[tid] += red[tid + o]; red2[tid] += red2[tid + o]; }
        __syncthreads();
    }
    const float mu = red[0] * (1.0f / DMODEL);
    const float var = red2[0] * (1.0f / DMODEL) - mu * mu;
    const float rstd = rsqrtf(var + 1e-5f);
    float* o = out + (size_t)row * DMODEL;
    float r0 = (v0 - mu) * rstd * g[tid] + bb[tid];
    float r1 = (v1 - mu) * rstd * g[tid + 256] + bb[tid + 256];
    o[tid] = r0;
    o[tid + 256] = r1;
    if (out_r) {
        float* orr = out_r + (size_t)row * DMODEL;
        orr[tid] = f2tf(r0);
        orr[tid + 256] = f2tf(r1);
    }
}

extern "C" void kernel_launch(void* const* d_in, const int* in_sizes, int n_in,
                              void* d_out, int out_size) {
    const float* inputs = (const float*)d_in[0];
    const float* r      = (const float*)d_in[1];
    const float* u      = (const float*)d_in[2];
    const float* v      = (const float*)d_in[3];
    const float* mem    = (const float*)d_in[4];
    const float* Wqkv   = (const float*)d_in[6];
    const float* Wr     = (const float*)d_in[7];
    const float* Wo     = (const float*)d_in[8];
    const float* ln1_g  = (const float*)d_in[9];
    const float* ln1_b  = (const float*)d_in[10];
    const float* w1     = (const float*)d_in[11];
    const float* b1     = (const float*)d_in[12];
    const float* w2     = (const float*)d_in[13];
    const float* b2     = (const float*)d_in[14];
    const float* ln2_g  = (const float*)d_in[15];
    const float* ln2_b  = (const float*)d_in[16];

    static cudaStream_t s2 = nullptr;
    static cudaEvent_t eFork = nullptr, eJoin = nullptr;
    if (!s2) {
        cudaFuncSetAttribute(lin_gemm, cudaFuncAttributeMaxDynamicSharedMemorySize, SMEM_DYN);
        cudaFuncSetAttribute(score_bd, cudaFuncAttributeMaxDynamicSharedMemorySize, SMEM_DYN);
        cudaFuncSetAttribute(score_ac, cudaFuncAttributeMaxDynamicSharedMemorySize, SMEM_DYN);
        cudaStreamCreateWithFlags(&s2, cudaStreamNonBlocking);
        cudaEventCreateWithFlags(&eFork, cudaEventDisableTiming);
        cudaEventCreateWithFlags(&eJoin, cudaEventDisableTiming);
    }

    float *qkvp, *rkp, *qup, *qvp, *vtp, *sp, *attnp, *aop, *yp, *yrp, *hp, *zp, *rnd;
    __nv_bfloat16* bdp;
    float2 *statp, *partp;
    cudaGetSymbolAddress((void**)&qkvp,  g_qkv);
    cudaGetSymbolAddress((void**)&rkp,   g_rk);
    cudaGetSymbolAddress((void**)&qup,   g_qu);
    cudaGetSymbolAddress((void**)&qvp,   g_qv);
    cudaGetSymbolAddress((void**)&vtp,   g_vt);
    cudaGetSymbolAddress((void**)&sp,    g_S);
    cudaGetSymbolAddress((void**)&bdp,   g_BDh);
    cudaGetSymbolAddress((void**)&statp, g_stat);
    cudaGetSymbolAddress((void**)&partp, g_part);
    cudaGetSymbolAddress((void**)&attnp, g_attn);
    cudaGetSymbolAddress((void**)&aop,   g_ao);
    cudaGetSymbolAddress((void**)&yp,    g_y);
    cudaGetSymbolAddress((void**)&yrp,   g_yr);
    cudaGetSymbolAddress((void**)&hp,    g_h);
    cudaGetSymbolAddress((void**)&zp,    g_z);
    cudaGetSymbolAddress((void**)&rnd,   g_rnd);

    const float* memr  = rnd;
    const float* rr    = rnd + OFF_R;
    const float* wqkvr = rnd + OFF_WQKV;
    const float* wrr   = rnd + OFF_WR;
    const float* wor   = rnd + OFF_WO;
    const float* w1r   = rnd + OFF_W1;
    const float* w2r   = rnd + OFF_W2;

    // 1: RNA rounding  2: qkv GEMM (+fused Qu/Qv)  3: rk  4: score_bd (profiled)
    round_all<<<(2162688 + 255) / 256, 256>>>(mem, inputs, r, Wqkv, Wr, Wo, w1, w2,
                                              (float4*)rnd);
    lin_gemm<<<dim3(QKVW / 128, KROWS / 128), 256, SMEM_DYN>>>(
        memr, wqkvr, nullptr, qkvp, u, v, qup, qvp, DMODEL, QKVW, 4 | 32);
    lin_gemm<<<dim3(DMODEL / 128, KLEN / 128), 256, SMEM_DYN>>>(
        rr, wrr, nullptr, rkp, nullptr, nullptr, nullptr, nullptr, DMODEL, DMODEL, 4);
    score_bd<<<dim3(KLEN / 128, QLEN / 128, BH), 256, SMEM_DYN>>>(qvp, rkp, bdp);
    // 5-7
    score_ac<<<dim3(KLEN / 128, QLEN / 128, BH), 256, SMEM_DYN>>>(qup, qkvp, bdp, sp, partp);
    prep_vt<<<dim3(KLEN / 32, DHEAD / 32, BH), 256>>>(qkvp, vtp);
    statcombine<<<(BH * QLEN + 255) / 256, 256>>>(partp, statp);
    // fork prob output onto side stream
    cudaEventRecord(eFork, 0);
    cudaStreamWaitEvent(s2, eFork, 0);
    float* prob_out = (float*)d_out + QLEN * BATCH * DMODEL;
    probout<<<dim3(KLEN / 128, QLEN), 256, 0, s2>>>(sp, statp, prob_out);
    cudaEventRecord(eJoin, s2);
    // tail
    attn_exp_gemm<<<dim3(QLEN / 128, BH), 128>>>(sp, statp, vtp, attnp);
    lin_gemm<<<dim3(DMODEL / 128, QROWS / 128), 256, SMEM_DYN>>>(
        attnp, wor, nullptr, aop, nullptr, nullptr, nullptr, nullptr, DMODEL, DMODEL, 0);
    add_ln<<<QROWS, 256>>>(inputs, aop, ln1_g, ln1_b, yp, yrp);
    lin_gemm<<<dim3(DMLP / 128, QROWS / 128), 256, SMEM_DYN>>>(
        yrp, w1r, b1, hp, nullptr, nullptr, nullptr, nullptr, DMODEL, DMLP, 7);
    lin_gemm<<<dim3(DMODEL / 128, QROWS / 128), 256, SMEM_DYN>>>(
        hp, w2r, b2, zp, nullptr, nullptr, nullptr, nullptr, DMLP, DMODEL, 1);
    add_ln<<<QROWS, 256>>>(yp, zp, ln2_g, ln2_b, (float*)d_out, nullptr);
    cudaStreamWaitEvent(0, eJoin, 0);
}

// round 13
// speedup vs baseline: 1.1039x; 1.0374x over previous
#include <cuda_runtime.h>
#include <cuda_bf16.h>
#include <cuda_fp16.h>
#include <math.h>

#define QLEN 1024
#define BATCH 4
#define DMODEL 512
#define HEADS 8
#define DHEAD 64
#define MEMLEN 1024
#define KLEN 2048
#define DMLP 2048
#define BH 32
#define QROWS 4096
#define KROWS 8192
#define QKVW 1536
#define QSTRIDE 6144
#define QK ((size_t)QLEN * KLEN)
#define SMEM_DYN 61440

__device__ float g_qkv[KROWS * QKVW];
__device__ float g_rk[KLEN * DMODEL];
__device__ __half g_quh[BH * QLEN * DHEAD];
__device__ __half g_qvh[BH * QLEN * DHEAD];
__device__ __half g_kh[BH * KLEN * DHEAD];
__device__ __half g_rkh[HEADS * KLEN * DHEAD];
__device__ float g_vt[BH * DHEAD * KLEN];
__device__ float g_S[(size_t)BH * QLEN * KLEN];
__device__ __half g_BDh[(size_t)BH * QLEN * KLEN];
__device__ float2 g_part[(size_t)BH * QLEN * 16];
__device__ float2 g_stat[BH * QLEN];
__device__ float g_attn[QROWS * DMODEL];
__device__ float g_ao[QROWS * DMODEL];
__device__ float g_y[QROWS * DMODEL];
__device__ float g_yr[QROWS * DMODEL];
__device__ float g_h[QROWS * DMLP];
__device__ float g_z[QROWS * DMODEL];
__device__ float g_rnd[8650752];

#define OFF_R    4194304
#define OFF_WQKV 5242880
#define OFF_WR   6029312
#define OFF_WO   6291456
#define OFF_W1   6553600
#define OFF_W2   7602176

__device__ __forceinline__ float f2tf(float x) {
    unsigned r;
    asm("cvt.rna.tf32.f32 %0, %1;" : "=r"(r) : "f"(x));
    return __uint_as_float(r);
}
__device__ __forceinline__ void cp16(float* dst_smem, const float* src) {
    unsigned d = (unsigned)__cvta_generic_to_shared(dst_smem);
    asm volatile("cp.async.ca.shared.global [%0], [%1], 16;" :: "r"(d), "l"(src));
}
__device__ __forceinline__ void cpa(unsigned dst, const void* src) {
    asm volatile("cp.async.ca.shared.global [%0], [%1], 16;" :: "r"(dst), "l"(src));
}
__device__ __forceinline__ void cp_commit() { asm volatile("cp.async.commit_group;"); }
__device__ __forceinline__ void cp_wait1()  { asm volatile("cp.async.wait_group 1;"); }
__device__ __forceinline__ void cp_wait0()  { asm volatile("cp.async.wait_group 0;"); }

__device__ __forceinline__ void mma_tf32(float* acc, unsigned a0, unsigned a1,
                                         unsigned a2, unsigned a3,
                                         unsigned b0, unsigned b1) {
    asm volatile(
        "mma.sync.aligned.m16n8k8.row.col.f32.tf32.tf32.f32 "
        "{%0,%1,%2,%3}, {%4,%5,%6,%7}, {%8,%9}, {%0,%1,%2,%3};"
        : "+f"(acc[0]), "+f"(acc[1]), "+f"(acc[2]), "+f"(acc[3])
        : "r"(a0), "r"(a1), "r"(a2), "r"(a3), "r"(b0), "r"(b1));
}
__device__ __forceinline__ void mma_f16(float* acc, unsigned a0, unsigned a1,
                                        unsigned a2, unsigned a3,
                                        unsigned b0, unsigned b1) {
    asm volatile(
        "mma.sync.aligned.m16n8k16.row.col.f32.f16.f16.f32 "
        "{%0,%1,%2,%3}, {%4,%5,%6,%7}, {%8,%9}, {%0,%1,%2,%3};"
        : "+f"(acc[0]), "+f"(acc[1]), "+f"(acc[2]), "+f"(acc[3])
        : "r"(a0), "r"(a1), "r"(a2), "r"(a3), "r"(b0), "r"(b1));
}
__device__ __forceinline__ void ldsm_x4(unsigned& r0, unsigned& r1, unsigned& r2,
                                        unsigned& r3, unsigned addr) {
    asm volatile("ldmatrix.sync.aligned.m8n8.x4.shared.b16 {%0,%1,%2,%3}, [%4];"
                 : "=r"(r0), "=r"(r1), "=r"(r2), "=r"(r3) : "r"(addr));
}

__global__ void round_all(const float* __restrict__ s0, const float* __restrict__ s1,
                          const float* __restrict__ s2, const float* __restrict__ s3,
                          const float* __restrict__ s4, const float* __restrict__ s5,
                          const float* __restrict__ s6, const float* __restrict__ s7,
                          float4* __restrict__ dst) {
    int idx = blockIdx.x * 256 + threadIdx.x;
    if (idx >= 2162688) return;
    const float4* src; int base;
    if      (idx < 524288)  { src = (const float4*)s0; base = 0; }
    else if (idx < 1048576) { src = (const float4*)s1; base = 524288; }
    else if (idx < 1310720) { src = (const float4*)s2; base = 1048576; }
    else if (idx < 1507328) { src = (const float4*)s3; base = 1310720; }
    else if (idx < 1572864) { src = (const float4*)s4; base = 1507328; }
    else if (idx < 1638400) { src = (const float4*)s5; base = 1572864; }
    else if (idx < 1900544) { src = (const float4*)s6; base = 1638400; }
    else                    { src = (const float4*)s7; base = 1900544; }
    float4 v = src[idx - base];
    v.x = f2tf(v.x); v.y = f2tf(v.y); v.z = f2tf(v.z); v.w = f2tf(v.w);
    dst[idx] = v;
}

// ---- tf32 core (linears): 256 threads, 8 warps (2M x 4N), 64x32 warp tiles --
__device__ __forceinline__ void gemm_core256(
    const float* __restrict__ A, int lda,
    const float* __restrict__ B, int ldb,
    int K0, int K1, float acc[4][4][4], float* sm)
{
    const int tid = threadIdx.x;
    const int lane = tid & 31, warp = tid >> 5;
    const int wm = warp & 1, wn = warp >> 1;
    #pragma unroll
    for (int mt = 0; mt < 4; mt++)
        #pragma unroll
        for (int nt = 0; nt < 4; nt++)
            #pragma unroll
            for (int q = 0; q < 4; q++) acc[mt][nt][q] = 0.0f;

    const int nk = (K1 - K0) >> 4;
    auto load = [&](int it, int s) {
        int kt = K0 + it * 16;
        float* as = sm + s * 2560;
        float* bs = sm + 7680 + s * 2560;
        #pragma unroll
        for (int l = 0; l < 2; l++) {
            int idx = l * 256 + tid;
            int r = idx >> 2, c4 = (idx & 3) << 2;
            cp16(as + r * 20 + c4, A + (size_t)r * lda + kt + c4);
            cp16(bs + r * 20 + c4, B + (size_t)r * ldb + kt + c4);
        }
        cp_commit();
    };
    load(0, 0);
    if (nk > 1) load(1, 1);

    const unsigned smem_u = (unsigned)__cvta_generic_to_shared(sm);
    const int rowsel = lane & 15;
    const int colsel = (lane >> 4) << 2;
    const unsigned aOff = (unsigned)((wm * 64 + rowsel) * 20 + colsel);
    const unsigned bOff = (unsigned)(7680 + (wn * 32 + rowsel) * 20 + colsel);

    for (int it = 0; it < nk; it++) {
        if (it + 1 < nk) cp_wait1(); else cp_wait0();
        __syncthreads();
        if (it + 2 < nk) load(it + 2, (it + 2) % 3);
        const unsigned stageOff = (unsigned)((it % 3) * 2560);
        const unsigned aS = smem_u + (stageOff + aOff) * 4;
        const unsigned bS = smem_u + (stageOff + bOff) * 4;
        #pragma unroll
        for (int ks = 0; ks < 16; ks += 8) {
            unsigned af[4][4], bf[4][2];
            #pragma unroll
            for (int mt = 0; mt < 4; mt++)
                ldsm_x4(af[mt][0], af[mt][1], af[mt][2], af[mt][3],
                        aS + (mt * 16 * 20 + ks) * 4);
            #pragma unroll
            for (int p = 0; p < 2; p++) {
                unsigned r0, r1, r2, r3;
                ldsm_x4(r0, r1, r2, r3, bS + (p * 16 * 20 + ks) * 4);
                bf[2*p][0] = r0; bf[2*p+1][0] = r1;
                bf[2*p][1] = r2; bf[2*p+1][1] = r3;
            }
            #pragma unroll
            for (int mt = 0; mt < 4; mt++)
                #pragma unroll
                for (int nt = 0; nt < 4; nt++)
                    mma_tf32(acc[mt][nt], af[mt][0], af[mt][1], af[mt][2], af[mt][3],
                             bf[nt][0], bf[nt][1]);
        }
    }
}

// ---- fp16 core (scores): 256 threads, 8 warps, k16 chunks, 48B row stride ---
__device__ __forceinline__ void gemm_core256h(
    const __half* __restrict__ A, int lda,
    const __half* __restrict__ B, int ldb,
    int K, float acc[4][4][4], char* smc)
{
    const int tid = threadIdx.x;
    const int lane = tid & 31, warp = tid >> 5;
    const int wm = warp & 1, wn = warp >> 1;
    #pragma unroll
    for (int mt = 0; mt < 4; mt++)
        #pragma unroll
        for (int nt = 0; nt < 4; nt++)
            #pragma unroll
            for (int q = 0; q < 4; q++) acc[mt][nt][q] = 0.0f;

    const unsigned sbase = (unsigned)__cvta_generic_to_shared(smc);
    const int nk = K >> 4;
    const int r = tid >> 1, qh = tid & 1;   // 128 rows x 2 16B chunks
    auto load = [&](int it, int s) {
        int kt = it * 16;
        unsigned as = sbase + s * 6144;
        unsigned bs = sbase + 18432 + s * 6144;
        cpa(as + r * 48 + qh * 16, A + (size_t)r * lda + kt + qh * 8);
        cpa(bs + r * 48 + qh * 16, B + (size_t)r * ldb + kt + qh * 8);
        cp_commit();
    };
    load(0, 0);
    if (nk > 1) load(1, 1);

    const unsigned aOff = (unsigned)((wm * 64 + (lane & 15)) * 48 + (lane >> 4) * 16);
    const unsigned bOff = (unsigned)(18432 + (wn * 32 + (lane & 15)) * 48 + (lane >> 4) * 16);

    for (int it = 0; it < nk; it++) {
        if (it + 1 < nk) cp_wait1(); else cp_wait0();
        __syncthreads();
        if (it + 2 < nk) load(it + 2, (it + 2) % 3);
        const unsigned st = (unsigned)((it % 3) * 6144);
        const unsigned aS = sbase + st + aOff;
        const unsigned bS = sbase + st + bOff;
        unsigned af[4][4], bf[4][2];
        #pragma unroll
        for (int mt = 0; mt < 4; mt++)
            ldsm_x4(af[mt][0], af[mt][1], af[mt][2], af[mt][3], aS + mt * 16 * 48);
        #pragma unroll
        for (int p = 0; p < 2; p++) {
            unsigned r0, r1, r2, r3;
            ldsm_x4(r0, r1, r2, r3, bS + p * 16 * 48);
            bf[2*p][0] = r0; bf[2*p+1][0] = r1;
            bf[2*p][1] = r2; bf[2*p+1][1] = r3;
        }
        #pragma unroll
        for (int mt = 0; mt < 4; mt++)
            #pragma unroll
            for (int nt = 0; nt < 4; nt++)
                mma_f16(acc[mt][nt], af[mt][0], af[mt][1], af[mt][2], af[mt][3],
                        bf[nt][0], bf[nt][1]);
    }
}

// linear GEMM; act: 1 bias, 2 relu, 4 round-out, 32 qkv-aux (Quh/Qvh/Kh), 64 rkh
__global__ __launch_bounds__(256, 2) void lin_gemm(
    const float* __restrict__ A, const float* __restrict__ W,
    const float* __restrict__ bias, float* __restrict__ C,
    const float* __restrict__ uu, const float* __restrict__ vv,
    __half* __restrict__ H1, __half* __restrict__ H2, __half* __restrict__ H3,
    int K, int N, int act)
{
    extern __shared__ float sm[];
    int m0 = blockIdx.y * 128, n0 = blockIdx.x * 128;
    float acc[4][4][4];
    gemm_core256(A + (size_t)m0 * K, K, W + (size_t)n0 * K, K, 0, K, acc, sm);
    const int lane = threadIdx.x & 31, warp = threadIdx.x >> 5;
    const int wm = warp & 1, wn = warp >> 1;
    const int grp = lane >> 2, tig = lane & 3;
    float* Cp = C + (size_t)m0 * N + n0;
    const float* bp = bias ? bias + n0 : nullptr;
    #pragma unroll
    for (int mt = 0; mt < 4; mt++) {
        int r0l = wm * 64 + mt * 16 + grp;
        #pragma unroll
        for (int nt = 0; nt < 4; nt++) {
            int c0 = wn * 32 + nt * 8 + tig * 2;
            float v0 = acc[mt][nt][0], v1 = acc[mt][nt][1];
            float v2 = acc[mt][nt][2], v3 = acc[mt][nt][3];
            if (act & 1) { float b0 = bp[c0], b1 = bp[c0 + 1];
                           v0 += b0; v1 += b1; v2 += b0; v3 += b1; }
            if (act & 2) { v0 = fmaxf(v0, 0.f); v1 = fmaxf(v1, 0.f);
                           v2 = fmaxf(v2, 0.f); v3 = fmaxf(v3, 0.f); }
            if (act & 32) {   // qkv aux: H1=Quh, H2=Qvh, H3=Kh
                int n = n0 + c0;
                #pragma unroll
                for (int hh = 0; hh < 2; hh++) {
                    int rg = m0 + r0l + hh * 8;
                    float q0 = acc[mt][nt][hh * 2 + 0];
                    float q1 = acc[mt][nt][hh * 2 + 1];
                    if (n < DMODEL) {
                        if (rg >= 4096) {
                            int j = (rg >> 2) - MEMLEN, b = rg & 3;
                            int h = n >> 6, d = n & 63;
                            size_t o = ((size_t)(b * HEADS + h) * QLEN + j) * DHEAD + d;
                            *(__half2*)(H1 + o) = __floats2half2_rn(q0 + uu[n], q1 + uu[n + 1]);
                            *(__half2*)(H2 + o) = __floats2half2_rn(q0 + vv[n], q1 + vv[n + 1]);
                        }
                    } else if (n < 2 * DMODEL) {
                        int j = rg >> 2, b = rg & 3;
                        int nn = n - DMODEL, h = nn >> 6, d = nn & 63;
                        size_t o = ((size_t)(b * HEADS + h) * KLEN + j) * DHEAD + d;
                        *(__half2*)(H3 + o) = __floats2half2_rn(q0, q1);
                    }
                }
            }
            if (act & 64) {   // rkh: H1, packed [h][p][64]
                int n = n0 + c0;
                int h = n >> 6, d = n & 63;
                #pragma unroll
                for (int hh = 0; hh < 2; hh++) {
                    int p = m0 + r0l + hh * 8;
                    size_t o = ((size_t)h * KLEN + p) * DHEAD + d;
                    *(__half2*)(H1 + o) =
                        __floats2half2_rn(acc[mt][nt][hh*2+0], acc[mt][nt][hh*2+1]);
                }
            }
            if (act & 4) { v0 = f2tf(v0); v1 = f2tf(v1); v2 = f2tf(v2); v3 = f2tf(v3); }
            *(float2*)(Cp + (size_t)r0l * N + c0) = make_float2(v0, v1);
            *(float2*)(Cp + (size_t)(r0l + 8) * N + c0) = make_float2(v2, v3);
        }
    }
}

// BD scores (fp16 in, fp16 out)
__global__ __launch_bounds__(256, 2) void score_bd(
    const __half* __restrict__ Qv, const __half* __restrict__ rkh,
    __half* __restrict__ BD)
{
    extern __shared__ float smf[];
    char* smc = (char*)smf;
    int bh = blockIdx.z, h = bh & 7;
    int i0 = blockIdx.y * 128, p0 = blockIdx.x * 128;
    if (p0 + i0 < 896) return;
    float acc[4][4][4];
    gemm_core256h(Qv + ((size_t)bh * QLEN + i0) * DHEAD, DHEAD,
                  rkh + ((size_t)h * KLEN + p0) * DHEAD, DHEAD, DHEAD, acc, smc);
    const int lane = threadIdx.x & 31, warp = threadIdx.x >> 5;
    const int wm = warp & 1, wn = warp >> 1;
    const int grp = lane >> 2, tig = lane & 3;
    __half* Cp = BD + (size_t)bh * QK + (size_t)i0 * KLEN + p0;
    #pragma unroll
    for (int mt = 0; mt < 4; mt++) {
        int r0 = wm * 64 + mt * 16 + grp;
        #pragma unroll
        for (int nt = 0; nt < 4; nt++) {
            int c0 = wn * 32 + nt * 8 + tig * 2;
            *(__half2*)(Cp + (size_t)r0 * KLEN + c0) =
                __floats2half2_rn(acc[mt][nt][0], acc[mt][nt][1]);
            *(__half2*)(Cp + (size_t)(r0 + 8) * KLEN + c0) =
                __floats2half2_rn(acc[mt][nt][2], acc[mt][nt][3]);
        }
    }
}

__global__ __launch_bounds__(256, 2) void score_ac(
    const __half* __restrict__ Qu, const __half* __restrict__ Kh,
    const __half* __restrict__ BD, float* __restrict__ S,
    float2* __restrict__ part_out)
{
    extern __shared__ float smf[];
    char* smc = (char*)smf;
    int bh = blockIdx.z;
    int i0 = blockIdx.y * 128, j0 = blockIdx.x * 128;
    if (j0 - i0 > 1024) return;
    float acc[4][4][4];
    gemm_core256h(Qu + ((size_t)bh * QLEN + i0) * DHEAD, DHEAD,
                  Kh + ((size_t)bh * KLEN + j0) * DHEAD, DHEAD, DHEAD, acc, smc);
    const int tid = threadIdx.x;
    const int lane = tid & 31, warp = tid >> 5;
    const int wm = warp & 1, wn = warp >> 1;
    const int grp = lane >> 2, tig = lane & 3;
    const __half* bdb = BD + (size_t)bh * QK;
    float* Sp = S + (size_t)bh * QK;
    #pragma unroll
    for (int mt = 0; mt < 4; mt++) {
        #pragma unroll
        for (int hh = 0; hh < 2; hh++) {
            int gi = i0 + wm * 64 + mt * 16 + grp + hh * 8;
            const __half* bdr = bdb + (size_t)gi * KLEN;
            int jmax = gi + MEMLEN;
            #pragma unroll
            for (int nt = 0; nt < 4; nt++) {
                int gj = j0 + wn * 32 + nt * 8 + tig * 2;
                int p0 = min(gj - gi + (QLEN - 1), KLEN - 1);
                int p1 = min(p0 + 1, KLEN - 1);
                float v0 = (gj <= jmax)
                    ? (acc[mt][nt][hh*2+0] + __half2float(bdr[p0])) * 0.125f : -1e30f;
                float v1 = (gj + 1 <= jmax)
                    ? (acc[mt][nt][hh*2+1] + __half2float(bdr[p1])) * 0.125f : -1e30f;
                acc[mt][nt][hh*2+0] = v0;
                acc[mt][nt][hh*2+1] = v1;
                *(float2*)(Sp + (size_t)gi * KLEN + gj) = make_float2(v0, v1);
            }
        }
    }
    __syncthreads();
    float2* part = (float2*)smf;
    #pragma unroll
    for (int mt = 0; mt < 4; mt++) {
        #pragma unroll
        for (int hh = 0; hh < 2; hh++) {
            float m = -1e30f;
            #pragma unroll
            for (int nt = 0; nt < 4; nt++) {
                m = fmaxf(m, acc[mt][nt][hh*2+0]);
                m = fmaxf(m, acc[mt][nt][hh*2+1]);
            }
            float s = 0.f;
            #pragma unroll
            for (int nt = 0; nt < 4; nt++) {
                s += __expf(acc[mt][nt][hh*2+0] - m);
                s += __expf(acc[mt][nt][hh*2+1] - m);
            }
            #pragma unroll
            for (int o = 1; o < 4; o <<= 1) {
                float m2 = __shfl_xor_sync(0xffffffffu, m, o);
                float s2 = __shfl_xor_sync(0xffffffffu, s, o);
                float mm = fmaxf(m, m2);
                s = s * __expf(m - mm) + s2 * __expf(m2 - mm);
                m = mm;
            }
            if (tig == 0)
                part[wn * 128 + wm * 64 + mt * 16 + hh * 8 + grp] = make_float2(m, s);
        }
    }
    __syncthreads();
    if (tid < 128) {
        float2 a = part[tid];
        float M = a.x, Ssum = a.y;
        #pragma unroll
        for (int t = 1; t < 4; t++) {
            float2 c = part[t * 128 + tid];
            float mm = fmaxf(M, c.x);
            Ssum = Ssum * __expf(M - mm) + c.y * __expf(c.x - mm);
            M = mm;
        }
        part_out[((size_t)bh * QLEN + i0 + tid) * 16 + (j0 >> 7)] = make_float2(M, Ssum);
    }
}

__global__ void statcombine(const float2* __restrict__ part, float2* __restrict__ stat) {
    int id = blockIdx.x * 256 + threadIdx.x;
    if (id >= BH * QLEN) return;
    int i = id & (QLEN - 1);
    int ntl = (i >> 7) + 9; if (ntl > 16) ntl = 16;
    float M = -1e30f, Ssum = 0.f;
    const float2* p = part + (size_t)id * 16;
    for (int t = 0; t < ntl; t++) {
        float2 q = p[t];
        float mm = fmaxf(M, q.x);
        Ssum = Ssum * __expf(M - mm) + q.y * __expf(q.x - mm);
        M = mm;
    }
    stat[id] = make_float2(M, 1.0f / Ssum);
}

__global__ void probout(const float* __restrict__ S, const float2* __restrict__ stat,
                        float* __restrict__ out) {
    __shared__ float t[128][33];
    __shared__ float m_s[32], inv_s[32];
    const int i = blockIdx.y, j0 = blockIdx.x * 128;
    const int tid = threadIdx.x;
    const int jmax = i + MEMLEN;
    float* obase = out + ((size_t)i * KLEN + j0) * 32;
    if (j0 > jmax) {
        float4 z = make_float4(0.f, 0.f, 0.f, 0.f);
        #pragma unroll
        for (int l = 0; l < 4; l++)
            ((float4*)obase)[l * 256 + tid] = z;
        return;
    }
    if (tid < 32) {
        float2 st = stat[tid * QLEN + i];
        m_s[tid] = st.x; inv_s[tid] = st.y;
    }
    __syncthreads();
    const int lb = tid >> 5, lj4 = tid & 31;
    #pragma unroll
    for (int r = 0; r < 4; r++) {
        int bh = r * 8 + lb;
        float4 v = *(const float4*)(S + ((size_t)bh * QLEN + i) * KLEN + j0 + lj4 * 4);
        float m = m_s[bh], iv = inv_s[bh];
        int j = j0 + lj4 * 4;
        t[lj4*4+0][bh] = (j     <= jmax) ? __expf(v.x - m) * iv : 0.f;
        t[lj4*4+1][bh] = (j + 1 <= jmax) ? __expf(v.y - m) * iv : 0.f;
        t[lj4*4+2][bh] = (j + 2 <= jmax) ? __expf(v.z - m) * iv : 0.f;
        t[lj4*4+3][bh] = (j + 3 <= jmax) ? __expf(v.w - m) * iv : 0.f;
    }
    __syncthreads();
    const int bh4 = (tid & 7) * 4;
    #pragma unroll
    for (int p = 0; p < 4; p++) {
        int jl = p * 32 + (tid >> 3);
        float4 w = make_float4(t[jl][bh4], t[jl][bh4+1], t[jl][bh4+2], t[jl][bh4+3]);
        *(float4*)(obase + (size_t)jl * 32 + bh4) = w;
    }
}

__global__ __launch_bounds__(128, 2) void attn_exp_gemm(
    const float* __restrict__ S, const float2* __restrict__ stat,
    const float* __restrict__ Vt, float* __restrict__ attn)
{
    const int bh = blockIdx.y, b = bh >> 3, h = bh & 7;
    const int i0 = blockIdx.x * 128;
    __shared__ __align__(16) float As[128][20];
    __shared__ __align__(16) float Bs[2][64][20];
    __shared__ float m_s[128], inv_s[128];
    const int tid = threadIdx.x;
    const int lane = tid & 31, warp = tid >> 5;
    const int wm = warp & 1, wn = warp >> 1;
    const int grp = lane >> 2, tig = lane & 3;
    {
        float2 st = stat[bh * QLEN + i0 + tid];
        m_s[tid] = st.x; inv_s[tid] = st.y;
    }
    __syncthreads();
    const float* Srow = S + (size_t)bh * QK + (size_t)i0 * KLEN;
    const float* Vb = Vt + (size_t)bh * DHEAD * KLEN;
    const int K1 = min(KLEN, i0 + 128 + MEMLEN);
    const int nk = K1 >> 4;

    float acc[4][4][4];
    #pragma unroll
    for (int mt = 0; mt < 4; mt++)
        #pragma unroll
        for (int nt = 0; nt < 4; nt++)
            #pragma unroll
            for (int q = 0; q < 4; q++) acc[mt][nt][q] = 0.f;

    float4 aReg[4];
    #pragma unroll
    for (int l = 0; l < 4; l++) {
        int idx = l * 128 + tid;
        int r = idx >> 2, c4 = (idx & 3) << 2;
        aReg[l] = *(const float4*)(Srow + (size_t)r * KLEN + c4);
    }
    #pragma unroll
    for (int l = 0; l < 2; l++) {
        int idx = l * 128 + tid;
        int r = idx >> 2, c4 = (idx & 3) << 2;
        cp16(&Bs[0][r][c4], Vb + (size_t)r * KLEN + c4);
    }
    cp_commit();

    const unsigned aBase = (unsigned)__cvta_generic_to_shared(&As[0][0]);
    const unsigned bBase = (unsigned)__cvta_generic_to_shared(&Bs[0][0][0]);
    const int rowsel = lane & 15;
    const int colsel = (lane >> 4) << 2;
    const unsigned aOff = aBase + (unsigned)(((wm * 64 + rowsel) * 20 + colsel) * 4);
    const unsigned bOff = bBase + (unsigned)(((wn * 32 + rowsel) * 20 + colsel) * 4);

    int cur = 0;
    for (int it = 0; it < nk; it++) {
        const int kt = it * 16;
        float4 aNext[4];
        if (it + 1 < nk) {
            int ktn = kt + 16;
            #pragma unroll
            for (int l = 0; l < 2; l++) {
                int idx = l * 128 + tid;
                int r = idx >> 2, c4 = (idx & 3) << 2;
                cp16(&Bs[cur ^ 1][r][c4], Vb + (size_t)r * KLEN + ktn + c4);
            }
            #pragma unroll
            for (int l = 0; l < 4; l++) {
                int idx = l * 128 + tid;
                int r = idx >> 2, c4 = (idx & 3) << 2;
                aNext[l] = *(const float4*)(Srow + (size_t)r * KLEN + ktn + c4);
            }
            cp_commit();
        }
        #pragma unroll
        for (int l = 0; l < 4; l++) {
            int idx = l * 128 + tid;
            int r = idx >> 2, c4 = (idx & 3) << 2;
            float mr = m_s[r];
            int jmax = i0 + r + MEMLEN;
            As[r][c4]     = (kt + c4 + 0 <= jmax) ? f2tf(__expf(aReg[l].x - mr)) : 0.f;
            As[r][c4 + 1] = (kt + c4 + 1 <= jmax) ? f2tf(__expf(aReg[l].y - mr)) : 0.f;
            As[r][c4 + 2] = (kt + c4 + 2 <= jmax) ? f2tf(__expf(aReg[l].z - mr)) : 0.f;
            As[r][c4 + 3] = (kt + c4 + 3 <= jmax) ? f2tf(__expf(aReg[l].w - mr)) : 0.f;
        }
        if (it + 1 < nk) cp_wait1(); else cp_wait0();
        __syncthreads();
        const unsigned bS = bOff + (unsigned)(cur * 64 * 20 * 4);
        #pragma unroll
        for (int ks = 0; ks < 16; ks += 8) {
            unsigned af[4][4], bf[4][2];
            #pragma unroll
            for (int mt = 0; mt < 4; mt++)
                ldsm_x4(af[mt][0], af[mt][1], af[mt][2], af[mt][3],
                        aOff + (mt * 16 * 20 + ks) * 4);
            #pragma unroll
            for (int p = 0; p < 2; p++) {
                unsigned r0, r1, r2, r3;
                ldsm_x4(r0, r1, r2, r3, bS + (p * 16 * 20 + ks) * 4);
                bf[2*p][0] = r0; bf[2*p+1][0] = r1;
                bf[2*p][1] = r2; bf[2*p+1][1] = r3;
            }
            #pragma unroll
            for (int mt = 0; mt < 4; mt++)
                #pragma unroll
                for (int nt = 0; nt < 4; nt++)
                    mma_tf32(acc[mt][nt], af[mt][0], af[mt][1], af[mt][2], af[mt][3],
                             bf[nt][0], bf[nt][1]);
        }
        __syncthreads();
        #pragma unroll
        for (int l = 0; l < 4; l++) aReg[l] = aNext[l];
        cur ^= 1;
    }
    #pragma unroll
    for (int mt = 0; mt < 4; mt++) {
        int r0 = wm * 64 + mt * 16 + grp;
        float iv0 = inv_s[r0], iv1 = inv_s[r0 + 8];
        #pragma unroll
        for (int nt = 0; nt < 4; nt++) {
            int c0 = wn * 32 + nt * 8 + tig * 2;
            float v0 = f2tf(acc[mt][nt][0] * iv0);
            float v1 = f2tf(acc[mt][nt][1] * iv0);
            float v2 = f2tf(acc[mt][nt][2] * iv1);
            float v3 = f2tf(acc[mt][nt][3] * iv1);
            size_t o0 = ((size_t)(i0 + r0) * BATCH + b) * DMODEL + h * DHEAD + c0;
            size_t o1 = ((size_t)(i0 + r0 + 8) * BATCH + b) * DMODEL + h * DHEAD + c0;
            *(float2*)(attn + o0) = make_float2(v0, v1);
            *(float2*)(attn + o1) = make_float2(v2, v3);
        }
    }
}

__global__ void prep_vt(const float* __restrict__ qkv, float* __restrict__ Vt) {
    __shared__ float t[32][33];
    int bh = blockIdx.z, b = bh >> 3, h = bh & 7;
    int j0 = blockIdx.x * 32, d0 = blockIdx.y * 32;
    int tc = threadIdx.x & 31, tr = threadIdx.x >> 5;
    #pragma unroll
    for (int rr = 0; rr < 32; rr += 8)
        t[tr + rr][tc] = qkv[(size_t)(j0 + tr + rr) * QSTRIDE + b * QKVW
                             + 2 * DMODEL + h * DHEAD + d0 + tc];
    __syncthreads();
    #pragma unroll
    for (int rr = 0; rr < 32; rr += 8)
        Vt[((size_t)bh * DHEAD + d0 + tr + rr) * KLEN + j0 + tc] = t[tc][tr + rr];
}

__global__ void add_ln(const float* __restrict__ x1, const float* __restrict__ x2,
                       const float* __restrict__ g, const float* __restrict__ bb,
                       float* __restrict__ out, float* __restrict__ out_r) {
    const int row = blockIdx.x;
    const int tid = threadIdx.x;
    __shared__ float red[256];
    __shared__ float red2[256];
    const float* a = x1 + (size_t)row * DMODEL;
    const float* c = x2 + (size_t)row * DMODEL;
    float v0 = a[tid] + c[tid];
    float v1 = a[tid + 256] + c[tid + 256];
    red[tid] = v0 + v1;
    red2[tid] = v0 * v0 + v1 * v1;
    __syncthreads();
    for (int o = 128; o > 0; o >>= 1) {
        if (tid < o) { red[tid] += red[tid + o]; red2[tid] += red2[tid + o]; }
        __syncthreads();
    }
    const float mu = red[0] * (1.0f / DMODEL);
    const float var = red2[0] * (1.0f / DMODEL) - mu * mu;
    const float rstd = rsqrtf(var + 1e-5f);
    float* o = out + (size_t)row * DMODEL;
    float r0 = (v0 - mu) * rstd * g[tid] + bb[tid];
    float r1 = (v1 - mu) * rstd * g[tid + 256] + bb[tid + 256];
    o[tid] = r0;
    o[tid + 256] = r1;
    if (out_r) {
        float* orr = out_r + (size_t)row * DMODEL;
        orr[tid] = f2tf(r0);
        orr[tid + 256] = f2tf(r1);
    }
}

extern "C" void kernel_launch(void* const* d_in, const int* in_sizes, int n_in,
                              void* d_out, int out_size) {
    const float* inputs = (const float*)d_in[0];
    const float* r      = (const float*)d_in[1];
    const float* u      = (const float*)d_in[2];
    const float* v      = (const float*)d_in[3];
    const float* mem    = (const float*)d_in[4];
    const float* Wqkv   = (const float*)d_in[6];
    const float* Wr     = (const float*)d_in[7];
    const float* Wo     = (const float*)d_in[8];
    const float* ln1_g  = (const float*)d_in[9];
    const float* ln1_b  = (const float*)d_in[10];
    const float* w1     = (const float*)d_in[11];
    const float* b1     = (const float*)d_in[12];
    const float* w2     = (const float*)d_in[13];
    const float* b2     = (const float*)d_in[14];
    const float* ln2_g  = (const float*)d_in[15];
    const float* ln2_b  = (const float*)d_in[16];

    static cudaStream_t s2 = nullptr;
    static cudaEvent_t eFork = nullptr, eJoin = nullptr;
    if (!s2) {
        cudaFuncSetAttribute(lin_gemm, cudaFuncAttributeMaxDynamicSharedMemorySize, SMEM_DYN);
        cudaFuncSetAttribute(score_bd, cudaFuncAttributeMaxDynamicSharedMemorySize, SMEM_DYN);
        cudaFuncSetAttribute(score_ac, cudaFuncAttributeMaxDynamicSharedMemorySize, SMEM_DYN);
        cudaStreamCreateWithFlags(&s2, cudaStreamNonBlocking);
        cudaEventCreateWithFlags(&eFork, cudaEventDisableTiming);
        cudaEventCreateWithFlags(&eJoin, cudaEventDisableTiming);
    }

    float *qkvp, *rkp, *vtp, *sp, *attnp, *aop, *yp, *yrp, *hp, *zp, *rnd;
    __half *quh, *qvh, *khp, *rkhp, *bdp;
    float2 *statp, *partp;
    cudaGetSymbolAddress((void**)&qkvp,  g_qkv);
    cudaGetSymbolAddress((void**)&rkp,   g_rk);
    cudaGetSymbolAddress((void**)&quh,   g_quh);
    cudaGetSymbolAddress((void**)&qvh,   g_qvh);
    cudaGetSymbolAddress((void**)&khp,   g_kh);
    cudaGetSymbolAddress((void**)&rkhp,  g_rkh);
    cudaGetSymbolAddress((void**)&vtp,   g_vt);
    cudaGetSymbolAddress((void**)&sp,    g_S);
    cudaGetSymbolAddress((void**)&bdp,   g_BDh);
    cudaGetSymbolAddress((void**)&statp, g_stat);
    cudaGetSymbolAddress((void**)&partp, g_part);
    cudaGetSymbolAddress((void**)&attnp, g_attn);
    cudaGetSymbolAddress((void**)&aop,   g_ao);
    cudaGetSymbolAddress((void**)&yp,    g_y);
    cudaGetSymbolAddress((void**)&yrp,   g_yr);
    cudaGetSymbolAddress((void**)&hp,    g_h);
    cudaGetSymbolAddress((void**)&zp,    g_z);
    cudaGetSymbolAddress((void**)&rnd,   g_rnd);

    const float* memr  = rnd;
    const float* rr    = rnd + OFF_R;
    const float* wqkvr = rnd + OFF_WQKV;
    const float* wrr   = rnd + OFF_WR;
    const float* wor   = rnd + OFF_WO;
    const float* w1r   = rnd + OFF_W1;
    const float* w2r   = rnd + OFF_W2;

    // 1: RNA round  2: qkv GEMM (+Quh/Qvh/Kh)  3: rk GEMM (+rkh)  4: score_bd (profiled)
    round_all<<<(2162688 + 255) / 256, 256>>>(mem, inputs, r, Wqkv, Wr, Wo, w1, w2,
                                              (float4*)rnd);
    lin_gemm<<<dim3(QKVW / 128, KROWS / 128), 256, SMEM_DYN>>>(
        memr, wqkvr, nullptr, qkvp, u, v, quh, qvh, khp, DMODEL, QKVW, 4 | 32);
    lin_gemm<<<dim3(DMODEL / 128, KLEN / 128), 256, SMEM_DYN>>>(
        rr, wrr, nullptr, rkp, nullptr, nullptr, rkhp, nullptr, nullptr,
        DMODEL, DMODEL, 4 | 64);
    score_bd<<<dim3(KLEN / 128, QLEN / 128, BH), 256, SMEM_DYN>>>(qvh, rkhp, bdp);
    // 5-7
    score_ac<<<dim3(KLEN / 128, QLEN / 128, BH), 256, SMEM_DYN>>>(quh, khp, bdp, sp, partp);
    prep_vt<<<dim3(KLEN / 32, DHEAD / 32, BH), 256>>>(qkvp, vtp);
    statcombine<<<(BH * QLEN + 255) / 256, 256>>>(partp, statp);
    // fork prob output onto side stream
    cudaEventRecord(eFork, 0);
    cudaStreamWaitEvent(s2, eFork, 0);
    float* prob_out = (float*)d_out + QLEN * BATCH * DMODEL;
    probout<<<dim3(KLEN / 128, QLEN), 256, 0, s2>>>(sp, statp, prob_out);
    cudaEventRecord(eJoin, s2);
    // tail
    attn_exp_gemm<<<dim3(QLEN / 128, BH), 128>>>(sp, statp, vtp, attnp);
    lin_gemm<<<dim3(DMODEL / 128, QROWS / 128), 256, SMEM_DYN>>>(
        attnp, wor, nullptr, aop, nullptr, nullptr, nullptr, nullptr, nullptr,
        DMODEL, DMODEL, 0);
    add_ln<<<QROWS, 256>>>(inputs, aop, ln1_g, ln1_b, yp, yrp);
    lin_gemm<<<dim3(DMLP / 128, QROWS / 128), 256, SMEM_DYN>>>(
        yrp, w1r, b1, hp, nullptr, nullptr, nullptr, nullptr, nullptr,
        DMODEL, DMLP, 7);
    lin_gemm<<<dim3(DMODEL / 128, QROWS / 128), 256, SMEM_DYN>>>(
        hp, w2r, b2, zp, nullptr, nullptr, nullptr, nullptr, nullptr,
        DMLP, DMODEL, 1);
    add_ln<<<QROWS, 256>>>(yp, zp, ln2_g, ln2_b, (float*)d_out, nullptr);
    cudaStreamWaitEvent(0, eJoin, 0);
}

// round 14
// speedup vs baseline: 1.4849x; 1.3452x over previous
#include <cuda_runtime.h>
#include <cuda_fp16.h>
#include <math.h>

#define QLEN 1024
#define BATCH 4
#define DMODEL 512
#define HEADS 8
#define DHEAD 64
#define MEMLEN 1024
#define KLEN 2048
#define DMLP 2048
#define BH 32
#define QROWS 4096
#define KROWS 8192
#define QKVW 1536
#define QSTRIDE 6144
#define QK ((size_t)QLEN * KLEN)
#define SMEM_H 36864

__device__ __half g_qkvh[KROWS * QKVW];
__device__ __half g_quh[BH * QLEN * DHEAD];
__device__ __half g_qvh[BH * QLEN * DHEAD];
__device__ __half g_kh[BH * KLEN * DHEAD];
__device__ __half g_rkh[HEADS * KLEN * DHEAD];
__device__ __half g_vth[BH * DHEAD * KLEN];
__device__ __half g_Sh[(size_t)BH * QLEN * KLEN];
__device__ __half g_BDh[(size_t)BH * QLEN * KLEN];
__device__ float2 g_part[(size_t)BH * QLEN * 16];
__device__ float2 g_stat[BH * QLEN];
__device__ __half g_ath[QROWS * DMODEL];
__device__ float g_ao[QROWS * DMODEL];
__device__ float g_y[QROWS * DMODEL];
__device__ __half g_yh[QROWS * DMODEL];
__device__ __half g_hh[QROWS * DMLP];
__device__ float g_z[QROWS * DMODEL];
__device__ __half g_xh[8650752];

#define OFF_R    4194304
#define OFF_WQKV 5242880
#define OFF_WR   6029312
#define OFF_WO   6291456
#define OFF_W1   6553600
#define OFF_W2   7602176

__device__ __forceinline__ void cpa(unsigned dst, const void* src) {
    asm volatile("cp.async.ca.shared.global [%0], [%1], 16;" :: "r"(dst), "l"(src));
}
__device__ __forceinline__ void cp_commit() { asm volatile("cp.async.commit_group;"); }
__device__ __forceinline__ void cp_wait1()  { asm volatile("cp.async.wait_group 1;"); }
__device__ __forceinline__ void cp_wait0()  { asm volatile("cp.async.wait_group 0;"); }

__device__ __forceinline__ void mma_f16(float* acc, unsigned a0, unsigned a1,
                                        unsigned a2, unsigned a3,
                                        unsigned b0, unsigned b1) {
    asm volatile(
        "mma.sync.aligned.m16n8k16.row.col.f32.f16.f16.f32 "
        "{%0,%1,%2,%3}, {%4,%5,%6,%7}, {%8,%9}, {%0,%1,%2,%3};"
        : "+f"(acc[0]), "+f"(acc[1]), "+f"(acc[2]), "+f"(acc[3])
        : "r"(a0), "r"(a1), "r"(a2), "r"(a3), "r"(b0), "r"(b1));
}
__device__ __forceinline__ void ldsm_x4(unsigned& r0, unsigned& r1, unsigned& r2,
                                        unsigned& r3, unsigned addr) {
    asm volatile("ldmatrix.sync.aligned.m8n8.x4.shared.b16 {%0,%1,%2,%3}, [%4];"
                 : "=r"(r0), "=r"(r1), "=r"(r2), "=r"(r3) : "r"(addr));
}

// ---------------- fp32 -> fp16 conversion of all operands --------------------
__global__ void half_all(const float* __restrict__ s0, const float* __restrict__ s1,
                         const float* __restrict__ s2, const float* __restrict__ s3,
                         const float* __restrict__ s4, const float* __restrict__ s5,
                         const float* __restrict__ s6, const float* __restrict__ s7,
                         __half* __restrict__ dst) {
    int idx = blockIdx.x * 256 + threadIdx.x;
    if (idx >= 2162688) return;
    const float4* src; int base;
    if      (idx < 524288)  { src = (const float4*)s0; base = 0; }
    else if (idx < 1048576) { src = (const float4*)s1; base = 524288; }
    else if (idx < 1310720) { src = (const float4*)s2; base = 1048576; }
    else if (idx < 1507328) { src = (const float4*)s3; base = 1310720; }
    else if (idx < 1572864) { src = (const float4*)s4; base = 1507328; }
    else if (idx < 1638400) { src = (const float4*)s5; base = 1572864; }
    else if (idx < 1900544) { src = (const float4*)s6; base = 1638400; }
    else                    { src = (const float4*)s7; base = 1900544; }
    float4 v = src[idx - base];
    __half2 h01 = __floats2half2_rn(v.x, v.y);
    __half2 h23 = __floats2half2_rn(v.z, v.w);
    uint2 o;
    o.x = *(unsigned*)&h01;
    o.y = *(unsigned*)&h23;
    *(uint2*)(dst + (size_t)idx * 4) = o;
}

// ---- fp16 NT GEMM core: 256 threads, 8 warps (2Mx4N), 64x32 tiles, k16 ------
__device__ __forceinline__ void gemm_core256h(
    const __half* __restrict__ A, int lda,
    const __half* __restrict__ B, int ldb,
    int K, float acc[4][4][4], char* smc)
{
    const int tid = threadIdx.x;
    const int lane = tid & 31, warp = tid >> 5;
    const int wm = warp & 1, wn = warp >> 1;
    #pragma unroll
    for (int mt = 0; mt < 4; mt++)
        #pragma unroll
        for (int nt = 0; nt < 4; nt++)
            #pragma unroll
            for (int q = 0; q < 4; q++) acc[mt][nt][q] = 0.0f;

    const unsigned sbase = (unsigned)__cvta_generic_to_shared(smc);
    const int nk = K >> 4;
    const int r = tid >> 1, qh = tid & 1;
    auto load = [&](int it, int s) {
        int kt = it * 16;
        unsigned as = sbase + s * 6144;
        unsigned bs = sbase + 18432 + s * 6144;
        cpa(as + r * 48 + qh * 16, A + (size_t)r * lda + kt + qh * 8);
        cpa(bs + r * 48 + qh * 16, B + (size_t)r * ldb + kt + qh * 8);
        cp_commit();
    };
    load(0, 0);
    if (nk > 1) load(1, 1);

    const unsigned aOff = (unsigned)((wm * 64 + (lane & 15)) * 48 + (lane >> 4) * 16);
    const unsigned bOff = (unsigned)(18432 + (wn * 32 + (lane & 15)) * 48 + (lane >> 4) * 16);

    for (int it = 0; it < nk; it++) {
        if (it + 1 < nk) cp_wait1(); else cp_wait0();
        __syncthreads();
        if (it + 2 < nk) load(it + 2, (it + 2) % 3);
        const unsigned st = (unsigned)((it % 3) * 6144);
        const unsigned aS = sbase + st + aOff;
        const unsigned bS = sbase + st + bOff;
        unsigned af[4][4], bf[4][2];
        #pragma unroll
        for (int mt = 0; mt < 4; mt++)
            ldsm_x4(af[mt][0], af[mt][1], af[mt][2], af[mt][3], aS + mt * 16 * 48);
        #pragma unroll
        for (int p = 0; p < 2; p++) {
            unsigned r0, r1, r2, r3;
            ldsm_x4(r0, r1, r2, r3, bS + p * 16 * 48);
            bf[2*p][0] = r0; bf[2*p+1][0] = r1;
            bf[2*p][1] = r2; bf[2*p+1][1] = r3;
        }
        #pragma unroll
        for (int mt = 0; mt < 4; mt++)
            #pragma unroll
            for (int nt = 0; nt < 4; nt++)
                mma_f16(acc[mt][nt], af[mt][0], af[mt][1], af[mt][2], af[mt][3],
                        bf[nt][0], bf[nt][1]);
    }
}

// fp16 linear GEMM; act: 1 bias, 2 relu, 8 fp16 Ch[m][N], 16 skip fp32 C,
//                   32 qkv-aux (Quh/Qvh/Kh), 64 rkh pack into Ch
__global__ __launch_bounds__(256, 2) void lin_gemm_h(
    const __half* __restrict__ A, const __half* __restrict__ W,
    const float* __restrict__ bias, float* __restrict__ C,
    __half* __restrict__ Ch,
    const float* __restrict__ uu, const float* __restrict__ vv,
    __half* __restrict__ Quh, __half* __restrict__ Qvh, __half* __restrict__ Kh,
    int K, int N, int act)
{
    extern __shared__ char smc[];
    int m0 = blockIdx.y * 128, n0 = blockIdx.x * 128;
    float acc[4][4][4];
    gemm_core256h(A + (size_t)m0 * K, K, W + (size_t)n0 * K, K, K, acc, smc);
    const int lane = threadIdx.x & 31, warp = threadIdx.x >> 5;
    const int wm = warp & 1, wn = warp >> 1;
    const int grp = lane >> 2, tig = lane & 3;
    const float* bp = bias ? bias + n0 : nullptr;
    #pragma unroll
    for (int mt = 0; mt < 4; mt++) {
        int r0l = wm * 64 + mt * 16 + grp;
        #pragma unroll
        for (int nt = 0; nt < 4; nt++) {
            int c0 = wn * 32 + nt * 8 + tig * 2;
            float v0 = acc[mt][nt][0], v1 = acc[mt][nt][1];
            float v2 = acc[mt][nt][2], v3 = acc[mt][nt][3];
            if (act & 1) { float b0 = bp[c0], b1 = bp[c0 + 1];
                           v0 += b0; v1 += b1; v2 += b0; v3 += b1; }
            if (act & 2) { v0 = fmaxf(v0, 0.f); v1 = fmaxf(v1, 0.f);
                           v2 = fmaxf(v2, 0.f); v3 = fmaxf(v3, 0.f); }
            int n = n0 + c0;
            if (act & 32) {   // Quh/Qvh from q-cols, Kh from k-cols
                #pragma unroll
                for (int hh = 0; hh < 2; hh++) {
                    int rg = m0 + r0l + hh * 8;
                    float q0 = (hh == 0) ? v0 : v2;
                    float q1 = (hh == 0) ? v1 : v3;
                    if (n < DMODEL) {
                        if (rg >= 4096) {
                            int j = (rg >> 2) - MEMLEN, b = rg & 3;
                            int h = n >> 6, d = n & 63;
                            size_t o = ((size_t)(b * HEADS + h) * QLEN + j) * DHEAD + d;
                            *(__half2*)(Quh + o) = __floats2half2_rn(q0 + uu[n], q1 + uu[n + 1]);
                            *(__half2*)(Qvh + o) = __floats2half2_rn(q0 + vv[n], q1 + vv[n + 1]);
                        }
                    } else if (n < 2 * DMODEL) {
                        int j = rg >> 2, b = rg & 3;
                        int nn = n - DMODEL, h = nn >> 6, d = nn & 63;
                        size_t o = ((size_t)(b * HEADS + h) * KLEN + j) * DHEAD + d;
                        *(__half2*)(Kh + o) = __floats2half2_rn(q0, q1);
                    }
                }
            }
            if (act & 64) {   // rkh packed [h][p][64]
                int h = n >> 6, d = n & 63;
                #pragma unroll
                for (int hh = 0; hh < 2; hh++) {
                    int p = m0 + r0l + hh * 8;
                    size_t o = ((size_t)h * KLEN + p) * DHEAD + d;
                    *(__half2*)(Ch + o) = __floats2half2_rn(hh == 0 ? v0 : v2,
                                                            hh == 0 ? v1 : v3);
                }
            }
            if (act & 8) {
                *(__half2*)(Ch + (size_t)r0l * N + m0 * (size_t)N + n) =
                    __floats2half2_rn(v0, v1);
                *(__half2*)(Ch + (size_t)(r0l + 8) * N + m0 * (size_t)N + n) =
                    __floats2half2_rn(v2, v3);
            }
            if (!(act & 16)) {
                float* Cp = C + (size_t)m0 * N + n0;
                *(float2*)(Cp + (size_t)r0l * N + c0) = make_float2(v0, v1);
                *(float2*)(Cp + (size_t)(r0l + 8) * N + c0) = make_float2(v2, v3);
            }
        }
    }
}

// BD scores (fp16)
__global__ __launch_bounds__(256, 2) void score_bd(
    const __half* __restrict__ Qv, const __half* __restrict__ rkh,
    __half* __restrict__ BD)
{
    extern __shared__ char smc[];
    int bh = blockIdx.z, h = bh & 7;
    int i0 = blockIdx.y * 128, p0 = blockIdx.x * 128;
    if (p0 + i0 < 896) return;
    float acc[4][4][4];
    gemm_core256h(Qv + ((size_t)bh * QLEN + i0) * DHEAD, DHEAD,
                  rkh + ((size_t)h * KLEN + p0) * DHEAD, DHEAD, DHEAD, acc, smc);
    const int lane = threadIdx.x & 31, warp = threadIdx.x >> 5;
    const int wm = warp & 1, wn = warp >> 1;
    const int grp = lane >> 2, tig = lane & 3;
    __half* Cp = BD + (size_t)bh * QK + (size_t)i0 * KLEN + p0;
    #pragma unroll
    for (int mt = 0; mt < 4; mt++) {
        int r0 = wm * 64 + mt * 16 + grp;
        #pragma unroll
        for (int nt = 0; nt < 4; nt++) {
            int c0 = wn * 32 + nt * 8 + tig * 2;
            *(__half2*)(Cp + (size_t)r0 * KLEN + c0) =
                __floats2half2_rn(acc[mt][nt][0], acc[mt][nt][1]);
            *(__half2*)(Cp + (size_t)(r0 + 8) * KLEN + c0) =
                __floats2half2_rn(acc[mt][nt][2], acc[mt][nt][3]);
        }
    }
}

// AC + shift + scale + partials; S stored fp16
__global__ __launch_bounds__(256, 2) void score_ac(
    const __half* __restrict__ Qu, const __half* __restrict__ Kh,
    const __half* __restrict__ BD, __half* __restrict__ S,
    float2* __restrict__ part_out)
{
    extern __shared__ char smc[];
    int bh = blockIdx.z;
    int i0 = blockIdx.y * 128, j0 = blockIdx.x * 128;
    if (j0 - i0 > 1024) return;
    float acc[4][4][4];
    gemm_core256h(Qu + ((size_t)bh * QLEN + i0) * DHEAD, DHEAD,
                  Kh + ((size_t)bh * KLEN + j0) * DHEAD, DHEAD, DHEAD, acc, smc);
    const int tid = threadIdx.x;
    const int lane = tid & 31, warp = tid >> 5;
    const int wm = warp & 1, wn = warp >> 1;
    const int grp = lane >> 2, tig = lane & 3;
    const __half* bdb = BD + (size_t)bh * QK;
    __half* Sp = S + (size_t)bh * QK;
    #pragma unroll
    for (int mt = 0; mt < 4; mt++) {
        #pragma unroll
        for (int hh = 0; hh < 2; hh++) {
            int gi = i0 + wm * 64 + mt * 16 + grp + hh * 8;
            const __half* bdr = bdb + (size_t)gi * KLEN;
            int jmax = gi + MEMLEN;
            #pragma unroll
            for (int nt = 0; nt < 4; nt++) {
                int gj = j0 + wn * 32 + nt * 8 + tig * 2;
                int p0 = min(gj - gi + (QLEN - 1), KLEN - 1);
                int p1 = min(p0 + 1, KLEN - 1);
                float v0 = (gj <= jmax)
                    ? (acc[mt][nt][hh*2+0] + __half2float(bdr[p0])) * 0.125f : -30000.0f;
                float v1 = (gj + 1 <= jmax)
                    ? (acc[mt][nt][hh*2+1] + __half2float(bdr[p1])) * 0.125f : -30000.0f;
                acc[mt][nt][hh*2+0] = v0;
                acc[mt][nt][hh*2+1] = v1;
                *(__half2*)(Sp + (size_t)gi * KLEN + gj) = __floats2half2_rn(v0, v1);
            }
        }
    }
    __syncthreads();
    float2* part = (float2*)smc;
    #pragma unroll
    for (int mt = 0; mt < 4; mt++) {
        #pragma unroll
        for (int hh = 0; hh < 2; hh++) {
            float m = -1e30f;
            #pragma unroll
            for (int nt = 0; nt < 4; nt++) {
                m = fmaxf(m, acc[mt][nt][hh*2+0]);
                m = fmaxf(m, acc[mt][nt][hh*2+1]);
            }
            float s = 0.f;
            #pragma unroll
            for (int nt = 0; nt < 4; nt++) {
                s += __expf(acc[mt][nt][hh*2+0] - m);
                s += __expf(acc[mt][nt][hh*2+1] - m);
            }
            #pragma unroll
            for (int o = 1; o < 4; o <<= 1) {
                float m2 = __shfl_xor_sync(0xffffffffu, m, o);
                float s2 = __shfl_xor_sync(0xffffffffu, s, o);
                float mm = fmaxf(m, m2);
                s = s * __expf(m - mm) + s2 * __expf(m2 - mm);
                m = mm;
            }
            if (tig == 0)
                part[wn * 128 + wm * 64 + mt * 16 + hh * 8 + grp] = make_float2(m, s);
        }
    }
    __syncthreads();
    if (tid < 128) {
        float2 a = part[tid];
        float M = a.x, Ssum = a.y;
        #pragma unroll
        for (int t = 1; t < 4; t++) {
            float2 c = part[t * 128 + tid];
            float mm = fmaxf(M, c.x);
            Ssum = Ssum * __expf(M - mm) + c.y * __expf(c.x - mm);
            M = mm;
        }
        part_out[((size_t)bh * QLEN + i0 + tid) * 16 + (j0 >> 7)] = make_float2(M, Ssum);
    }
}

__global__ void statcombine(const float2* __restrict__ part, float2* __restrict__ stat) {
    int id = blockIdx.x * 256 + threadIdx.x;
    if (id >= BH * QLEN) return;
    int i = id & (QLEN - 1);
    int ntl = (i >> 7) + 9; if (ntl > 16) ntl = 16;
    float M = -1e30f, Ssum = 0.f;
    const float2* p = part + (size_t)id * 16;
    for (int t = 0; t < ntl; t++) {
        float2 q = p[t];
        float mm = fmaxf(M, q.x);
        Ssum = Ssum * __expf(M - mm) + q.y * __expf(q.x - mm);
        M = mm;
    }
    stat[id] = make_float2(M, 1.0f / Ssum);
}

// prob output (reads fp16 S)
__global__ void probout(const __half* __restrict__ S, const float2* __restrict__ stat,
                        float* __restrict__ out) {
    __shared__ float t[128][33];
    __shared__ float m_s[32], inv_s[32];
    const int i = blockIdx.y, j0 = blockIdx.x * 128;
    const int tid = threadIdx.x;
    const int jmax = i + MEMLEN;
    float* obase = out + ((size_t)i * KLEN + j0) * 32;
    if (j0 > jmax) {
        float4 z = make_float4(0.f, 0.f, 0.f, 0.f);
        #pragma unroll
        for (int l = 0; l < 4; l++)
            ((float4*)obase)[l * 256 + tid] = z;
        return;
    }
    if (tid < 32) {
        float2 st = stat[tid * QLEN + i];
        m_s[tid] = st.x; inv_s[tid] = st.y;
    }
    __syncthreads();
    const int lb = tid >> 5, lj4 = tid & 31;
    #pragma unroll
    for (int r = 0; r < 4; r++) {
        int bh = r * 8 + lb;
        uint2 raw = *(const uint2*)(S + ((size_t)bh * QLEN + i) * KLEN + j0 + lj4 * 4);
        float2 f0 = __half22float2(*(__half2*)&raw.x);
        float2 f1 = __half22float2(*(__half2*)&raw.y);
        float m = m_s[bh], iv = inv_s[bh];
        int j = j0 + lj4 * 4;
        t[lj4*4+0][bh] = (j     <= jmax) ? __expf(f0.x - m) * iv : 0.f;
        t[lj4*4+1][bh] = (j + 1 <= jmax) ? __expf(f0.y - m) * iv : 0.f;
        t[lj4*4+2][bh] = (j + 2 <= jmax) ? __expf(f1.x - m) * iv : 0.f;
        t[lj4*4+3][bh] = (j + 3 <= jmax) ? __expf(f1.y - m) * iv : 0.f;
    }
    __syncthreads();
    const int bh4 = (tid & 7) * 4;
    #pragma unroll
    for (int p = 0; p < 4; p++) {
        int jl = p * 32 + (tid >> 3);
        float4 w = make_float4(t[jl][bh4], t[jl][bh4+1], t[jl][bh4+2], t[jl][bh4+3]);
        *(float4*)(obase + (size_t)jl * 32 + bh4) = w;
    }
}

// attention: fp16 S -> exp -> fp16 smem A, Vt fp16, fp16 mma; out fp16 attn
__global__ __launch_bounds__(128, 2) void attn_exp_gemm(
    const __half* __restrict__ S, const float2* __restrict__ stat,
    const __half* __restrict__ Vt, __half* __restrict__ ath)
{
    const int bh = blockIdx.y, b = bh >> 3, h = bh & 7;
    const int i0 = blockIdx.x * 128;
    __shared__ __align__(16) __half As[128 * 24];
    __shared__ __align__(16) __half Bs[2][64 * 24];
    __shared__ float m_s[128], inv_s[128];
    const int tid = threadIdx.x;
    const int lane = tid & 31, warp = tid >> 5;
    const int wm = warp & 1, wn = warp >> 1;
    const int grp = lane >> 2, tig = lane & 3;
    {
        float2 st = stat[bh * QLEN + i0 + tid];
        m_s[tid] = st.x; inv_s[tid] = st.y;
    }
    __syncthreads();
    const __half* Srow = S + (size_t)bh * QK + (size_t)i0 * KLEN;
    const __half* Vb = Vt + (size_t)bh * DHEAD * KLEN;
    const int K1 = min(KLEN, i0 + 128 + MEMLEN);
    const int nk = K1 >> 4;

    float acc[4][4][4];
    #pragma unroll
    for (int mt = 0; mt < 4; mt++)
        #pragma unroll
        for (int nt = 0; nt < 4; nt++)
            #pragma unroll
            for (int q = 0; q < 4; q++) acc[mt][nt][q] = 0.f;

    const unsigned aBase = (unsigned)__cvta_generic_to_shared(As);
    const unsigned bBase = (unsigned)__cvta_generic_to_shared(&Bs[0][0]);
    const int rowsel = lane & 15, chsel = lane >> 4;
    const unsigned aOff = aBase + (unsigned)((wm * 64 + rowsel) * 48 + chsel * 16);
    const unsigned bOff = bBase + (unsigned)((wn * 32 + rowsel) * 48 + chsel * 16);

    // prefetch chunk 0
    uint4 aR[2];
    aR[0] = *(const uint4*)(Srow + (size_t)tid * KLEN);
    aR[1] = *(const uint4*)(Srow + (size_t)tid * KLEN + 8);
    {
        int rb = tid >> 1, ch = tid & 1;
        cpa(bBase + rb * 48 + ch * 16, Vb + (size_t)rb * KLEN + ch * 8);
        cp_commit();
    }
    const float mr = m_s[tid];
    const int jmaxr = i0 + tid + MEMLEN;

    int cur = 0;
    for (int it = 0; it < nk; it++) {
        const int kt = it * 16;
        uint4 aN[2];
        if (it + 1 < nk) {
            int ktn = kt + 16;
            int rb = tid >> 1, ch = tid & 1;
            cpa(bBase + (cur ^ 1) * 3072 + rb * 48 + ch * 16,
                Vb + (size_t)rb * KLEN + ktn + ch * 8);
            aN[0] = *(const uint4*)(Srow + (size_t)tid * KLEN + ktn);
            aN[1] = *(const uint4*)(Srow + (size_t)tid * KLEN + ktn + 8);
            cp_commit();
        }
        // exp -> fp16 As (row = tid)
        {
            const __half* hp = (const __half*)aR;
            __half outh[16];
            #pragma unroll
            for (int c = 0; c < 16; c++) {
                float e = (kt + c <= jmaxr) ? __expf(__half2float(hp[c]) - mr) : 0.f;
                outh[c] = __float2half_rn(e);
            }
            *(uint4*)(As + tid * 24)     = *(uint4*)outh;
            *(uint4*)(As + tid * 24 + 8) = *(uint4*)(outh + 8);
        }
        if (it + 1 < nk) cp_wait1(); else cp_wait0();
        __syncthreads();
        const unsigned bS = bOff + (unsigned)(cur * 3072);
        unsigned af[4][4], bf[4][2];
        #pragma unroll
        for (int mt = 0; mt < 4; mt++)
            ldsm_x4(af[mt][0], af[mt][1], af[mt][2], af[mt][3], aOff + mt * 16 * 48);
        #pragma unroll
        for (int p = 0; p < 2; p++) {
            unsigned r0, r1, r2, r3;
            ldsm_x4(r0, r1, r2, r3, bS + p * 16 * 48);
            bf[2*p][0] = r0; bf[2*p+1][0] = r1;
            bf[2*p][1] = r2; bf[2*p+1][1] = r3;
        }
        #pragma unroll
        for (int mt = 0; mt < 4; mt++)
            #pragma unroll
            for (int nt = 0; nt < 4; nt++)
                mma_f16(acc[mt][nt], af[mt][0], af[mt][1], af[mt][2], af[mt][3],
                        bf[nt][0], bf[nt][1]);
        __syncthreads();
        aR[0] = aN[0]; aR[1] = aN[1];
        cur ^= 1;
    }
    #pragma unroll
    for (int mt = 0; mt < 4; mt++) {
        int r0 = wm * 64 + mt * 16 + grp;
        float iv0 = inv_s[r0], iv1 = inv_s[r0 + 8];
        #pragma unroll
        for (int nt = 0; nt < 4; nt++) {
            int c0 = wn * 32 + nt * 8 + tig * 2;
            size_t o0 = ((size_t)(i0 + r0) * BATCH + b) * DMODEL + h * DHEAD + c0;
            size_t o1 = ((size_t)(i0 + r0 + 8) * BATCH + b) * DMODEL + h * DHEAD + c0;
            *(__half2*)(ath + o0) =
                __floats2half2_rn(acc[mt][nt][0] * iv0, acc[mt][nt][1] * iv0);
            *(__half2*)(ath + o1) =
                __floats2half2_rn(acc[mt][nt][2] * iv1, acc[mt][nt][3] * iv1);
        }
    }
}

__global__ void prep_vt(const __half* __restrict__ qkvh, __half* __restrict__ Vt) {
    __shared__ __half t[32][34];
    int bh = blockIdx.z, b = bh >> 3, h = bh & 7;
    int j0 = blockIdx.x * 32, d0 = blockIdx.y * 32;
    int tc = threadIdx.x & 31, tr = threadIdx.x >> 5;
    #pragma unroll
    for (int rr = 0; rr < 32; rr += 8)
        t[tr + rr][tc] = qkvh[(size_t)(j0 + tr + rr) * QSTRIDE + b * QKVW
                              + 2 * DMODEL + h * DHEAD + d0 + tc];
    __syncthreads();
    #pragma unroll
    for (int rr = 0; rr < 32; rr += 8)
        Vt[((size_t)bh * DHEAD + d0 + tr + rr) * KLEN + j0 + tc] = t[tc][tr + rr];
}

__global__ void add_ln(const float* __restrict__ x1, const float* __restrict__ x2,
                       const float* __restrict__ g, const float* __restrict__ bb,
                       float* __restrict__ out, __half* __restrict__ outh) {
    const int row = blockIdx.x;
    const int tid = threadIdx.x;
    __shared__ float red[256];
    __shared__ float red2[256];
    const float* a = x1 + (size_t)row * DMODEL;
    const float* c = x2 + (size_t)row * DMODEL;
    float v0 = a[tid] + c[tid];
    float v1 = a[tid + 256] + c[tid + 256];
    red[tid] = v0 + v1;
    red2[tid] = v0 * v0 + v1 * v1;
    __syncthreads();
    for (int o = 128; o > 0; o >>= 1) {
        if (tid < o) { red[tid] += red[tid + o]; red2[tid] += red2[tid + o]; }
        __syncthreads();
    }
    const float mu = red[0] * (1.0f / DMODEL);
    const float var = red2[0] * (1.0f / DMODEL) - mu * mu;
    const float rstd = rsqrtf(var + 1e-5f);
    float* o = out + (size_t)row * DMODEL;
    float r0 = (v0 - mu) * rstd * g[tid] + bb[tid];
    float r1 = (v1 - mu) * rstd * g[tid + 256] + bb[tid + 256];
    o[tid] = r0;
    o[tid + 256] = r1;
    if (outh) {
        outh[(size_t)row * DMODEL + tid] = __float2half_rn(r0);
        outh[(size_t)row * DMODEL + tid + 256] = __float2half_rn(r1);
    }
}

extern "C" void kernel_launch(void* const* d_in, const int* in_sizes, int n_in,
                              void* d_out, int out_size) {
    const float* inputs = (const float*)d_in[0];
    const float* r      = (const float*)d_in[1];
    const float* u      = (const float*)d_in[2];
    const float* v      = (const float*)d_in[3];
    const float* mem    = (const float*)d_in[4];
    const float* Wqkv   = (const float*)d_in[6];
    const float* Wr     = (const float*)d_in[7];
    const float* Wo     = (const float*)d_in[8];
    const float* ln1_g  = (const float*)d_in[9];
    const float* ln1_b  = (const float*)d_in[10];
    const float* w1     = (const float*)d_in[11];
    const float* b1     = (const float*)d_in[12];
    const float* w2     = (const float*)d_in[13];
    const float* b2     = (const float*)d_in[14];
    const float* ln2_g  = (const float*)d_in[15];
    const float* ln2_b  = (const float*)d_in[16];

    static cudaStream_t s2 = nullptr;
    static cudaEvent_t eFork = nullptr, eJoin = nullptr;
    if (!s2) {
        cudaFuncSetAttribute(lin_gemm_h, cudaFuncAttributeMaxDynamicSharedMemorySize, SMEM_H);
        cudaFuncSetAttribute(score_bd, cudaFuncAttributeMaxDynamicSharedMemorySize, SMEM_H);
        cudaFuncSetAttribute(score_ac, cudaFuncAttributeMaxDynamicSharedMemorySize, SMEM_H);
        cudaStreamCreateWithFlags(&s2, cudaStreamNonBlocking);
        cudaEventCreateWithFlags(&eFork, cudaEventDisableTiming);
        cudaEventCreateWithFlags(&eJoin, cudaEventDisableTiming);
    }

    float *aop, *yp, *zp;
    __half *qkvh, *quh, *qvh, *khp, *rkhp, *vth, *shp, *bdp, *athp, *yh, *hh, *xh;
    float2 *statp, *partp;
    cudaGetSymbolAddress((void**)&qkvh,  g_qkvh);
    cudaGetSymbolAddress((void**)&quh,   g_quh);
    cudaGetSymbolAddress((void**)&qvh,   g_qvh);
    cudaGetSymbolAddress((void**)&khp,   g_kh);
    cudaGetSymbolAddress((void**)&rkhp,  g_rkh);
    cudaGetSymbolAddress((void**)&vth,   g_vth);
    cudaGetSymbolAddress((void**)&shp,   g_Sh);
    cudaGetSymbolAddress((void**)&bdp,   g_BDh);
    cudaGetSymbolAddress((void**)&statp, g_stat);
    cudaGetSymbolAddress((void**)&partp, g_part);
    cudaGetSymbolAddress((void**)&athp,  g_ath);
    cudaGetSymbolAddress((void**)&aop,   g_ao);
    cudaGetSymbolAddress((void**)&yp,    g_y);
    cudaGetSymbolAddress((void**)&yh,    g_yh);
    cudaGetSymbolAddress((void**)&hh,    g_hh);
    cudaGetSymbolAddress((void**)&zp,    g_z);
    cudaGetSymbolAddress((void**)&xh,    g_xh);

    const __half* memh  = xh;
    const __half* rh    = xh + OFF_R;
    const __half* wqkvh = xh + OFF_WQKV;
    const __half* wrh   = xh + OFF_WR;
    const __half* woh   = xh + OFF_WO;
    const __half* w1h   = xh + OFF_W1;
    const __half* w2h   = xh + OFF_W2;

    // 1: fp16 conversion  2: qkv (fp16 out + aux)  3: rk (rkh only)  4: score_bd
    half_all<<<(2162688 + 255) / 256, 256>>>(mem, inputs, r, Wqkv, Wr, Wo, w1, w2, xh);
    lin_gemm_h<<<dim3(QKVW / 128, KROWS / 128), 256, SMEM_H>>>(
        memh, wqkvh, nullptr, nullptr, qkvh, u, v, quh, qvh, khp,
        DMODEL, QKVW, 8 | 16 | 32);
    lin_gemm_h<<<dim3(DMODEL / 128, KLEN / 128), 256, SMEM_H>>>(
        rh, wrh, nullptr, nullptr, rkhp, nullptr, nullptr, nullptr, nullptr, nullptr,
        DMODEL, DMODEL, 16 | 64);
    score_bd<<<dim3(KLEN / 128, QLEN / 128, BH), 256, SMEM_H>>>(qvh, rkhp, bdp);
    // 5-7
    score_ac<<<dim3(KLEN / 128, QLEN / 128, BH), 256, SMEM_H>>>(quh, khp, bdp, shp, partp);
    prep_vt<<<dim3(KLEN / 32, DHEAD / 32, BH), 256>>>(qkvh, vth);
    statcombine<<<(BH * QLEN + 255) / 256, 256>>>(partp, statp);
    // fork prob output onto side stream
    cudaEventRecord(eFork, 0);
    cudaStreamWaitEvent(s2, eFork, 0);
    float* prob_out = (float*)d_out + QLEN * BATCH * DMODEL;
    probout<<<dim3(KLEN / 128, QLEN), 256, 0, s2>>>(shp, statp, prob_out);
    cudaEventRecord(eJoin, s2);
    // tail
    attn_exp_gemm<<<dim3(QLEN / 128, BH), 128>>>(shp, statp, vth, athp);
    lin_gemm_h<<<dim3(DMODEL / 128, QROWS / 128), 256, SMEM_H>>>(
        athp, woh, nullptr, aop, nullptr, nullptr, nullptr, nullptr, nullptr, nullptr,
        DMODEL, DMODEL, 0);
    add_ln<<<QROWS, 256>>>(inputs, aop, ln1_g, ln1_b, yp, yh);
    lin_gemm_h<<<dim3(DMLP / 128, QROWS / 128), 256, SMEM_H>>>(
        yh, w1h, b1, nullptr, hh, nullptr, nullptr, nullptr, nullptr, nullptr,
        DMODEL, DMLP, 1 | 2 | 8 | 16);
    lin_gemm_h<<<dim3(DMODEL / 128, QROWS / 128), 256, SMEM_H>>>(
        hh, w2h, b2, zp, nullptr, nullptr, nullptr, nullptr, nullptr, nullptr,
        DMLP, DMODEL, 1);
    add_ln<<<QROWS, 256>>>(yp, zp, ln2_g, ln2_b, (float*)d_out, nullptr);
    cudaStreamWaitEvent(0, eJoin, 0);
}

// round 15
// speedup vs baseline: 1.5746x; 1.0604x over previous
#include <cuda_runtime.h>
#include <cuda_fp16.h>
#include <math.h>

#define QLEN 1024
#define BATCH 4
#define DMODEL 512
#define HEADS 8
#define DHEAD 64
#define MEMLEN 1024
#define KLEN 2048
#define DMLP 2048
#define BH 32
#define QROWS 4096
#define KROWS 8192
#define QKVW 1536
#define QSTRIDE 6144
#define QK ((size_t)QLEN * KLEN)
#define SMEM_H 36864
#define BDPAD 264
#define SMEM_AC (36864 + 128 * BDPAD * 2)   // pipeline + BD tile

__device__ __half g_qkvh[KROWS * QKVW];
__device__ __half g_quh[BH * QLEN * DHEAD];
__device__ __half g_qvh[BH * QLEN * DHEAD];
__device__ __half g_kh[BH * KLEN * DHEAD];
__device__ __half g_rkh[HEADS * KLEN * DHEAD];
__device__ __half g_vth[BH * DHEAD * KLEN];
__device__ __half g_Sh[(size_t)BH * QLEN * KLEN];
__device__ float2 g_part[(size_t)BH * QLEN * 16];
__device__ float2 g_stat[BH * QLEN];
__device__ __half g_ath[QROWS * DMODEL];
__device__ float g_ao[QROWS * DMODEL];
__device__ float g_y[QROWS * DMODEL];
__device__ __half g_yh[QROWS * DMODEL];
__device__ __half g_hh[QROWS * DMLP];
__device__ float g_z[QROWS * DMODEL];
__device__ __half g_xh[8650752];

#define OFF_R    4194304
#define OFF_WQKV 5242880
#define OFF_WR   6029312
#define OFF_WO   6291456
#define OFF_W1   6553600
#define OFF_W2   7602176

__device__ __forceinline__ void cpa(unsigned dst, const void* src) {
    asm volatile("cp.async.ca.shared.global [%0], [%1], 16;" :: "r"(dst), "l"(src));
}
__device__ __forceinline__ void cp_commit() { asm volatile("cp.async.commit_group;"); }
__device__ __forceinline__ void cp_wait1()  { asm volatile("cp.async.wait_group 1;"); }
__device__ __forceinline__ void cp_wait0()  { asm volatile("cp.async.wait_group 0;"); }

__device__ __forceinline__ void mma_f16(float* acc, unsigned a0, unsigned a1,
                                        unsigned a2, unsigned a3,
                                        unsigned b0, unsigned b1) {
    asm volatile(
        "mma.sync.aligned.m16n8k16.row.col.f32.f16.f16.f32 "
        "{%0,%1,%2,%3}, {%4,%5,%6,%7}, {%8,%9}, {%0,%1,%2,%3};"
        : "+f"(acc[0]), "+f"(acc[1]), "+f"(acc[2]), "+f"(acc[3])
        : "r"(a0), "r"(a1), "r"(a2), "r"(a3), "r"(b0), "r"(b1));
}
__device__ __forceinline__ void ldsm_x4(unsigned& r0, unsigned& r1, unsigned& r2,
                                        unsigned& r3, unsigned addr) {
    asm volatile("ldmatrix.sync.aligned.m8n8.x4.shared.b16 {%0,%1,%2,%3}, [%4];"
                 : "=r"(r0), "=r"(r1), "=r"(r2), "=r"(r3) : "r"(addr));
}

__global__ void half_all(const float* __restrict__ s0, const float* __restrict__ s1,
                         const float* __restrict__ s2, const float* __restrict__ s3,
                         const float* __restrict__ s4, const float* __restrict__ s5,
                         const float* __restrict__ s6, const float* __restrict__ s7,
                         __half* __restrict__ dst) {
    int idx = blockIdx.x * 256 + threadIdx.x;
    if (idx >= 2162688) return;
    const float4* src; int base;
    if      (idx < 524288)  { src = (const float4*)s0; base = 0; }
    else if (idx < 1048576) { src = (const float4*)s1; base = 524288; }
    else if (idx < 1310720) { src = (const float4*)s2; base = 1048576; }
    else if (idx < 1507328) { src = (const float4*)s3; base = 1310720; }
    else if (idx < 1572864) { src = (const float4*)s4; base = 1507328; }
    else if (idx < 1638400) { src = (const float4*)s5; base = 1572864; }
    else if (idx < 1900544) { src = (const float4*)s6; base = 1638400; }
    else                    { src = (const float4*)s7; base = 1900544; }
    float4 v = src[idx - base];
    __half2 h01 = __floats2half2_rn(v.x, v.y);
    __half2 h23 = __floats2half2_rn(v.z, v.w);
    uint2 o;
    o.x = *(unsigned*)&h01;
    o.y = *(unsigned*)&h23;
    *(uint2*)(dst + (size_t)idx * 4) = o;
}

// ---- fp16 NT GEMM core: 256 thr, 8 warps (2Mx4N), 64x32 tiles, k16, 3-stage -
// B row index = min(brow0 + r, blim): clamped gather for the BD tiles.
__device__ __forceinline__ void gemm_core256h(
    const __half* __restrict__ A, int lda,
    const __half* __restrict__ B, int ldb, int brow0, int blim,
    int K, float acc[4][4][4], char* smc)
{
    const int tid = threadIdx.x;
    const int lane = tid & 31, warp = tid >> 5;
    const int wm = warp & 1, wn = warp >> 1;
    __syncthreads();   // stage-reuse safety for back-to-back core calls
    #pragma unroll
    for (int mt = 0; mt < 4; mt++)
        #pragma unroll
        for (int nt = 0; nt < 4; nt++)
            #pragma unroll
            for (int q = 0; q < 4; q++) acc[mt][nt][q] = 0.0f;

    const unsigned sbase = (unsigned)__cvta_generic_to_shared(smc);
    const int nk = K >> 4;
    const int r = tid >> 1, qh = tid & 1;
    const int br = min(brow0 + r, blim);
    auto load = [&](int it, int s) {
        int kt = it * 16;
        unsigned as = sbase + s * 6144;
        unsigned bs = sbase + 18432 + s * 6144;
        cpa(as + r * 48 + qh * 16, A + (size_t)r * lda + kt + qh * 8);
        cpa(bs + r * 48 + qh * 16, B + (size_t)br * ldb + kt + qh * 8);
        cp_commit();
    };
    load(0, 0);
    if (nk > 1) load(1, 1);

    const unsigned aOff = (unsigned)((wm * 64 + (lane & 15)) * 48 + (lane >> 4) * 16);
    const unsigned bOff = (unsigned)(18432 + (wn * 32 + (lane & 15)) * 48 + (lane >> 4) * 16);

    for (int it = 0; it < nk; it++) {
        if (it + 1 < nk) cp_wait1(); else cp_wait0();
        __syncthreads();
        if (it + 2 < nk) load(it + 2, (it + 2) % 3);
        const unsigned st = (unsigned)((it % 3) * 6144);
        const unsigned aS = sbase + st + aOff;
        const unsigned bS = sbase + st + bOff;
        unsigned af[4][4], bf[4][2];
        #pragma unroll
        for (int mt = 0; mt < 4; mt++)
            ldsm_x4(af[mt][0], af[mt][1], af[mt][2], af[mt][3], aS + mt * 16 * 48);
        #pragma unroll
        for (int p = 0; p < 2; p++) {
            unsigned r0, r1, r2, r3;
            ldsm_x4(r0, r1, r2, r3, bS + p * 16 * 48);
            bf[2*p][0] = r0; bf[2*p+1][0] = r1;
            bf[2*p][1] = r2; bf[2*p+1][1] = r3;
        }
        #pragma unroll
        for (int mt = 0; mt < 4; mt++)
            #pragma unroll
            for (int nt = 0; nt < 4; nt++)
                mma_f16(acc[mt][nt], af[mt][0], af[mt][1], af[mt][2], af[mt][3],
                        bf[nt][0], bf[nt][1]);
    }
}

// fp16 linear GEMM; act: 1 bias, 2 relu, 8 fp16 Ch, 16 skip fp32 C,
//                   32 qkv-aux, 64 rkh pack, 128 Ch only for V-columns
__global__ __launch_bounds__(256, 2) void lin_gemm_h(
    const __half* __restrict__ A, const __half* __restrict__ W,
    const float* __restrict__ bias, float* __restrict__ C,
    __half* __restrict__ Ch,
    const float* __restrict__ uu, const float* __restrict__ vv,
    __half* __restrict__ Quh, __half* __restrict__ Qvh, __half* __restrict__ Kh,
    int K, int N, int act)
{
    extern __shared__ char smc[];
    int m0 = blockIdx.y * 128, n0 = blockIdx.x * 128;
    float acc[4][4][4];
    gemm_core256h(A + (size_t)m0 * K, K, W + (size_t)n0 * K, K, 0, 1 << 30, K, acc, smc);
    const int lane = threadIdx.x & 31, warp = threadIdx.x >> 5;
    const int wm = warp & 1, wn = warp >> 1;
    const int grp = lane >> 2, tig = lane & 3;
    const float* bp = bias ? bias + n0 : nullptr;
    #pragma unroll
    for (int mt = 0; mt < 4; mt++) {
        int r0l = wm * 64 + mt * 16 + grp;
        #pragma unroll
        for (int nt = 0; nt < 4; nt++) {
            int c0 = wn * 32 + nt * 8 + tig * 2;
            float v0 = acc[mt][nt][0], v1 = acc[mt][nt][1];
            float v2 = acc[mt][nt][2], v3 = acc[mt][nt][3];
            if (act & 1) { float b0 = bp[c0], b1 = bp[c0 + 1];
                           v0 += b0; v1 += b1; v2 += b0; v3 += b1; }
            if (act & 2) { v0 = fmaxf(v0, 0.f); v1 = fmaxf(v1, 0.f);
                           v2 = fmaxf(v2, 0.f); v3 = fmaxf(v3, 0.f); }
            int n = n0 + c0;
            if (act & 32) {
                #pragma unroll
                for (int hh = 0; hh < 2; hh++) {
                    int rg = m0 + r0l + hh * 8;
                    float q0 = (hh == 0) ? v0 : v2;
                    float q1 = (hh == 0) ? v1 : v3;
                    if (n < DMODEL) {
                        if (rg >= 4096) {
                            int j = (rg >> 2) - MEMLEN, b = rg & 3;
                            int h = n >> 6, d = n & 63;
                            size_t o = ((size_t)(b * HEADS + h) * QLEN + j) * DHEAD + d;
                            *(__half2*)(Quh + o) = __floats2half2_rn(q0 + uu[n], q1 + uu[n + 1]);
                            *(__half2*)(Qvh + o) = __floats2half2_rn(q0 + vv[n], q1 + vv[n + 1]);
                        }
                    } else if (n < 2 * DMODEL) {
                        int j = rg >> 2, b = rg & 3;
                        int nn = n - DMODEL, h = nn >> 6, d = nn & 63;
                        size_t o = ((size_t)(b * HEADS + h) * KLEN + j) * DHEAD + d;
                        *(__half2*)(Kh + o) = __floats2half2_rn(q0, q1);
                    }
                }
            }
            if (act & 64) {
                int h = n >> 6, d = n & 63;
                #pragma unroll
                for (int hh = 0; hh < 2; hh++) {
                    int p = m0 + r0l + hh * 8;
                    size_t o = ((size_t)h * KLEN + p) * DHEAD + d;
                    *(__half2*)(Ch + o) = __floats2half2_rn(hh == 0 ? v0 : v2,
                                                            hh == 0 ? v1 : v3);
                }
            }
            if ((act & 8) && (!(act & 128) || n >= 2 * DMODEL)) {
                *(__half2*)(Ch + (size_t)r0l * N + m0 * (size_t)N + n) =
                    __floats2half2_rn(v0, v1);
                *(__half2*)(Ch + (size_t)(r0l + 8) * N + m0 * (size_t)N + n) =
                    __floats2half2_rn(v2, v3);
            }
            if (!(act & 16)) {
                float* Cp = C + (size_t)m0 * N + n0;
                *(float2*)(Cp + (size_t)r0l * N + c0) = make_float2(v0, v1);
                *(float2*)(Cp + (size_t)(r0l + 8) * N + c0) = make_float2(v2, v3);
            }
        }
    }
}

// fused scores: BD (2 tiles, in smem) + AC + rel-shift + scale + partials
__global__ __launch_bounds__(256, 2) void score_ac(
    const __half* __restrict__ Qu, const __half* __restrict__ Kh,
    const __half* __restrict__ Qv, const __half* __restrict__ rkh,
    __half* __restrict__ S, float2* __restrict__ part_out)
{
    extern __shared__ char smc[];
    __half* BDs = (__half*)(smc + SMEM_H);
    int bh = blockIdx.z, h = bh & 7;
    int i0 = blockIdx.y * 128, j0 = blockIdx.x * 128;
    if (j0 - i0 > 1024) return;
    const int p0 = j0 - i0 + 896;   // >= 0 always
    const int tid = threadIdx.x;
    const int lane = tid & 31, warp = tid >> 5;
    const int wm = warp & 1, wn = warp >> 1;
    const int grp = lane >> 2, tig = lane & 3;

    float acc[4][4][4];
    const __half* QvA = Qv + ((size_t)bh * QLEN + i0) * DHEAD;
    const __half* rkB = rkh + (size_t)h * KLEN * DHEAD;

    // BD halves -> smem tile [128][BDPAD]
    #pragma unroll
    for (int half_idx = 0; half_idx < 2; half_idx++) {
        gemm_core256h(QvA, DHEAD, rkB, DHEAD, p0 + half_idx * 128, KLEN - 1,
                      DHEAD, acc, smc);
        #pragma unroll
        for (int mt = 0; mt < 4; mt++) {
            int r0 = wm * 64 + mt * 16 + grp;
            #pragma unroll
            for (int nt = 0; nt < 4; nt++) {
                int c0 = wn * 32 + nt * 8 + tig * 2 + half_idx * 128;
                *(__half2*)(BDs + r0 * BDPAD + c0) =
                    __floats2half2_rn(acc[mt][nt][0], acc[mt][nt][1]);
                *(__half2*)(BDs + (r0 + 8) * BDPAD + c0) =
                    __floats2half2_rn(acc[mt][nt][2], acc[mt][nt][3]);
            }
        }
    }
    // AC
    gemm_core256h(Qu + ((size_t)bh * QLEN + i0) * DHEAD, DHEAD,
                  Kh + ((size_t)bh * KLEN + j0) * DHEAD, DHEAD, 0, 1 << 30,
                  DHEAD, acc, smc);
    __syncthreads();   // BDs fully written before reads

    __half* Sp = S + (size_t)bh * QK;
    #pragma unroll
    for (int mt = 0; mt < 4; mt++) {
        #pragma unroll
        for (int hh = 0; hh < 2; hh++) {
            int li = wm * 64 + mt * 16 + grp + hh * 8;
            int gi = i0 + li;
            int jmax = gi + MEMLEN;
            const __half* bdr = BDs + li * BDPAD;
            #pragma unroll
            for (int nt = 0; nt < 4; nt++) {
                int lj = wn * 32 + nt * 8 + tig * 2;
                int gj = j0 + lj;
                int pl = lj - li + 127;          // in [0, 254]
                float v0 = (gj <= jmax)
                    ? (acc[mt][nt][hh*2+0] + __half2float(bdr[pl])) * 0.125f : -30000.0f;
                float v1 = (gj + 1 <= jmax)
                    ? (acc[mt][nt][hh*2+1] + __half2float(bdr[pl + 1])) * 0.125f : -30000.0f;
                acc[mt][nt][hh*2+0] = v0;
                acc[mt][nt][hh*2+1] = v1;
                *(__half2*)(Sp + (size_t)gi * KLEN + gj) = __floats2half2_rn(v0, v1);
            }
        }
    }
    __syncthreads();
    float2* part = (float2*)smc;
    #pragma unroll
    for (int mt = 0; mt < 4; mt++) {
        #pragma unroll
        for (int hh = 0; hh < 2; hh++) {
            float m = -1e30f;
            #pragma unroll
            for (int nt = 0; nt < 4; nt++) {
                m = fmaxf(m, acc[mt][nt][hh*2+0]);
                m = fmaxf(m, acc[mt][nt][hh*2+1]);
            }
            float s = 0.f;
            #pragma unroll
            for (int nt = 0; nt < 4; nt++) {
                s += __expf(acc[mt][nt][hh*2+0] - m);
                s += __expf(acc[mt][nt][hh*2+1] - m);
            }
            #pragma unroll
            for (int o = 1; o < 4; o <<= 1) {
                float m2 = __shfl_xor_sync(0xffffffffu, m, o);
                float s2 = __shfl_xor_sync(0xffffffffu, s, o);
                float mm = fmaxf(m, m2);
                s = s * __expf(m - mm) + s2 * __expf(m2 - mm);
                m = mm;
            }
            if (tig == 0)
                part[wn * 128 + wm * 64 + mt * 16 + hh * 8 + grp] = make_float2(m, s);
        }
    }
    __syncthreads();
    if (tid < 128) {
        float2 a = part[tid];
        float M = a.x, Ssum = a.y;
        #pragma unroll
        for (int t = 1; t < 4; t++) {
            float2 c = part[t * 128 + tid];
            float mm = fmaxf(M, c.x);
            Ssum = Ssum * __expf(M - mm) + c.y * __expf(c.x - mm);
            M = mm;
        }
        part_out[((size_t)bh * QLEN + i0 + tid) * 16 + (j0 >> 7)] = make_float2(M, Ssum);
    }
}

__global__ void statcombine(const float2* __restrict__ part, float2* __restrict__ stat) {
    int id = blockIdx.x * 256 + threadIdx.x;
    if (id >= BH * QLEN) return;
    int i = id & (QLEN - 1);
    int ntl = (i >> 7) + 9; if (ntl > 16) ntl = 16;
    float M = -1e30f, Ssum = 0.f;
    const float2* p = part + (size_t)id * 16;
    for (int t = 0; t < ntl; t++) {
        float2 q = p[t];
        float mm = fmaxf(M, q.x);
        Ssum = Ssum * __expf(M - mm) + q.y * __expf(q.x - mm);
        M = mm;
    }
    stat[id] = make_float2(M, 1.0f / Ssum);
}

__global__ void probout(const __half* __restrict__ S, const float2* __restrict__ stat,
                        float* __restrict__ out) {
    __shared__ float t[128][33];
    __shared__ float m_s[32], inv_s[32];
    const int i = blockIdx.y, j0 = blockIdx.x * 128;
    const int tid = threadIdx.x;
    const int jmax = i + MEMLEN;
    float* obase = out + ((size_t)i * KLEN + j0) * 32;
    if (j0 > jmax) {
        float4 z = make_float4(0.f, 0.f, 0.f, 0.f);
        #pragma unroll
        for (int l = 0; l < 4; l++)
            ((float4*)obase)[l * 256 + tid] = z;
        return;
    }
    if (tid < 32) {
        float2 st = stat[tid * QLEN + i];
        m_s[tid] = st.x; inv_s[tid] = st.y;
    }
    __syncthreads();
    const int lb = tid >> 5, lj4 = tid & 31;
    #pragma unroll
    for (int r = 0; r < 4; r++) {
        int bh = r * 8 + lb;
        uint2 raw = *(const uint2*)(S + ((size_t)bh * QLEN + i) * KLEN + j0 + lj4 * 4);
        float2 f0 = __half22float2(*(__half2*)&raw.x);
        float2 f1 = __half22float2(*(__half2*)&raw.y);
        float m = m_s[bh], iv = inv_s[bh];
        int j = j0 + lj4 * 4;
        t[lj4*4+0][bh] = (j     <= jmax) ? __expf(f0.x - m) * iv : 0.f;
        t[lj4*4+1][bh] = (j + 1 <= jmax) ? __expf(f0.y - m) * iv : 0.f;
        t[lj4*4+2][bh] = (j + 2 <= jmax) ? __expf(f1.x - m) * iv : 0.f;
        t[lj4*4+3][bh] = (j + 3 <= jmax) ? __expf(f1.y - m) * iv : 0.f;
    }
    __syncthreads();
    const int bh4 = (tid & 7) * 4;
    #pragma unroll
    for (int p = 0; p < 4; p++) {
        int jl = p * 32 + (tid >> 3);
        float4 w = make_float4(t[jl][bh4], t[jl][bh4+1], t[jl][bh4+2], t[jl][bh4+3]);
        *(float4*)(obase + (size_t)jl * 32 + bh4) = w;
    }
}

__global__ __launch_bounds__(128, 2) void attn_exp_gemm(
    const __half* __restrict__ S, const float2* __restrict__ stat,
    const __half* __restrict__ Vt, __half* __restrict__ ath)
{
    const int bh = blockIdx.y, b = bh >> 3, h = bh & 7;
    const int i0 = blockIdx.x * 128;
    __shared__ __align__(16) __half As[128 * 24];
    __shared__ __align__(16) __half Bs[2][64 * 24];
    __shared__ float m_s[128], inv_s[128];
    const int tid = threadIdx.x;
    const int lane = tid & 31, warp = tid >> 5;
    const int wm = warp & 1, wn = warp >> 1;
    const int grp = lane >> 2, tig = lane & 3;
    {
        float2 st = stat[bh * QLEN + i0 + tid];
        m_s[tid] = st.x; inv_s[tid] = st.y;
    }
    __syncthreads();
    const __half* Srow = S + (size_t)bh * QK + (size_t)i0 * KLEN;
    const __half* Vb = Vt + (size_t)bh * DHEAD * KLEN;
    const int K1 = min(KLEN, i0 + 128 + MEMLEN);
    const int nk = K1 >> 4;

    float acc[4][4][4];
    #pragma unroll
    for (int mt = 0; mt < 4; mt++)
        #pragma unroll
        for (int nt = 0; nt < 4; nt++)
            #pragma unroll
            for (int q = 0; q < 4; q++) acc[mt][nt][q] = 0.f;

    const unsigned aBase = (unsigned)__cvta_generic_to_shared(As);
    const unsigned bBase = (unsigned)__cvta_generic_to_shared(&Bs[0][0]);
    const int rowsel = lane & 15, chsel = lane >> 4;
    const unsigned aOff = aBase + (unsigned)((wm * 64 + rowsel) * 48 + chsel * 16);
    const unsigned bOff = bBase + (unsigned)((wn * 32 + rowsel) * 48 + chsel * 16);

    uint4 aR[2];
    aR[0] = *(const uint4*)(Srow + (size_t)tid * KLEN);
    aR[1] = *(const uint4*)(Srow + (size_t)tid * KLEN + 8);
    {
        int rb = tid >> 1, ch = tid & 1;
        cpa(bBase + rb * 48 + ch * 16, Vb + (size_t)rb * KLEN + ch * 8);
        cp_commit();
    }
    const float mr = m_s[tid];
    const int jmaxr = i0 + tid + MEMLEN;

    int cur = 0;
    for (int it = 0; it < nk; it++) {
        const int kt = it * 16;
        uint4 aN[2];
        if (it + 1 < nk) {
            int ktn = kt + 16;
            int rb = tid >> 1, ch = tid & 1;
            cpa(bBase + (cur ^ 1) * 3072 + rb * 48 + ch * 16,
                Vb + (size_t)rb * KLEN + ktn + ch * 8);
            aN[0] = *(const uint4*)(Srow + (size_t)tid * KLEN + ktn);
            aN[1] = *(const uint4*)(Srow + (size_t)tid * KLEN + ktn + 8);
            cp_commit();
        }
        {
            const __half* hp = (const __half*)aR;
            __half outh[16];
            #pragma unroll
            for (int c = 0; c < 16; c++) {
                float e = (kt + c <= jmaxr) ? __expf(__half2float(hp[c]) - mr) : 0.f;
                outh[c] = __float2half_rn(e);
            }
            *(uint4*)(As + tid * 24)     = *(uint4*)outh;
            *(uint4*)(As + tid * 24 + 8) = *(uint4*)(outh + 8);
        }
        if (it + 1 < nk) cp_wait1(); else cp_wait0();
        __syncthreads();
        const unsigned bS = bOff + (unsigned)(cur * 3072);
        unsigned af[4][4], bf[4][2];
        #pragma unroll
        for (int mt = 0; mt < 4; mt++)
            ldsm_x4(af[mt][0], af[mt][1], af[mt][2], af[mt][3], aOff + mt * 16 * 48);
        #pragma unroll
        for (int p = 0; p < 2; p++) {
            unsigned r0, r1, r2, r3;
            ldsm_x4(r0, r1, r2, r3, bS + p * 16 * 48);
            bf[2*p][0] = r0; bf[2*p+1][0] = r1;
            bf[2*p][1] = r2; bf[2*p+1][1] = r3;
        }
        #pragma unroll
        for (int mt = 0; mt < 4; mt++)
            #pragma unroll
            for (int nt = 0; nt < 4; nt++)
                mma_f16(acc[mt][nt], af[mt][0], af[mt][1], af[mt][2], af[mt][3],
                        bf[nt][0], bf[nt][1]);
        __syncthreads();
        aR[0] = aN[0]; aR[1] = aN[1];
        cur ^= 1;
    }
    #pragma unroll
    for (int mt = 0; mt < 4; mt++) {
        int r0 = wm * 64 + mt * 16 + grp;
        float iv0 = inv_s[r0], iv1 = inv_s[r0 + 8];
        #pragma unroll
        for (int nt = 0; nt < 4; nt++) {
            int c0 = wn * 32 + nt * 8 + tig * 2;
            size_t o0 = ((size_t)(i0 + r0) * BATCH + b) * DMODEL + h * DHEAD + c0;
            size_t o1 = ((size_t)(i0 + r0 + 8) * BATCH + b) * DMODEL + h * DHEAD + c0;
            *(__half2*)(ath + o0) =
                __floats2half2_rn(acc[mt][nt][0] * iv0, acc[mt][nt][1] * iv0);
            *(__half2*)(ath + o1) =
                __floats2half2_rn(acc[mt][nt][2] * iv1, acc[mt][nt][3] * iv1);
        }
    }
}

__global__ void prep_vt(const __half* __restrict__ qkvh, __half* __restrict__ Vt) {
    __shared__ __half t[32][34];
    int bh = blockIdx.z, b = bh >> 3, h = bh & 7;
    int j0 = blockIdx.x * 32, d0 = blockIdx.y * 32;
    int tc = threadIdx.x & 31, tr = threadIdx.x >> 5;
    #pragma unroll
    for (int rr = 0; rr < 32; rr += 8)
        t[tr + rr][tc] = qkvh[(size_t)(j0 + tr + rr) * QSTRIDE + b * QKVW
                              + 2 * DMODEL + h * DHEAD + d0 + tc];
    __syncthreads();
    #pragma unroll
    for (int rr = 0; rr < 32; rr += 8)
        Vt[((size_t)bh * DHEAD + d0 + tr + rr) * KLEN + j0 + tc] = t[tc][tr + rr];
}

__global__ void add_ln(const float* __restrict__ x1, const float* __restrict__ x2,
                       const float* __restrict__ g, const float* __restrict__ bb,
                       float* __restrict__ out, __half* __restrict__ outh) {
    const int row = blockIdx.x;
    const int tid = threadIdx.x;
    __shared__ float red[256];
    __shared__ float red2[256];
    const float* a = x1 + (size_t)row * DMODEL;
    const float* c = x2 + (size_t)row * DMODEL;
    float v0 = a[tid] + c[tid];
    float v1 = a[tid + 256] + c[tid + 256];
    red[tid] = v0 + v1;
    red2[tid] = v0 * v0 + v1 * v1;
    __syncthreads();
    for (int o = 128; o > 0; o >>= 1) {
        if (tid < o) { red[tid] += red[tid + o]; red2[tid] += red2[tid + o]; }
        __syncthreads();
    }
    const float mu = red[0] * (1.0f / DMODEL);
    const float var = red2[0] * (1.0f / DMODEL) - mu * mu;
    const float rstd = rsqrtf(var + 1e-5f);
    float* o = out + (size_t)row * DMODEL;
    float r0 = (v0 - mu) * rstd * g[tid] + bb[tid];
    float r1 = (v1 - mu) * rstd * g[tid + 256] + bb[tid + 256];
    o[tid] = r0;
    o[tid + 256] = r1;
    if (outh) {
        outh[(size_t)row * DMODEL + tid] = __float2half_rn(r0);
        outh[(size_t)row * DMODEL + tid + 256] = __float2half_rn(r1);
    }
}

extern "C" void kernel_launch(void* const* d_in, const int* in_sizes, int n_in,
                              void* d_out, int out_size) {
    const float* inputs = (const float*)d_in[0];
    const float* r      = (const float*)d_in[1];
    const float* u      = (const float*)d_in[2];
    const float* v      = (const float*)d_in[3];
    const float* mem    = (const float*)d_in[4];
    const float* Wqkv   = (const float*)d_in[6];
    const float* Wr     = (const float*)d_in[7];
    const float* Wo     = (const float*)d_in[8];
    const float* ln1_g  = (const float*)d_in[9];
    const float* ln1_b  = (const float*)d_in[10];
    const float* w1     = (const float*)d_in[11];
    const float* b1     = (const float*)d_in[12];
    const float* w2     = (const float*)d_in[13];
    const float* b2     = (const float*)d_in[14];
    const float* ln2_g  = (const float*)d_in[15];
    const float* ln2_b  = (const float*)d_in[16];

    static cudaStream_t s2 = nullptr;
    static cudaEvent_t eFork = nullptr, eJoin = nullptr;
    if (!s2) {
        cudaFuncSetAttribute(lin_gemm_h, cudaFuncAttributeMaxDynamicSharedMemorySize, SMEM_H);
        cudaFuncSetAttribute(score_ac, cudaFuncAttributeMaxDynamicSharedMemorySize, SMEM_AC);
        cudaStreamCreateWithFlags(&s2, cudaStreamNonBlocking);
        cudaEventCreateWithFlags(&eFork, cudaEventDisableTiming);
        cudaEventCreateWithFlags(&eJoin, cudaEventDisableTiming);
    }

    float *aop, *yp, *zp;
    __half *qkvh, *quh, *qvh, *khp, *rkhp, *vth, *shp, *athp, *yh, *hh, *xh;
    float2 *statp, *partp;
    cudaGetSymbolAddress((void**)&qkvh,  g_qkvh);
    cudaGetSymbolAddress((void**)&quh,   g_quh);
    cudaGetSymbolAddress((void**)&qvh,   g_qvh);
    cudaGetSymbolAddress((void**)&khp,   g_kh);
    cudaGetSymbolAddress((void**)&rkhp,  g_rkh);
    cudaGetSymbolAddress((void**)&vth,   g_vth);
    cudaGetSymbolAddress((void**)&shp,   g_Sh);
    cudaGetSymbolAddress((void**)&statp, g_stat);
    cudaGetSymbolAddress((void**)&partp, g_part);
    cudaGetSymbolAddress((void**)&athp,  g_ath);
    cudaGetSymbolAddress((void**)&aop,   g_ao);
    cudaGetSymbolAddress((void**)&yp,    g_y);
    cudaGetSymbolAddress((void**)&yh,    g_yh);
    cudaGetSymbolAddress((void**)&hh,    g_hh);
    cudaGetSymbolAddress((void**)&zp,    g_z);
    cudaGetSymbolAddress((void**)&xh,    g_xh);

    const __half* memh  = xh;
    const __half* rh    = xh + OFF_R;
    const __half* wqkvh = xh + OFF_WQKV;
    const __half* wrh   = xh + OFF_WR;
    const __half* woh   = xh + OFF_WO;
    const __half* w1h   = xh + OFF_W1;
    const __half* w2h   = xh + OFF_W2;

    // 1: fp16 conv  2: qkv (V-only Ch + aux)  3: rk (rkh)  4: fused score_ac
    half_all<<<(2162688 + 255) / 256, 256>>>(mem, inputs, r, Wqkv, Wr, Wo, w1, w2, xh);
    lin_gemm_h<<<dim3(QKVW / 128, KROWS / 128), 256, SMEM_H>>>(
        memh, wqkvh, nullptr, nullptr, qkvh, u, v, quh, qvh, khp,
        DMODEL, QKVW, 8 | 16 | 32 | 128);
    lin_gemm_h<<<dim3(DMODEL / 128, KLEN / 128), 256, SMEM_H>>>(
        rh, wrh, nullptr, nullptr, rkhp, nullptr, nullptr, nullptr, nullptr, nullptr,
        DMODEL, DMODEL, 16 | 64);
    score_ac<<<dim3(KLEN / 128, QLEN / 128, BH), 256, SMEM_AC>>>(
        quh, khp, qvh, rkhp, shp, partp);
    // 5-6
    prep_vt<<<dim3(KLEN / 32, DHEAD / 32, BH), 256>>>(qkvh, vth);
    statcombine<<<(BH * QLEN + 255) / 256, 256>>>(partp, statp);
    // fork prob output onto side stream
    cudaEventRecord(eFork, 0);
    cudaStreamWaitEvent(s2, eFork, 0);
    float* prob_out = (float*)d_out + QLEN * BATCH * DMODEL;
    probout<<<dim3(KLEN / 128, QLEN), 256, 0, s2>>>(shp, statp, prob_out);
    cudaEventRecord(eJoin, s2);
    // tail
    attn_exp_gemm<<<dim3(QLEN / 128, BH), 128>>>(shp, statp, vth, athp);
    lin_gemm_h<<<dim3(DMODEL / 128, QROWS / 128), 256, SMEM_H>>>(
        athp, woh, nullptr, aop, nullptr, nullptr, nullptr, nullptr, nullptr, nullptr,
        DMODEL, DMODEL, 0);
    add_ln<<<QROWS, 256>>>(inputs, aop, ln1_g, ln1_b, yp, yh);
    lin_gemm_h<<<dim3(DMLP / 128, QROWS / 128), 256, SMEM_H>>>(
        yh, w1h, b1, nullptr, hh, nullptr, nullptr, nullptr, nullptr, nullptr,
        DMODEL, DMLP, 1 | 2 | 8 | 16);
    lin_gemm_h<<<dim3(DMODEL / 128, QROWS / 128), 256, SMEM_H>>>(
        hh, w2h, b2, zp, nullptr, nullptr, nullptr, nullptr, nullptr, nullptr,
        DMLP, DMODEL, 1);
    add_ln<<<QROWS, 256>>>(yp, zp, ln2_g, ln2_b, (float*)d_out, nullptr);
    cudaStreamWaitEvent(0, eJoin, 0);
}

// round 16
// speedup vs baseline: 1.6165x; 1.0266x over previous
#include <cuda_runtime.h>
#include <cuda_fp16.h>
#include <math.h>

#define QLEN 1024
#define BATCH 4
#define DMODEL 512
#define HEADS 8
#define DHEAD 64
#define MEMLEN 1024
#define KLEN 2048
#define DMLP 2048
#define BH 32
#define QROWS 4096
#define KROWS 8192
#define QKVW 1536
#define QSTRIDE 6144
#define QK ((size_t)QLEN * KLEN)
#define SMEM_H 36864
// score_ac: A tile 128x144B, B tile 128x144B, BD tile 128x260 halves
#define ROWB 144
#define OPB_OFF 18432
#define BD_OFF 36864
#define BDPAD 260
#define SMEM_AC (BD_OFF + 128 * BDPAD * 2)   // 103424

__device__ __half g_qkvh[KROWS * QKVW];
__device__ __half g_quh[BH * QLEN * DHEAD];
__device__ __half g_qvh[BH * QLEN * DHEAD];
__device__ __half g_kh[BH * KLEN * DHEAD];
__device__ __half g_rkh[HEADS * KLEN * DHEAD];
__device__ __half g_vth[BH * DHEAD * KLEN];
__device__ __half g_Sh[(size_t)BH * QLEN * KLEN];
__device__ float2 g_part[(size_t)BH * QLEN * 16];
__device__ float2 g_stat[BH * QLEN];
__device__ __half g_ath[QROWS * DMODEL];
__device__ float g_ao[QROWS * DMODEL];
__device__ float g_y[QROWS * DMODEL];
__device__ __half g_yh[QROWS * DMODEL];
__device__ __half g_hh[QROWS * DMLP];
__device__ float g_z[QROWS * DMODEL];
__device__ __half g_xh[8650752];

#define OFF_R    4194304
#define OFF_WQKV 5242880
#define OFF_WR   6029312
#define OFF_WO   6291456
#define OFF_W1   6553600
#define OFF_W2   7602176

__device__ __forceinline__ void cpa(unsigned dst, const void* src) {
    asm volatile("cp.async.ca.shared.global [%0], [%1], 16;" :: "r"(dst), "l"(src));
}
__device__ __forceinline__ void cp_commit() { asm volatile("cp.async.commit_group;"); }
__device__ __forceinline__ void cp_wait1()  { asm volatile("cp.async.wait_group 1;"); }
__device__ __forceinline__ void cp_wait0()  { asm volatile("cp.async.wait_group 0;"); }

__device__ __forceinline__ void mma_f16(float* acc, unsigned a0, unsigned a1,
                                        unsigned a2, unsigned a3,
                                        unsigned b0, unsigned b1) {
    asm volatile(
        "mma.sync.aligned.m16n8k16.row.col.f32.f16.f16.f32 "
        "{%0,%1,%2,%3}, {%4,%5,%6,%7}, {%8,%9}, {%0,%1,%2,%3};"
        : "+f"(acc[0]), "+f"(acc[1]), "+f"(acc[2]), "+f"(acc[3])
        : "r"(a0), "r"(a1), "r"(a2), "r"(a3), "r"(b0), "r"(b1));
}
__device__ __forceinline__ void ldsm_x4(unsigned& r0, unsigned& r1, unsigned& r2,
                                        unsigned& r3, unsigned addr) {
    asm volatile("ldmatrix.sync.aligned.m8n8.x4.shared.b16 {%0,%1,%2,%3}, [%4];"
                 : "=r"(r0), "=r"(r1), "=r"(r2), "=r"(r3) : "r"(addr));
}

__global__ void half_all(const float* __restrict__ s0, const float* __restrict__ s1,
                         const float* __restrict__ s2, const float* __restrict__ s3,
                         const float* __restrict__ s4, const float* __restrict__ s5,
                         const float* __restrict__ s6, const float* __restrict__ s7,
                         __half* __restrict__ dst) {
    int idx = blockIdx.x * 256 + threadIdx.x;
    if (idx >= 2162688) return;
    const float4* src; int base;
    if      (idx < 524288)  { src = (const float4*)s0; base = 0; }
    else if (idx < 1048576) { src = (const float4*)s1; base = 524288; }
    else if (idx < 1310720) { src = (const float4*)s2; base = 1048576; }
    else if (idx < 1507328) { src = (const float4*)s3; base = 1310720; }
    else if (idx < 1572864) { src = (const float4*)s4; base = 1507328; }
    else if (idx < 1638400) { src = (const float4*)s5; base = 1572864; }
    else if (idx < 1900544) { src = (const float4*)s6; base = 1638400; }
    else                    { src = (const float4*)s7; base = 1900544; }
    float4 v = src[idx - base];
    __half2 h01 = __floats2half2_rn(v.x, v.y);
    __half2 h23 = __floats2half2_rn(v.z, v.w);
    uint2 o;
    o.x = *(unsigned*)&h01;
    o.y = *(unsigned*)&h23;
    *(uint2*)(dst + (size_t)idx * 4) = o;
}

// ---- fp16 NT GEMM pipelined core (linears/attn prep): unchanged from R15 ----
__device__ __forceinline__ void gemm_core256h(
    const __half* __restrict__ A, int lda,
    const __half* __restrict__ B, int ldb,
    int K, float acc[4][4][4], char* smc)
{
    const int tid = threadIdx.x;
    const int lane = tid & 31, warp = tid >> 5;
    const int wm = warp & 1, wn = warp >> 1;
    #pragma unroll
    for (int mt = 0; mt < 4; mt++)
        #pragma unroll
        for (int nt = 0; nt < 4; nt++)
            #pragma unroll
            for (int q = 0; q < 4; q++) acc[mt][nt][q] = 0.0f;

    const unsigned sbase = (unsigned)__cvta_generic_to_shared(smc);
    const int nk = K >> 4;
    const int r = tid >> 1, qh = tid & 1;
    auto load = [&](int it, int s) {
        int kt = it * 16;
        unsigned as = sbase + s * 6144;
        unsigned bs = sbase + 18432 + s * 6144;
        cpa(as + r * 48 + qh * 16, A + (size_t)r * lda + kt + qh * 8);
        cpa(bs + r * 48 + qh * 16, B + (size_t)r * ldb + kt + qh * 8);
        cp_commit();
    };
    load(0, 0);
    if (nk > 1) load(1, 1);

    const unsigned aOff = (unsigned)((wm * 64 + (lane & 15)) * 48 + (lane >> 4) * 16);
    const unsigned bOff = (unsigned)(18432 + (wn * 32 + (lane & 15)) * 48 + (lane >> 4) * 16);

    for (int it = 0; it < nk; it++) {
        if (it + 1 < nk) cp_wait1(); else cp_wait0();
        __syncthreads();
        if (it + 2 < nk) load(it + 2, (it + 2) % 3);
        const unsigned st = (unsigned)((it % 3) * 6144);
        const unsigned aS = sbase + st + aOff;
        const unsigned bS = sbase + st + bOff;
        unsigned af[4][4], bf[4][2];
        #pragma unroll
        for (int mt = 0; mt < 4; mt++)
            ldsm_x4(af[mt][0], af[mt][1], af[mt][2], af[mt][3], aS + mt * 16 * 48);
        #pragma unroll
        for (int p = 0; p < 2; p++) {
            unsigned r0, r1, r2, r3;
            ldsm_x4(r0, r1, r2, r3, bS + p * 16 * 48);
            bf[2*p][0] = r0; bf[2*p+1][0] = r1;
            bf[2*p][1] = r2; bf[2*p+1][1] = r3;
        }
        #pragma unroll
        for (int mt = 0; mt < 4; mt++)
            #pragma unroll
            for (int nt = 0; nt < 4; nt++)
                mma_f16(acc[mt][nt], af[mt][0], af[mt][1], af[mt][2], af[mt][3],
                        bf[nt][0], bf[nt][1]);
        __syncthreads();
    }
}

// fp16 linear GEMM; act: 1 bias, 2 relu, 8 fp16 Ch, 16 skip fp32 C,
//                   32 qkv-aux, 64 rkh pack, 128 Ch only for V-columns
__global__ __launch_bounds__(256, 2) void lin_gemm_h(
    const __half* __restrict__ A, const __half* __restrict__ W,
    const float* __restrict__ bias, float* __restrict__ C,
    __half* __restrict__ Ch,
    const float* __restrict__ uu, const float* __restrict__ vv,
    __half* __restrict__ Quh, __half* __restrict__ Qvh, __half* __restrict__ Kh,
    int K, int N, int act)
{
    extern __shared__ char smc[];
    int m0 = blockIdx.y * 128, n0 = blockIdx.x * 128;
    float acc[4][4][4];
    gemm_core256h(A + (size_t)m0 * K, K, W + (size_t)n0 * K, K, K, acc, smc);
    const int lane = threadIdx.x & 31, warp = threadIdx.x >> 5;
    const int wm = warp & 1, wn = warp >> 1;
    const int grp = lane >> 2, tig = lane & 3;
    const float* bp = bias ? bias + n0 : nullptr;
    #pragma unroll
    for (int mt = 0; mt < 4; mt++) {
        int r0l = wm * 64 + mt * 16 + grp;
        #pragma unroll
        for (int nt = 0; nt < 4; nt++) {
            int c0 = wn * 32 + nt * 8 + tig * 2;
            float v0 = acc[mt][nt][0], v1 = acc[mt][nt][1];
            float v2 = acc[mt][nt][2], v3 = acc[mt][nt][3];
            if (act & 1) { float b0 = bp[c0], b1 = bp[c0 + 1];
                           v0 += b0; v1 += b1; v2 += b0; v3 += b1; }
            if (act & 2) { v0 = fmaxf(v0, 0.f); v1 = fmaxf(v1, 0.f);
                           v2 = fmaxf(v2, 0.f); v3 = fmaxf(v3, 0.f); }
            int n = n0 + c0;
            if (act & 32) {
                #pragma unroll
                for (int hh = 0; hh < 2; hh++) {
                    int rg = m0 + r0l + hh * 8;
                    float q0 = (hh == 0) ? v0 : v2;
                    float q1 = (hh == 0) ? v1 : v3;
                    if (n < DMODEL) {
                        if (rg >= 4096) {
                            int j = (rg >> 2) - MEMLEN, b = rg & 3;
                            int h = n >> 6, d = n & 63;
                            size_t o = ((size_t)(b * HEADS + h) * QLEN + j) * DHEAD + d;
                            *(__half2*)(Quh + o) = __floats2half2_rn(q0 + uu[n], q1 + uu[n + 1]);
                            *(__half2*)(Qvh + o) = __floats2half2_rn(q0 + vv[n], q1 + vv[n + 1]);
                        }
                    } else if (n < 2 * DMODEL) {
                        int j = rg >> 2, b = rg & 3;
                        int nn = n - DMODEL, h = nn >> 6, d = nn & 63;
                        size_t o = ((size_t)(b * HEADS + h) * KLEN + j) * DHEAD + d;
                        *(__half2*)(Kh + o) = __floats2half2_rn(q0, q1);
                    }
                }
            }
            if (act & 64) {
                int h = n >> 6, d = n & 63;
                #pragma unroll
                for (int hh = 0; hh < 2; hh++) {
                    int p = m0 + r0l + hh * 8;
                    size_t o = ((size_t)h * KLEN + p) * DHEAD + d;
                    *(__half2*)(Ch + o) = __floats2half2_rn(hh == 0 ? v0 : v2,
                                                            hh == 0 ? v1 : v3);
                }
            }
            if ((act & 8) && (!(act & 128) || n >= 2 * DMODEL)) {
                *(__half2*)(Ch + (size_t)r0l * N + m0 * (size_t)N + n) =
                    __floats2half2_rn(v0, v1);
                *(__half2*)(Ch + (size_t)(r0l + 8) * N + m0 * (size_t)N + n) =
                    __floats2half2_rn(v2, v3);
            }
            if (!(act & 16)) {
                float* Cp = C + (size_t)m0 * N + n0;
                *(float2*)(Cp + (size_t)r0l * N + c0) = make_float2(v0, v1);
                *(float2*)(Cp + (size_t)(r0l + 8) * N + c0) = make_float2(v2, v3);
            }
        }
    }
}

// ---- single-shot K=64 tile helpers for fused score kernel -------------------
__device__ __forceinline__ void load_tile64(unsigned dst, const __half* G, int base,
                                            int lim, int tid) {
    // 128 rows x 8 chunks(16B); 256 threads -> 4 each; row stride ROWB
    #pragma unroll
    for (int l = 0; l < 4; l++) {
        int idx = l * 256 + tid;
        int r = idx >> 3, ch = idx & 7;
        int gr = min(base + r, lim);
        cpa(dst + r * ROWB + ch * 16, G + (size_t)gr * DHEAD + ch * 8);
    }
}
__device__ __forceinline__ void mma_tile64(unsigned sbase, float acc[4][4][4],
                                           int wm, int wn, int lane) {
    #pragma unroll
    for (int mt = 0; mt < 4; mt++)
        #pragma unroll
        for (int nt = 0; nt < 4; nt++)
            #pragma unroll
            for (int q = 0; q < 4; q++) acc[mt][nt][q] = 0.0f;
    const unsigned aOff = sbase + (unsigned)((wm * 64 + (lane & 15)) * ROWB + (lane >> 4) * 16);
    const unsigned bOff = sbase + (unsigned)(OPB_OFF + (wn * 32 + (lane & 15)) * ROWB + (lane >> 4) * 16);
    #pragma unroll
    for (int ks = 0; ks < 4; ks++) {
        unsigned af[4][4], bf[4][2];
        #pragma unroll
        for (int mt = 0; mt < 4; mt++)
            ldsm_x4(af[mt][0], af[mt][1], af[mt][2], af[mt][3],
                    aOff + mt * 16 * ROWB + ks * 32);
        #pragma unroll
        for (int p = 0; p < 2; p++) {
            unsigned r0, r1, r2, r3;
            ldsm_x4(r0, r1, r2, r3, bOff + p * 16 * ROWB + ks * 32);
            bf[2*p][0] = r0; bf[2*p+1][0] = r1;
            bf[2*p][1] = r2; bf[2*p+1][1] = r3;
        }
        #pragma unroll
        for (int mt = 0; mt < 4; mt++)
            #pragma unroll
            for (int nt = 0; nt < 4; nt++)
                mma_f16(acc[mt][nt], af[mt][0], af[mt][1], af[mt][2], af[mt][3],
                        bf[nt][0], bf[nt][1]);
    }
}

// fused scores: BD (2 half-tiles) + AC + rel-shift + scale + partials
__global__ __launch_bounds__(256, 2) void score_ac(
    const __half* __restrict__ Qu, const __half* __restrict__ Kh,
    const __half* __restrict__ Qv, const __half* __restrict__ rkh,
    __half* __restrict__ S, float2* __restrict__ part_out)
{
    extern __shared__ char smc[];
    __half* BDs = (__half*)(smc + BD_OFF);
    int bh = blockIdx.z, h = bh & 7;
    int i0 = blockIdx.y * 128, j0 = blockIdx.x * 128;
    if (j0 - i0 > 1024) return;
    const int p0 = j0 - i0 + 896;
    const int tid = threadIdx.x;
    const int lane = tid & 31, warp = tid >> 5;
    const int wm = warp & 1, wn = warp >> 1;
    const int grp = lane >> 2, tig = lane & 3;
    const unsigned sbase = (unsigned)__cvta_generic_to_shared(smc);

    float acc[4][4][4];
    const __half* rkB = rkh + (size_t)h * KLEN * DHEAD;

    // phase 1: Qv + rk[p0:p0+128) -> BD cols [0,128)
    load_tile64(sbase, Qv + ((size_t)bh * QLEN + i0) * DHEAD, 0, 1 << 30, tid);
    load_tile64(sbase + OPB_OFF, rkB, p0, KLEN - 1, tid);
    cp_commit(); cp_wait0(); __syncthreads();
    mma_tile64(sbase, acc, wm, wn, lane);
    #pragma unroll
    for (int mt = 0; mt < 4; mt++) {
        int r0 = wm * 64 + mt * 16 + grp;
        #pragma unroll
        for (int nt = 0; nt < 4; nt++) {
            int c0 = wn * 32 + nt * 8 + tig * 2;
            *(__half2*)(BDs + r0 * BDPAD + c0) =
                __floats2half2_rn(acc[mt][nt][0], acc[mt][nt][1]);
            *(__half2*)(BDs + (r0 + 8) * BDPAD + c0) =
                __floats2half2_rn(acc[mt][nt][2], acc[mt][nt][3]);
        }
    }
    __syncthreads();                   // phase-1 B reads done
    // phase 2: rk[p0+128:p0+256) -> BD cols [128,256)   (Qv stays resident)
    load_tile64(sbase + OPB_OFF, rkB, p0 + 128, KLEN - 1, tid);
    cp_commit(); cp_wait0(); __syncthreads();
    mma_tile64(sbase, acc, wm, wn, lane);
    #pragma unroll
    for (int mt = 0; mt < 4; mt++) {
        int r0 = wm * 64 + mt * 16 + grp;
        #pragma unroll
        for (int nt = 0; nt < 4; nt++) {
            int c0 = wn * 32 + nt * 8 + tig * 2 + 128;
            *(__half2*)(BDs + r0 * BDPAD + c0) =
                __floats2half2_rn(acc[mt][nt][0], acc[mt][nt][1]);
            *(__half2*)(BDs + (r0 + 8) * BDPAD + c0) =
                __floats2half2_rn(acc[mt][nt][2], acc[mt][nt][3]);
        }
    }
    __syncthreads();                   // phase-2 reads done + BD stores visible
    // phase 3: Qu + K[j0:j0+128) -> AC
    load_tile64(sbase, Qu + ((size_t)bh * QLEN + i0) * DHEAD, 0, 1 << 30, tid);
    load_tile64(sbase + OPB_OFF, Kh + ((size_t)bh * KLEN + j0) * DHEAD, 0, 1 << 30, tid);
    cp_commit(); cp_wait0(); __syncthreads();
    mma_tile64(sbase, acc, wm, wn, lane);

    __half* Sp = S + (size_t)bh * QK;
    #pragma unroll
    for (int mt = 0; mt < 4; mt++) {
        #pragma unroll
        for (int hh = 0; hh < 2; hh++) {
            int li = wm * 64 + mt * 16 + grp + hh * 8;
            int gi = i0 + li;
            int jmax = gi + MEMLEN;
            const __half* bdr = BDs + li * BDPAD;
            #pragma unroll
            for (int nt = 0; nt < 4; nt++) {
                int lj = wn * 32 + nt * 8 + tig * 2;
                int gj = j0 + lj;
                int pl = lj - li + 127;
                float v0 = (gj <= jmax)
                    ? (acc[mt][nt][hh*2+0] + __half2float(bdr[pl])) * 0.125f : -30000.0f;
                float v1 = (gj + 1 <= jmax)
                    ? (acc[mt][nt][hh*2+1] + __half2float(bdr[pl + 1])) * 0.125f : -30000.0f;
                acc[mt][nt][hh*2+0] = v0;
                acc[mt][nt][hh*2+1] = v1;
                *(__half2*)(Sp + (size_t)gi * KLEN + gj) = __floats2half2_rn(v0, v1);
            }
        }
    }
    __syncthreads();
    float2* part = (float2*)smc;
    #pragma unroll
    for (int mt = 0; mt < 4; mt++) {
        #pragma unroll
        for (int hh = 0; hh < 2; hh++) {
            float m = -1e30f;
            #pragma unroll
            for (int nt = 0; nt < 4; nt++) {
                m = fmaxf(m, acc[mt][nt][hh*2+0]);
                m = fmaxf(m, acc[mt][nt][hh*2+1]);
            }
            float s = 0.f;
            #pragma unroll
            for (int nt = 0; nt < 4; nt++) {
                s += __expf(acc[mt][nt][hh*2+0] - m);
                s += __expf(acc[mt][nt][hh*2+1] - m);
            }
            #pragma unroll
            for (int o = 1; o < 4; o <<= 1) {
                float m2 = __shfl_xor_sync(0xffffffffu, m, o);
                float s2 = __shfl_xor_sync(0xffffffffu, s, o);
                float mm = fmaxf(m, m2);
                s = s * __expf(m - mm) + s2 * __expf(m2 - mm);
                m = mm;
            }
            if (tig == 0)
                part[wn * 128 + wm * 64 + mt * 16 + hh * 8 + grp] = make_float2(m, s);
        }
    }
    __syncthreads();
    if (tid < 128) {
        float2 a = part[tid];
        float M = a.x, Ssum = a.y;
        #pragma unroll
        for (int t = 1; t < 4; t++) {
            float2 c = part[t * 128 + tid];
            float mm = fmaxf(M, c.x);
            Ssum = Ssum * __expf(M - mm) + c.y * __expf(c.x - mm);
            M = mm;
        }
        part_out[((size_t)bh * QLEN + i0 + tid) * 16 + (j0 >> 7)] = make_float2(M, Ssum);
    }
}

__global__ void statcombine(const float2* __restrict__ part, float2* __restrict__ stat) {
    int id = blockIdx.x * 256 + threadIdx.x;
    if (id >= BH * QLEN) return;
    int i = id & (QLEN - 1);
    int ntl = (i >> 7) + 9; if (ntl > 16) ntl = 16;
    float M = -1e30f, Ssum = 0.f;
    const float2* p = part + (size_t)id * 16;
    for (int t = 0; t < ntl; t++) {
        float2 q = p[t];
        float mm = fmaxf(M, q.x);
        Ssum = Ssum * __expf(M - mm) + q.y * __expf(q.x - mm);
        M = mm;
    }
    stat[id] = make_float2(M, 1.0f / Ssum);
}

__global__ void probout(const __half* __restrict__ S, const float2* __restrict__ stat,
                        float* __restrict__ out) {
    __shared__ float t[128][33];
    __shared__ float m_s[32], inv_s[32];
    const int i = blockIdx.y, j0 = blockIdx.x * 128;
    const int tid = threadIdx.x;
    const int jmax = i + MEMLEN;
    float* obase = out + ((size_t)i * KLEN + j0) * 32;
    if (j0 > jmax) {
        float4 z = make_float4(0.f, 0.f, 0.f, 0.f);
        #pragma unroll
        for (int l = 0; l < 4; l++)
            ((float4*)obase)[l * 256 + tid] = z;
        return;
    }
    if (tid < 32) {
        float2 st = stat[tid * QLEN + i];
        m_s[tid] = st.x; inv_s[tid] = st.y;
    }
    __syncthreads();
    const int lb = tid >> 5, lj4 = tid & 31;
    #pragma unroll
    for (int r = 0; r < 4; r++) {
        int bh = r * 8 + lb;
        uint2 raw = *(const uint2*)(S + ((size_t)bh * QLEN + i) * KLEN + j0 + lj4 * 4);
        float2 f0 = __half22float2(*(__half2*)&raw.x);
        float2 f1 = __half22float2(*(__half2*)&raw.y);
        float m = m_s[bh], iv = inv_s[bh];
        int j = j0 + lj4 * 4;
        t[lj4*4+0][bh] = (j     <= jmax) ? __expf(f0.x - m) * iv : 0.f;
        t[lj4*4+1][bh] = (j + 1 <= jmax) ? __expf(f0.y - m) * iv : 0.f;
        t[lj4*4+2][bh] = (j + 2 <= jmax) ? __expf(f1.x - m) * iv : 0.f;
        t[lj4*4+3][bh] = (j + 3 <= jmax) ? __expf(f1.y - m) * iv : 0.f;
    }
    __syncthreads();
    const int bh4 = (tid & 7) * 4;
    #pragma unroll
    for (int p = 0; p < 4; p++) {
        int jl = p * 32 + (tid >> 3);
        float4 w = make_float4(t[jl][bh4], t[jl][bh4+1], t[jl][bh4+2], t[jl][bh4+3]);
        *(float4*)(obase + (size_t)jl * 32 + bh4) = w;
    }
}

__global__ __launch_bounds__(128, 2) void attn_exp_gemm(
    const __half* __restrict__ S, const float2* __restrict__ stat,
    const __half* __restrict__ Vt, __half* __restrict__ ath)
{
    const int bh = blockIdx.y, b = bh >> 3, h = bh & 7;
    const int i0 = blockIdx.x * 128;
    __shared__ __align__(16) __half As[128 * 24];
    __shared__ __align__(16) __half Bs[2][64 * 24];
    __shared__ float m_s[128], inv_s[128];
    const int tid = threadIdx.x;
    const int lane = tid & 31, warp = tid >> 5;
    const int wm = warp & 1, wn = warp >> 1;
    const int grp = lane >> 2, tig = lane & 3;
    {
        float2 st = stat[bh * QLEN + i0 + tid];
        m_s[tid] = st.x; inv_s[tid] = st.y;
    }
    __syncthreads();
    const __half* Srow = S + (size_t)bh * QK + (size_t)i0 * KLEN;
    const __half* Vb = Vt + (size_t)bh * DHEAD * KLEN;
    const int K1 = min(KLEN, i0 + 128 + MEMLEN);
    const int nk = K1 >> 4;

    float acc[4][4][4];
    #pragma unroll
    for (int mt = 0; mt < 4; mt++)
        #pragma unroll
        for (int nt = 0; nt < 4; nt++)
            #pragma unroll
            for (int q = 0; q < 4; q++) acc[mt][nt][q] = 0.f;

    const unsigned aBase = (unsigned)__cvta_generic_to_shared(As);
    const unsigned bBase = (unsigned)__cvta_generic_to_shared(&Bs[0][0]);
    const int rowsel = lane & 15, chsel = lane >> 4;
    const unsigned aOff = aBase + (unsigned)((wm * 64 + rowsel) * 48 + chsel * 16);
    const unsigned bOff = bBase + (unsigned)((wn * 32 + rowsel) * 48 + chsel * 16);

    uint4 aR[2];
    aR[0] = *(const uint4*)(Srow + (size_t)tid * KLEN);
    aR[1] = *(const uint4*)(Srow + (size_t)tid * KLEN + 8);
    {
        int rb = tid >> 1, ch = tid & 1;
        cpa(bBase + rb * 48 + ch * 16, Vb + (size_t)rb * KLEN + ch * 8);
        cp_commit();
    }
    const float mr = m_s[tid];
    const int jmaxr = i0 + tid + MEMLEN;

    int cur = 0;
    for (int it = 0; it < nk; it++) {
        const int kt = it * 16;
        uint4 aN[2];
        if (it + 1 < nk) {
            int ktn = kt + 16;
            int rb = tid >> 1, ch = tid & 1;
            cpa(bBase + (cur ^ 1) * 3072 + rb * 48 + ch * 16,
                Vb + (size_t)rb * KLEN + ktn + ch * 8);
            aN[0] = *(const uint4*)(Srow + (size_t)tid * KLEN + ktn);
            aN[1] = *(const uint4*)(Srow + (size_t)tid * KLEN + ktn + 8);
            cp_commit();
        }
        {
            const __half* hp = (const __half*)aR;
            __half outh[16];
            #pragma unroll
            for (int c = 0; c < 16; c++) {
                float e = (kt + c <= jmaxr) ? __expf(__half2float(hp[c]) - mr) : 0.f;
                outh[c] = __float2half_rn(e);
            }
            *(uint4*)(As + tid * 24)     = *(uint4*)outh;
            *(uint4*)(As + tid * 24 + 8) = *(uint4*)(outh + 8);
        }
        if (it + 1 < nk) cp_wait1(); else cp_wait0();
        __syncthreads();
        const unsigned bS = bOff + (unsigned)(cur * 3072);
        unsigned af[4][4], bf[4][2];
        #pragma unroll
        for (int mt = 0; mt < 4; mt++)
            ldsm_x4(af[mt][0], af[mt][1], af[mt][2], af[mt][3], aOff + mt * 16 * 48);
        #pragma unroll
        for (int p = 0; p < 2; p++) {
            unsigned r0, r1, r2, r3;
            ldsm_x4(r0, r1, r2, r3, bS + p * 16 * 48);
            bf[2*p][0] = r0; bf[2*p+1][0] = r1;
            bf[2*p][1] = r2; bf[2*p+1][1] = r3;
        }
        #pragma unroll
        for (int mt = 0; mt < 4; mt++)
            #pragma unroll
            for (int nt = 0; nt < 4; nt++)
                mma_f16(acc[mt][nt], af[mt][0], af[mt][1], af[mt][2], af[mt][3],
                        bf[nt][0], bf[nt][1]);
        __syncthreads();
        aR[0] = aN[0]; aR[1] = aN[1];
        cur ^= 1;
    }
    #pragma unroll
    for (int mt = 0; mt < 4; mt++) {
        int r0 = wm * 64 + mt * 16 + grp;
        float iv0 = inv_s[r0], iv1 = inv_s[r0 + 8];
        #pragma unroll
        for (int nt = 0; nt < 4; nt++) {
            int c0 = wn * 32 + nt * 8 + tig * 2;
            size_t o0 = ((size_t)(i0 + r0) * BATCH + b) * DMODEL + h * DHEAD + c0;
            size_t o1 = ((size_t)(i0 + r0 + 8) * BATCH + b) * DMODEL + h * DHEAD + c0;
            *(__half2*)(ath + o0) =
                __floats2half2_rn(acc[mt][nt][0] * iv0, acc[mt][nt][1] * iv0);
            *(__half2*)(ath + o1) =
                __floats2half2_rn(acc[mt][nt][2] * iv1, acc[mt][nt][3] * iv1);
        }
    }
}

__global__ void prep_vt(const __half* __restrict__ qkvh, __half* __restrict__ Vt) {
    __shared__ __half t[32][34];
    int bh = blockIdx.z, b = bh >> 3, h = bh & 7;
    int j0 = blockIdx.x * 32, d0 = blockIdx.y * 32;
    int tc = threadIdx.x & 31, tr = threadIdx.x >> 5;
    #pragma unroll
    for (int rr = 0; rr < 32; rr += 8)
        t[tr + rr][tc] = qkvh[(size_t)(j0 + tr + rr) * QSTRIDE + b * QKVW
                              + 2 * DMODEL + h * DHEAD + d0 + tc];
    __syncthreads();
    #pragma unroll
    for (int rr = 0; rr < 32; rr += 8)
        Vt[((size_t)bh * DHEAD + d0 + tr + rr) * KLEN + j0 + tc] = t[tc][tr + rr];
}

__global__ void add_ln(const float* __restrict__ x1, const float* __restrict__ x2,
                       const float* __restrict__ g, const float* __restrict__ bb,
                       float* __restrict__ out, __half* __restrict__ outh) {
    const int row = blockIdx.x;
    const int tid = threadIdx.x;
    __shared__ float red[256];
    __shared__ float red2[256];
    const float* a = x1 + (size_t)row * DMODEL;
    const float* c = x2 + (size_t)row * DMODEL;
    float v0 = a[tid] + c[tid];
    float v1 = a[tid + 256] + c[tid + 256];
    red[tid] = v0 + v1;
    red2[tid] = v0 * v0 + v1 * v1;
    __syncthreads();
    for (int o = 128; o > 0; o >>= 1) {
        if (tid < o) { red[tid] += red[tid + o]; red2[tid] += red2[tid + o]; }
        __syncthreads();
    }
    const float mu = red[0] * (1.0f / DMODEL);
    const float var = red2[0] * (1.0f / DMODEL) - mu * mu;
    const float rstd = rsqrtf(var + 1e-5f);
    float* o = out + (size_t)row * DMODEL;
    float r0 = (v0 - mu) * rstd * g[tid] + bb[tid];
    float r1 = (v1 - mu) * rstd * g[tid + 256] + bb[tid + 256];
    o[tid] = r0;
    o[tid + 256] = r1;
    if (outh) {
        outh[(size_t)row * DMODEL + tid] = __float2half_rn(r0);
        outh[(size_t)row * DMODEL + tid + 256] = __float2half_rn(r1);
    }
}

extern "C" void kernel_launch(void* const* d_in, const int* in_sizes, int n_in,
                              void* d_out, int out_size) {
    const float* inputs = (const float*)d_in[0];
    const float* r      = (const float*)d_in[1];
    const float* u      = (const float*)d_in[2];
    const float* v      = (const float*)d_in[3];
    const float* mem    = (const float*)d_in[4];
    const float* Wqkv   = (const float*)d_in[6];
    const float* Wr     = (const float*)d_in[7];
    const float* Wo     = (const float*)d_in[8];
    const float* ln1_g  = (const float*)d_in[9];
    const float* ln1_b  = (const float*)d_in[10];
    const float* w1     = (const float*)d_in[11];
    const float* b1     = (const float*)d_in[12];
    const float* w2     = (const float*)d_in[13];
    const float* b2     = (const float*)d_in[14];
    const float* ln2_g  = (const float*)d_in[15];
    const float* ln2_b  = (const float*)d_in[16];

    static cudaStream_t s2 = nullptr;
    static cudaEvent_t eFork = nullptr, eJoin = nullptr;
    if (!s2) {
        cudaFuncSetAttribute(lin_gemm_h, cudaFuncAttributeMaxDynamicSharedMemorySize, SMEM_H);
        cudaFuncSetAttribute(score_ac, cudaFuncAttributeMaxDynamicSharedMemorySize, SMEM_AC);
        cudaStreamCreateWithFlags(&s2, cudaStreamNonBlocking);
        cudaEventCreateWithFlags(&eFork, cudaEventDisableTiming);
        cudaEventCreateWithFlags(&eJoin, cudaEventDisableTiming);
    }

    float *aop, *yp, *zp;
    __half *qkvh, *quh, *qvh, *khp, *rkhp, *vth, *shp, *athp, *yh, *hh, *xh;
    float2 *statp, *partp;
    cudaGetSymbolAddress((void**)&qkvh,  g_qkvh);
    cudaGetSymbolAddress((void**)&quh,   g_quh);
    cudaGetSymbolAddress((void**)&qvh,   g_qvh);
    cudaGetSymbolAddress((void**)&khp,   g_kh);
    cudaGetSymbolAddress((void**)&rkhp,  g_rkh);
    cudaGetSymbolAddress((void**)&vth,   g_vth);
    cudaGetSymbolAddress((void**)&shp,   g_Sh);
    cudaGetSymbolAddress((void**)&statp, g_stat);
    cudaGetSymbolAddress((void**)&partp, g_part);
    cudaGetSymbolAddress((void**)&athp,  g_ath);
    cudaGetSymbolAddress((void**)&aop,   g_ao);
    cudaGetSymbolAddress((void**)&yp,    g_y);
    cudaGetSymbolAddress((void**)&yh,    g_yh);
    cudaGetSymbolAddress((void**)&hh,    g_hh);
    cudaGetSymbolAddress((void**)&zp,    g_z);
    cudaGetSymbolAddress((void**)&xh,    g_xh);

    const __half* memh  = xh;
    const __half* rh    = xh + OFF_R;
    const __half* wqkvh = xh + OFF_WQKV;
    const __half* wrh   = xh + OFF_WR;
    const __half* woh   = xh + OFF_WO;
    const __half* w1h   = xh + OFF_W1;
    const __half* w2h   = xh + OFF_W2;

    // 1: fp16 conv  2: qkv (V-only Ch + aux)  3: rk (rkh)  4: fused score_ac
    half_all<<<(2162688 + 255) / 256, 256>>>(mem, inputs, r, Wqkv, Wr, Wo, w1, w2, xh);
    lin_gemm_h<<<dim3(QKVW / 128, KROWS / 128), 256, SMEM_H>>>(
        memh, wqkvh, nullptr, nullptr, qkvh, u, v, quh, qvh, khp,
        DMODEL, QKVW, 8 | 16 | 32 | 128);
    lin_gemm_h<<<dim3(DMODEL / 128, KLEN / 128), 256, SMEM_H>>>(
        rh, wrh, nullptr, nullptr, rkhp, nullptr, nullptr, nullptr, nullptr, nullptr,
        DMODEL, DMODEL, 16 | 64);
    score_ac<<<dim3(KLEN / 128, QLEN / 128, BH), 256, SMEM_AC>>>(
        quh, khp, qvh, rkhp, shp, partp);
    // 5-6
    prep_vt<<<dim3(KLEN / 32, DHEAD / 32, BH), 256>>>(qkvh, vth);
    statcombine<<<(BH * QLEN + 255) / 256, 256>>>(partp, statp);
    // fork prob output onto side stream
    cudaEventRecord(eFork, 0);
    cudaStreamWaitEvent(s2, eFork, 0);
    float* prob_out = (float*)d_out + QLEN * BATCH * DMODEL;
    probout<<<dim3(KLEN / 128, QLEN), 256, 0, s2>>>(shp, statp, prob_out);
    cudaEventRecord(eJoin, s2);
    // tail
    attn_exp_gemm<<<dim3(QLEN / 128, BH), 128>>>(shp, statp, vth, athp);
    lin_gemm_h<<<dim3(DMODEL / 128, QROWS / 128), 256, SMEM_H>>>(
        athp, woh, nullptr, aop, nullptr, nullptr, nullptr, nullptr, nullptr, nullptr,
        DMODEL, DMODEL, 0);
    add_ln<<<QROWS, 256>>>(inputs, aop, ln1_g, ln1_b, yp, yh);
    lin_gemm_h<<<dim3(DMLP / 128, QROWS / 128), 256, SMEM_H>>>(
        yh, w1h, b1, nullptr, hh, nullptr, nullptr, nullptr, nullptr, nullptr,
        DMODEL, DMLP, 1 | 2 | 8 | 16);
    lin_gemm_h<<<dim3(DMODEL / 128, QROWS / 128), 256, SMEM_H>>>(
        hh, w2h, b2, zp, nullptr, nullptr, nullptr, nullptr, nullptr, nullptr,
        DMLP, DMODEL, 1);
    add_ln<<<QROWS, 256>>>(yp, zp, ln2_g, ln2_b, (float*)d_out, nullptr);
    cudaStreamWaitEvent(0, eJoin, 0);
}